// round 4
// baseline (speedup 1.0000x reference)
#include <cuda_runtime.h>

#define BN 64
#define TT 12
#define NN 716
#define DD 64
#define EE 32
#define TN 8592            // TT*NN
#define XELEMS 35192832    // BN*TN*DD

typedef unsigned long long ull;

__device__ float g_bufA[XELEMS];
__device__ float g_bufB[XELEMS];
__device__ float g_assignd[(size_t)BN*TN*64];   // duplicated: [row][2e]=[2e+1]=p
__device__ float g_hf[BN*EE*DD];
__device__ float g_ho[BN*EE*DD];

__device__ __forceinline__ ull fma2(ull a, ull b, ull c) {
    ull d;
    asm("fma.rn.f32x2 %0, %1, %2, %3;" : "=l"(d) : "l"(a), "l"(b), "l"(c));
    return d;
}
__device__ __forceinline__ void unpack2(ull v, float& lo, float& hi) {
    asm("mov.b64 {%0, %1}, %2;" : "=f"(lo), "=f"(hi) : "l"(v));
}
__device__ __forceinline__ ull pack2(float lo, float hi) {
    ull d;
    asm("mov.b64 %0, {%1, %2};" : "=l"(d) : "f"(lo), "f"(hi));
    return d;
}

__global__ __launch_bounds__(256) void k_zero_hf(float* hf) {
    int i = blockIdx.x*256 + threadIdx.x;
    if (i < BN*EE*DD) hf[i] = 0.f;
}

// ============================ K1: assign + hf ============================
#define K1_STAGE 64
#define K1_STAGES 4
#define K1_CHUNK (K1_STAGE*K1_STAGES)                     // 256
#define K1_BLOCKS_PER_B ((TN + K1_CHUNK - 1)/K1_CHUNK)    // 34

__global__ __launch_bounds__(256) void k_assign_hf(
    const float* __restrict__ x, const float* __restrict__ edge_clf,
    float* __restrict__ assignd, float* __restrict__ hf)
{
    __shared__ float ecp[32*64];     // [k2][e*2+{0,1}] = ec[2k2+i][e]  (k-paired)
    __shared__ float xs[64][64];
    __shared__ float as[64][32];
    int tid = threadIdx.x;
    int b = blockIdx.x;
    int r0base = blockIdx.y * K1_CHUNK;
    int lane = tid & 31, warp = tid >> 5;
    int e_own = tid >> 3;
    int dbase = (tid & 7) * 8;

    for (int i = tid; i < 64*32; i += 256) {
        int k = i >> 5, e = i & 31;
        ecp[(k>>1)*64 + e*2 + (k&1)] = edge_clf[i];
    }

    float acc[8];
    #pragma unroll
    for (int j = 0; j < 8; j++) acc[j] = 0.f;

    const float* xb = x + (size_t)b*TN*DD;

    for (int s = 0; s < K1_STAGES; s++) {
        int r0 = r0base + s*K1_STAGE;
        __syncthreads();
        #pragma unroll
        for (int p = 0; p < 4; p++) {
            int row = p*16 + (tid >> 4);
            int q = (tid & 15) * 4;
            int gr = r0 + row;
            float4 v = make_float4(0.f,0.f,0.f,0.f);
            if (gr < TN) v = *(const float4*)(xb + (size_t)gr*DD + q);
            *(float4*)(&xs[row][q]) = v;
        }
        __syncthreads();
        // logits via fma2 over k-pairs: warp handles rows warp*8..+7, lane = e
        {
            ull v2[8];
            #pragma unroll
            for (int j = 0; j < 8; j++) v2[j] = 0ull;
            #pragma unroll 4
            for (int k2 = 0; k2 < 32; k2++) {
                ull ev = *(const ull*)&ecp[k2*64 + lane*2];
                #pragma unroll
                for (int j = 0; j < 8; j++) {
                    ull xv = *(const ull*)&xs[warp*8 + j][2*k2];
                    v2[j] = fma2(xv, ev, v2[j]);
                }
            }
            #pragma unroll
            for (int j = 0; j < 8; j++) {
                int r = warp*8 + j;
                int gr = r0 + r;
                float vlo, vhi;
                unpack2(v2[j], vlo, vhi);
                float v = vlo + vhi;
                float m = v;
                #pragma unroll
                for (int o = 16; o; o >>= 1) m = fmaxf(m, __shfl_xor_sync(0xffffffffu, m, o));
                float ex = __expf(v - m);
                float sm = ex;
                #pragma unroll
                for (int o = 16; o; o >>= 1) sm += __shfl_xor_sync(0xffffffffu, sm, o);
                float p = ex / sm;
                bool valid = (gr < TN);
                as[r][lane] = valid ? p : 0.f;
                if (valid) {
                    // duplicated write: one STG.64
                    *(ull*)(assignd + ((size_t)b*TN + gr)*64 + 2*lane) = pack2(p, p);
                }
            }
        }
        __syncthreads();
        #pragma unroll 4
        for (int r = 0; r < 64; r++) {
            float a = as[r][e_own];
            float4 x0 = *(const float4*)&xs[r][dbase];
            float4 x1 = *(const float4*)&xs[r][dbase+4];
            acc[0] = fmaf(a, x0.x, acc[0]); acc[1] = fmaf(a, x0.y, acc[1]);
            acc[2] = fmaf(a, x0.z, acc[2]); acc[3] = fmaf(a, x0.w, acc[3]);
            acc[4] = fmaf(a, x1.x, acc[4]); acc[5] = fmaf(a, x1.y, acc[5]);
            acc[6] = fmaf(a, x1.z, acc[6]); acc[7] = fmaf(a, x1.w, acc[7]);
        }
    }
    float* hb = hf + b*EE*DD + e_own*DD + dbase;
    #pragma unroll
    for (int j = 0; j < 8; j++) atomicAdd(hb + j, acc[j]);
}

// ============================ K2: edge mix ============================
__global__ __launch_bounds__(256) void k_edge_mix(
    const float* __restrict__ hf, const float* __restrict__ edge_map,
    float* __restrict__ ho)
{
    __shared__ float hfs[32][64];
    __shared__ float em[32][32];
    int tid = threadIdx.x;
    int b = blockIdx.x;
    const float* hb = hf + b*EE*DD;
    for (int i = tid; i < 2048; i += 256) hfs[i>>6][i&63] = hb[i];
    for (int i = tid; i < 1024; i += 256) em[i>>5][i&31] = edge_map[i];
    __syncthreads();
    int e = tid >> 3, dbase = (tid & 7) * 8;
    float o[8];
    #pragma unroll
    for (int j = 0; j < 8; j++) o[j] = 0.f;
    #pragma unroll
    for (int f = 0; f < 32; f++) {
        float w = em[e][f];
        #pragma unroll
        for (int j = 0; j < 8; j++) o[j] = fmaf(w, hfs[f][dbase + j], o[j]);
    }
    float* ob = ho + b*EE*DD + e*DD + dbase;
    #pragma unroll
    for (int j = 0; j < 8; j++) ob[j] = fmaxf(o[j], 0.f) + hfs[e][dbase + j];
}

// ============================ K3: fused output ============================
// 8 warps/block, 8 rows/warp, lane owns column pair (2l, 2l+1).
// xm staged DUPLICATED in smem -> mov-free fma2 main loop.
#define K3_ROWS 64
#define K3_BLOCKS_PER_B ((TN + K3_ROWS - 1)/K3_ROWS)   // 135
#define K3_SMEM_FLOATS (8192 + 8192 + 2048 + 384)      // w4s + xmd + hos + prm

__global__ __launch_bounds__(256, 3) void k_fused_out(
    const float* __restrict__ x,
    const float* __restrict__ W1, const float* __restrict__ b1,
    const float* __restrict__ W2, const float* __restrict__ b2,
    const float* __restrict__ ln1g, const float* __restrict__ ln1b,
    const float* __restrict__ ln2g, const float* __restrict__ ln2b,
    const float* __restrict__ assignd, const float* __restrict__ ho,
    float* __restrict__ out)
{
    extern __shared__ float smem[];
    float* w4s = smem;              // [k][128]: (w1[k][2l],w1[k][2l+1],w2[k][2l],w2[k][2l+1])
    float* xmd = w4s + 8192;        // [warp][8 rows][128]: xm duplicated (2k,2k+1)
    float* hos = xmd + 8192;        // [e][64]
    float* prm = hos + 2048;        // [6][64]

    int tid = threadIdx.x;
    int b = blockIdx.x;
    int lane = tid & 31, warp = tid >> 5;

    for (int i = tid; i < 4096; i += 256) {
        int k = i >> 6, c = i & 63;
        int p = c >> 1, q = c & 1;
        w4s[k*128 + p*4 + q]     = W1[i];
        w4s[k*128 + p*4 + 2 + q] = W2[i];
    }
    for (int i = tid; i < 2048; i += 256) hos[i] = ho[b*EE*DD + i];
    if (tid < 64) {
        prm[0*64 + tid] = b1[tid];   prm[1*64 + tid] = b2[tid];
        prm[2*64 + tid] = ln1g[tid]; prm[3*64 + tid] = ln1b[tid];
        prm[4*64 + tid] = ln2g[tid]; prm[5*64 + tid] = ln2b[tid];
    }
    __syncthreads();

    int rowbase = blockIdx.y * K3_ROWS + warp * 8;
    const float* xb = x + (size_t)b*TN*DD;
    const float* adb = assignd + (size_t)b*TN*64;
    float* ob = out + (size_t)b*TN*DD;
    float* xmw = xmd + warp*8*128;

    // ---- prologue: windowed mean, written DUPLICATED ----
    #pragma unroll
    for (int r = 0; r < 8; r++) {
        int row = rowbase + r;
        float2 xv = make_float2(0.f, 0.f), xp = make_float2(0.f, 0.f);
        if (row < TN) {
            xv = *(const float2*)(xb + (size_t)row*DD + 2*lane);
            if (row >= NN) xp = *(const float2*)(xb + (size_t)(row - NN)*DD + 2*lane);
        }
        float mx = 0.5f*(xv.x + xp.x), my = 0.5f*(xv.y + xp.y);
        *(float4*)(xmw + r*128 + 4*lane) = make_float4(mx, mx, my, my);
    }
    __syncwarp();

    // ---- main GEMVs: mov-free fma2 ----
    ull B1p = pack2(prm[0*64 + 2*lane], prm[0*64 + 2*lane + 1]);
    ull B2p = pack2(prm[1*64 + 2*lane], prm[1*64 + 2*lane + 1]);
    ull G1[8], G2[8];
    #pragma unroll
    for (int r = 0; r < 8; r++) { G1[r] = B1p; G2[r] = B2p; }

    #pragma unroll 2
    for (int k4 = 0; k4 < 16; k4++) {
        ulonglong2 wv0 = *(const ulonglong2*)&w4s[(4*k4+0)*128 + lane*4];
        ulonglong2 wv1 = *(const ulonglong2*)&w4s[(4*k4+1)*128 + lane*4];
        ulonglong2 wv2 = *(const ulonglong2*)&w4s[(4*k4+2)*128 + lane*4];
        ulonglong2 wv3 = *(const ulonglong2*)&w4s[(4*k4+3)*128 + lane*4];
        #pragma unroll
        for (int r = 0; r < 8; r++) {
            ulonglong2 ma = *(const ulonglong2*)(xmw + r*128 + 8*k4);     // dup(m0), dup(m1)
            ulonglong2 mb = *(const ulonglong2*)(xmw + r*128 + 8*k4 + 4); // dup(m2), dup(m3)
            G1[r] = fma2(wv0.x, ma.x, G1[r]); G2[r] = fma2(wv0.y, ma.x, G2[r]);
            G1[r] = fma2(wv1.x, ma.y, G1[r]); G2[r] = fma2(wv1.y, ma.y, G2[r]);
            G1[r] = fma2(wv2.x, mb.x, G1[r]); G2[r] = fma2(wv2.y, mb.x, G2[r]);
            G1[r] = fma2(wv3.x, mb.y, G1[r]); G2[r] = fma2(wv3.y, mb.y, G2[r]);
        }
    }

    // ---- hyper: Y = assign @ ho, assign read duplicated from gmem ----
    ull Y[8];
    #pragma unroll
    for (int r = 0; r < 8; r++) Y[r] = 0ull;
    #pragma unroll 4
    for (int e2 = 0; e2 < 16; e2++) {
        ull H0 = *(const ull*)&hos[(2*e2)*64 + 2*lane];
        ull H1 = *(const ull*)&hos[(2*e2+1)*64 + 2*lane];
        #pragma unroll
        for (int r = 0; r < 8; r++) {
            int row = rowbase + r;
            ulonglong2 ad = (row < TN)
                ? *(const ulonglong2*)(adb + (size_t)row*64 + 4*e2)
                : make_ulonglong2(0ull, 0ull);
            Y[r] = fma2(H0, ad.x, Y[r]);
            Y[r] = fma2(H1, ad.y, Y[r]);
        }
    }

    // ---- epilogue ----
    float g1w = prm[2*64 + 2*lane], g1w2 = prm[2*64 + 2*lane + 1];
    float b1w = prm[3*64 + 2*lane], b1w2 = prm[3*64 + 2*lane + 1];
    float g2w = prm[4*64 + 2*lane], g2w2 = prm[4*64 + 2*lane + 1];
    float b2w = prm[5*64 + 2*lane], b2w2 = prm[5*64 + 2*lane + 1];

    #pragma unroll
    for (int r = 0; r < 8; r++) {
        int row = rowbase + r;
        if (row >= TN) break;   // warp-uniform
        float2 xv = *(const float2*)(xb + (size_t)row*DD + 2*lane);  // residual reload
        float g1a, g1b, g2a, g2b, y0, y1;
        unpack2(G1[r], g1a, g1b);
        unpack2(G2[r], g2a, g2b);
        unpack2(Y[r], y0, y1);
        float f0 = fmaxf(g1a*g2a, 0.f) + g1a + xv.x;
        float f1 = fmaxf(g1b*g2b, 0.f) + g1b + xv.y;
        float s = f0 + f1, s2 = f0*f0 + f1*f1;
        #pragma unroll
        for (int o = 16; o; o >>= 1) {
            s  += __shfl_xor_sync(0xffffffffu, s,  o);
            s2 += __shfl_xor_sync(0xffffffffu, s2, o);
        }
        float mu = s * (1.f/64.f);
        float var = s2 * (1.f/64.f) - mu*mu;
        float rs = rsqrtf(var + 1e-5f);
        float o1a = (f0 - mu)*rs*g1w + b1w;
        float o1b = (f1 - mu)*rs*g1w2 + b1w2;

        float h0 = fmaxf(y0, 0.f) + xv.x;
        float h1 = fmaxf(y1, 0.f) + xv.y;
        s = h0 + h1; s2 = h0*h0 + h1*h1;
        #pragma unroll
        for (int o = 16; o; o >>= 1) {
            s  += __shfl_xor_sync(0xffffffffu, s,  o);
            s2 += __shfl_xor_sync(0xffffffffu, s2, o);
        }
        mu = s * (1.f/64.f);
        var = s2 * (1.f/64.f) - mu*mu;
        rs = rsqrtf(var + 1e-5f);
        float o2a = (h0 - mu)*rs*g2w + b2w;
        float o2b = (h1 - mu)*rs*g2w2 + b2w2;

        *(float2*)(ob + (size_t)row*DD + 2*lane) =
            make_float2(0.5f*(o1a + o2a), 0.5f*(o1b + o2b));
    }
}

extern "C" void kernel_launch(void* const* d_in, const int* in_sizes, int n_in,
                              void* d_out, int out_size) {
    const float* x    = (const float*)d_in[0];
    const float* W1   = (const float*)d_in[1];
    const float* b1   = (const float*)d_in[2];
    const float* W2   = (const float*)d_in[3];
    const float* b2   = (const float*)d_in[4];
    const float* ln1g = (const float*)d_in[5];
    const float* ln1b = (const float*)d_in[6];
    const float* eclf = (const float*)d_in[7];
    const float* emap = (const float*)d_in[8];
    const float* ln2g = (const float*)d_in[9];
    const float* ln2b = (const float*)d_in[10];

    float *bufA, *bufB, *assignd, *hf, *ho;
    cudaGetSymbolAddress((void**)&bufA,    g_bufA);
    cudaGetSymbolAddress((void**)&bufB,    g_bufB);
    cudaGetSymbolAddress((void**)&assignd, g_assignd);
    cudaGetSymbolAddress((void**)&hf,      g_hf);
    cudaGetSymbolAddress((void**)&ho,      g_ho);

    cudaFuncSetAttribute(k_fused_out, cudaFuncAttributeMaxDynamicSharedMemorySize,
                         K3_SMEM_FLOATS * (int)sizeof(float));

    const float* cur = x;
    float* outs[3] = { bufA, bufB, (float*)d_out };

    for (int i = 0; i < 3; i++) {
        k_zero_hf<<<(BN*EE*DD + 255)/256, 256>>>(hf);
        dim3 g1(BN, K1_BLOCKS_PER_B);
        k_assign_hf<<<g1, 256>>>(cur, eclf, assignd, hf);
        k_edge_mix<<<BN, 256>>>(hf, emap, ho);
        dim3 g3(BN, K3_BLOCKS_PER_B);
        k_fused_out<<<g3, 256, K3_SMEM_FLOATS * sizeof(float)>>>(
            cur, W1 + i*DD*DD, b1 + i*DD, W2 + i*DD*DD, b2 + i*DD,
            ln1g + i*DD, ln1b + i*DD, ln2g, ln2b,
            assignd, ho, outs[i]);
        cur = outs[i];
    }
}

// round 5
// speedup vs baseline: 1.2886x; 1.2886x over previous
#include <cuda_runtime.h>

#define BN 64
#define TT 12
#define NN 716
#define DD 64
#define EE 32
#define TN 8592            // TT*NN
#define XELEMS 35192832    // BN*TN*DD

typedef unsigned long long ull;

#define K1_STAGE 64
#define K1_STAGES 4
#define K1_CHUNK (K1_STAGE*K1_STAGES)                     // 256
#define K1_BLOCKS_PER_B ((TN + K1_CHUNK - 1)/K1_CHUNK)    // 34

__device__ float g_bufA[XELEMS];
__device__ float g_bufB[XELEMS];
__device__ float g_assign[(size_t)BN*TN*EE];
__device__ float g_hfp[(size_t)BN*K1_BLOCKS_PER_B*EE*DD];   // per-chunk partials
__device__ float g_ho[BN*EE*DD];

__device__ __forceinline__ ull fma2(ull a, ull b, ull c) {
    ull d;
    asm("fma.rn.f32x2 %0, %1, %2, %3;" : "=l"(d) : "l"(a), "l"(b), "l"(c));
    return d;
}
__device__ __forceinline__ ull packdup(float m) {
    ull d;
    asm("mov.b64 %0, {%1, %1};" : "=l"(d) : "f"(m));
    return d;
}
__device__ __forceinline__ ull pack2(float lo, float hi) {
    ull d;
    asm("mov.b64 %0, {%1, %2};" : "=l"(d) : "f"(lo), "f"(hi));
    return d;
}
__device__ __forceinline__ void unpack2(ull v, float& lo, float& hi) {
    asm("mov.b64 {%0, %1}, %2;" : "=f"(lo), "=f"(hi) : "l"(v));
}

// ============================ K1: assign + hf partials ============================
__global__ __launch_bounds__(256) void k_assign_hf(
    const float* __restrict__ x, const float* __restrict__ edge_clf,
    float* __restrict__ assign, float* __restrict__ hfp)
{
    __shared__ float ecp[32*64];     // [k2][e*2+{0,1}] = ec[2k2+i][e]  (k-paired)
    __shared__ float xs[64][64];
    __shared__ float as[64][32];
    int tid = threadIdx.x;
    int b = blockIdx.x;
    int r0base = blockIdx.y * K1_CHUNK;
    int lane = tid & 31, warp = tid >> 5;
    int e_own = tid >> 3;
    int dbase = (tid & 7) * 8;

    for (int i = tid; i < 64*32; i += 256) {
        int k = i >> 5, e = i & 31;
        ecp[(k>>1)*64 + e*2 + (k&1)] = edge_clf[i];
    }

    ull acc2[4];
    #pragma unroll
    for (int j = 0; j < 4; j++) acc2[j] = 0ull;

    const float* xb = x + (size_t)b*TN*DD;

    for (int s = 0; s < K1_STAGES; s++) {
        int r0 = r0base + s*K1_STAGE;
        __syncthreads();
        #pragma unroll
        for (int p = 0; p < 4; p++) {
            int row = p*16 + (tid >> 4);
            int q = (tid & 15) * 4;
            int gr = r0 + row;
            float4 v = make_float4(0.f,0.f,0.f,0.f);
            if (gr < TN) v = *(const float4*)(xb + (size_t)gr*DD + q);
            *(float4*)(&xs[row][q]) = v;
        }
        __syncthreads();
        // logits via fma2 over k-pairs: warp handles rows warp*8..+7, lane = e
        {
            ull v2[8];
            #pragma unroll
            for (int j = 0; j < 8; j++) v2[j] = 0ull;
            #pragma unroll 4
            for (int k2 = 0; k2 < 32; k2++) {
                ull ev = *(const ull*)&ecp[k2*64 + lane*2];
                #pragma unroll
                for (int j = 0; j < 8; j++) {
                    ull xv = *(const ull*)&xs[warp*8 + j][2*k2];
                    v2[j] = fma2(xv, ev, v2[j]);
                }
            }
            #pragma unroll
            for (int j = 0; j < 8; j++) {
                int r = warp*8 + j;
                int gr = r0 + r;
                float vlo, vhi;
                unpack2(v2[j], vlo, vhi);
                float v = vlo + vhi;
                float m = v;
                #pragma unroll
                for (int o = 16; o; o >>= 1) m = fmaxf(m, __shfl_xor_sync(0xffffffffu, m, o));
                float ex = __expf(v - m);
                float sm = ex;
                #pragma unroll
                for (int o = 16; o; o >>= 1) sm += __shfl_xor_sync(0xffffffffu, sm, o);
                float p = ex / sm;
                bool valid = (gr < TN);
                as[r][lane] = valid ? p : 0.f;
                if (valid) assign[((size_t)b*TN + gr)*EE + lane] = p;
            }
        }
        __syncthreads();
        // rank-1 accumulation via fma2
        #pragma unroll 4
        for (int r = 0; r < 64; r++) {
            ull ad = packdup(as[r][e_own]);
            ulonglong2 x0 = *(const ulonglong2*)&xs[r][dbase];
            ulonglong2 x1 = *(const ulonglong2*)&xs[r][dbase+4];
            acc2[0] = fma2(ad, x0.x, acc2[0]);
            acc2[1] = fma2(ad, x0.y, acc2[1]);
            acc2[2] = fma2(ad, x1.x, acc2[2]);
            acc2[3] = fma2(ad, x1.y, acc2[3]);
        }
    }
    // store partials (no atomics)
    float* hp = hfp + ((size_t)b*K1_BLOCKS_PER_B + blockIdx.y)*(EE*DD) + e_own*DD + dbase;
    *(ulonglong2*)hp       = make_ulonglong2(acc2[0], acc2[1]);
    *(ulonglong2*)(hp + 4) = make_ulonglong2(acc2[2], acc2[3]);
}

// ============================ K2: reduce partials + edge mix ============================
__global__ __launch_bounds__(256) void k_edge_mix(
    const float* __restrict__ hfp, const float* __restrict__ edge_map,
    float* __restrict__ ho)
{
    __shared__ float hfs[32][64];
    __shared__ float em[32][32];
    int tid = threadIdx.x;
    int b = blockIdx.x;
    // reduce 34 chunks: thread owns 8 contiguous floats (tid*8 .. tid*8+7)
    float4 s0 = make_float4(0.f,0.f,0.f,0.f), s1 = make_float4(0.f,0.f,0.f,0.f);
    const float* pb = hfp + (size_t)b*K1_BLOCKS_PER_B*(EE*DD) + tid*8;
    #pragma unroll 2
    for (int c = 0; c < K1_BLOCKS_PER_B; c++) {
        float4 a0 = *(const float4*)(pb + (size_t)c*(EE*DD));
        float4 a1 = *(const float4*)(pb + (size_t)c*(EE*DD) + 4);
        s0.x += a0.x; s0.y += a0.y; s0.z += a0.z; s0.w += a0.w;
        s1.x += a1.x; s1.y += a1.y; s1.z += a1.z; s1.w += a1.w;
    }
    int e = tid >> 3, dbase = (tid & 7) * 8;
    *(float4*)&hfs[e][dbase]     = s0;
    *(float4*)&hfs[e][dbase + 4] = s1;
    for (int i = tid; i < 1024; i += 256) em[i>>5][i&31] = edge_map[i];
    __syncthreads();
    float o[8];
    #pragma unroll
    for (int j = 0; j < 8; j++) o[j] = 0.f;
    #pragma unroll
    for (int f = 0; f < 32; f++) {
        float w = em[e][f];
        #pragma unroll
        for (int j = 0; j < 8; j++) o[j] = fmaf(w, hfs[f][dbase + j], o[j]);
    }
    float* ob = ho + b*EE*DD + e*DD + dbase;
    #pragma unroll
    for (int j = 0; j < 8; j++) ob[j] = fmaxf(o[j], 0.f) + hfs[e][dbase + j];
}

// ============================ K3: fused output ============================
// 8 warps/block, 8 rows/warp, lane owns column pair (2l, 2l+1). R3 structure,
// XV dropped (x reloaded in epilogue), launch_bounds(256,3) for occupancy.
#define K3_ROWS 64
#define K3_BLOCKS_PER_B ((TN + K3_ROWS - 1)/K3_ROWS)   // 135
#define K3_SMEM_FLOATS (8192 + 2048 + 384 + 4096 + 2048)

__global__ __launch_bounds__(256, 3) void k_fused_out(
    const float* __restrict__ x,
    const float* __restrict__ W1, const float* __restrict__ b1,
    const float* __restrict__ W2, const float* __restrict__ b2,
    const float* __restrict__ ln1g, const float* __restrict__ ln1b,
    const float* __restrict__ ln2g, const float* __restrict__ ln2b,
    const float* __restrict__ assign, const float* __restrict__ ho,
    float* __restrict__ out)
{
    extern __shared__ float smem[];
    float* w4s = smem;              // [k][128]: (w1[k][2l],w1[k][2l+1],w2[k][2l],w2[k][2l+1])
    float* hos = w4s + 8192;        // [e][64]
    float* prm = hos + 2048;        // [6][64]
    float* xms = prm + 384;         // [warp][8][64]
    float* ass = xms + 4096;        // [warp][8][32]

    int tid = threadIdx.x;
    int b = blockIdx.x;
    int lane = tid & 31, warp = tid >> 5;

    for (int i = tid; i < 4096; i += 256) {
        int k = i >> 6, c = i & 63;
        int p = c >> 1, q = c & 1;
        w4s[k*128 + p*4 + q]     = W1[i];
        w4s[k*128 + p*4 + 2 + q] = W2[i];
    }
    for (int i = tid; i < 2048; i += 256) hos[i] = ho[b*EE*DD + i];
    if (tid < 64) {
        prm[0*64 + tid] = b1[tid];   prm[1*64 + tid] = b2[tid];
        prm[2*64 + tid] = ln1g[tid]; prm[3*64 + tid] = ln1b[tid];
        prm[4*64 + tid] = ln2g[tid]; prm[5*64 + tid] = ln2b[tid];
    }
    __syncthreads();

    int rowbase = blockIdx.y * K3_ROWS + warp * 8;
    const float* xb = x + (size_t)b*TN*DD;
    const float* ab = assign + (size_t)b*TN*EE;
    float* ob = out + (size_t)b*TN*DD;
    float* xmw = xms + warp*8*64;
    float* asw = ass + warp*8*32;

    // ---- prologue: windowed mean + assign staging ----
    #pragma unroll
    for (int r = 0; r < 8; r++) {
        int row = rowbase + r;
        float2 xv = make_float2(0.f, 0.f), xp = make_float2(0.f, 0.f);
        float a = 0.f;
        if (row < TN) {
            xv = *(const float2*)(xb + (size_t)row*DD + 2*lane);
            if (row >= NN) xp = *(const float2*)(xb + (size_t)(row - NN)*DD + 2*lane);
            a = ab[(size_t)row*EE + lane];
        }
        *(float2*)(xmw + r*64 + 2*lane) = make_float2(0.5f*(xv.x + xp.x), 0.5f*(xv.y + xp.y));
        asw[r*32 + lane] = a;
    }
    __syncwarp();

    // ---- main GEMVs via FFMA2 ----
    ull B1p = pack2(prm[0*64 + 2*lane], prm[0*64 + 2*lane + 1]);
    ull B2p = pack2(prm[1*64 + 2*lane], prm[1*64 + 2*lane + 1]);
    ull G1[8], G2[8];
    #pragma unroll
    for (int r = 0; r < 8; r++) { G1[r] = B1p; G2[r] = B2p; }

    #pragma unroll 2
    for (int k4 = 0; k4 < 16; k4++) {
        ulonglong2 wv0 = *(const ulonglong2*)&w4s[(4*k4+0)*128 + lane*4];
        ulonglong2 wv1 = *(const ulonglong2*)&w4s[(4*k4+1)*128 + lane*4];
        ulonglong2 wv2 = *(const ulonglong2*)&w4s[(4*k4+2)*128 + lane*4];
        ulonglong2 wv3 = *(const ulonglong2*)&w4s[(4*k4+3)*128 + lane*4];
        #pragma unroll
        for (int r = 0; r < 8; r++) {
            float4 mv = *(const float4*)(xmw + r*64 + 4*k4);
            ull m0 = packdup(mv.x), m1 = packdup(mv.y);
            ull m2 = packdup(mv.z), m3 = packdup(mv.w);
            G1[r] = fma2(wv0.x, m0, G1[r]); G2[r] = fma2(wv0.y, m0, G2[r]);
            G1[r] = fma2(wv1.x, m1, G1[r]); G2[r] = fma2(wv1.y, m1, G2[r]);
            G1[r] = fma2(wv2.x, m2, G1[r]); G2[r] = fma2(wv2.y, m2, G2[r]);
            G1[r] = fma2(wv3.x, m3, G1[r]); G2[r] = fma2(wv3.y, m3, G2[r]);
        }
    }

    // ---- hyper: Y = assign @ ho (from smem) ----
    ull Y[8];
    #pragma unroll
    for (int r = 0; r < 8; r++) Y[r] = 0ull;
    #pragma unroll 4
    for (int e2 = 0; e2 < 16; e2++) {
        ull H0 = *(const ull*)&hos[(2*e2)*64 + 2*lane];
        ull H1 = *(const ull*)&hos[(2*e2+1)*64 + 2*lane];
        #pragma unroll
        for (int r = 0; r < 8; r++) {
            float2 a2 = *(const float2*)(asw + r*32 + 2*e2);
            Y[r] = fma2(H0, packdup(a2.x), Y[r]);
            Y[r] = fma2(H1, packdup(a2.y), Y[r]);
        }
    }

    // ---- epilogue (x reloaded from L2) ----
    float g1w = prm[2*64 + 2*lane], g1w2 = prm[2*64 + 2*lane + 1];
    float b1w = prm[3*64 + 2*lane], b1w2 = prm[3*64 + 2*lane + 1];
    float g2w = prm[4*64 + 2*lane], g2w2 = prm[4*64 + 2*lane + 1];
    float b2w = prm[5*64 + 2*lane], b2w2 = prm[5*64 + 2*lane + 1];

    #pragma unroll
    for (int r = 0; r < 8; r++) {
        int row = rowbase + r;
        if (row >= TN) break;   // warp-uniform
        float2 xv = *(const float2*)(xb + (size_t)row*DD + 2*lane);
        float g1a, g1b, g2a, g2b, y0, y1;
        unpack2(G1[r], g1a, g1b);
        unpack2(G2[r], g2a, g2b);
        unpack2(Y[r], y0, y1);
        float f0 = fmaxf(g1a*g2a, 0.f) + g1a + xv.x;
        float f1 = fmaxf(g1b*g2b, 0.f) + g1b + xv.y;
        float s = f0 + f1, s2 = f0*f0 + f1*f1;
        #pragma unroll
        for (int o = 16; o; o >>= 1) {
            s  += __shfl_xor_sync(0xffffffffu, s,  o);
            s2 += __shfl_xor_sync(0xffffffffu, s2, o);
        }
        float mu = s * (1.f/64.f);
        float var = s2 * (1.f/64.f) - mu*mu;
        float rs = rsqrtf(var + 1e-5f);
        float o1a = (f0 - mu)*rs*g1w + b1w;
        float o1b = (f1 - mu)*rs*g1w2 + b1w2;

        float h0 = fmaxf(y0, 0.f) + xv.x;
        float h1 = fmaxf(y1, 0.f) + xv.y;
        s = h0 + h1; s2 = h0*h0 + h1*h1;
        #pragma unroll
        for (int o = 16; o; o >>= 1) {
            s  += __shfl_xor_sync(0xffffffffu, s,  o);
            s2 += __shfl_xor_sync(0xffffffffu, s2, o);
        }
        mu = s * (1.f/64.f);
        var = s2 * (1.f/64.f) - mu*mu;
        rs = rsqrtf(var + 1e-5f);
        float o2a = (h0 - mu)*rs*g2w + b2w;
        float o2b = (h1 - mu)*rs*g2w2 + b2w2;

        *(float2*)(ob + (size_t)row*DD + 2*lane) =
            make_float2(0.5f*(o1a + o2a), 0.5f*(o1b + o2b));
    }
}

extern "C" void kernel_launch(void* const* d_in, const int* in_sizes, int n_in,
                              void* d_out, int out_size) {
    const float* x    = (const float*)d_in[0];
    const float* W1   = (const float*)d_in[1];
    const float* b1   = (const float*)d_in[2];
    const float* W2   = (const float*)d_in[3];
    const float* b2   = (const float*)d_in[4];
    const float* ln1g = (const float*)d_in[5];
    const float* ln1b = (const float*)d_in[6];
    const float* eclf = (const float*)d_in[7];
    const float* emap = (const float*)d_in[8];
    const float* ln2g = (const float*)d_in[9];
    const float* ln2b = (const float*)d_in[10];

    float *bufA, *bufB, *assign, *hfp, *ho;
    cudaGetSymbolAddress((void**)&bufA,   g_bufA);
    cudaGetSymbolAddress((void**)&bufB,   g_bufB);
    cudaGetSymbolAddress((void**)&assign, g_assign);
    cudaGetSymbolAddress((void**)&hfp,    g_hfp);
    cudaGetSymbolAddress((void**)&ho,     g_ho);

    cudaFuncSetAttribute(k_fused_out, cudaFuncAttributeMaxDynamicSharedMemorySize,
                         K3_SMEM_FLOATS * (int)sizeof(float));

    const float* cur = x;
    float* outs[3] = { bufA, bufB, (float*)d_out };

    for (int i = 0; i < 3; i++) {
        dim3 g1(BN, K1_BLOCKS_PER_B);
        k_assign_hf<<<g1, 256>>>(cur, eclf, assign, hfp);
        k_edge_mix<<<BN, 256>>>(hfp, emap, ho);
        dim3 g3(BN, K3_BLOCKS_PER_B);
        k_fused_out<<<g3, 256, K3_SMEM_FLOATS * sizeof(float)>>>(
            cur, W1 + i*DD*DD, b1 + i*DD, W2 + i*DD*DD, b2 + i*DD,
            ln1g + i*DD, ln1b + i*DD, ln2g, ln2b,
            assign, ho, outs[i]);
        cur = outs[i];
    }
}

// round 6
// speedup vs baseline: 1.5476x; 1.2010x over previous
#include <cuda_runtime.h>

#define BN 64
#define TT 12
#define NN 716
#define DD 64
#define EE 32
#define TN 8592            // TT*NN
#define XELEMS 35192832    // BN*TN*DD

typedef unsigned long long ull;

#define K1_STAGE 64
#define K1_STAGES 4
#define K1_CHUNK (K1_STAGE*K1_STAGES)                     // 256
#define K1_BLOCKS_PER_B ((TN + K1_CHUNK - 1)/K1_CHUNK)    // 34

__device__ float g_bufA[XELEMS];
__device__ float g_bufB[XELEMS];
__device__ float g_assign[(size_t)BN*TN*EE];
__device__ float g_hfp[(size_t)BN*K1_BLOCKS_PER_B*EE*DD];   // per-chunk partials
__device__ float g_ho[BN*EE*DD];

__device__ __forceinline__ ull fma2(ull a, ull b, ull c) {
    ull d;
    asm("fma.rn.f32x2 %0, %1, %2, %3;" : "=l"(d) : "l"(a), "l"(b), "l"(c));
    return d;
}
__device__ __forceinline__ ull packdup(float m) {
    ull d;
    asm("mov.b64 %0, {%1, %1};" : "=l"(d) : "f"(m));
    return d;
}
__device__ __forceinline__ ull pack2(float lo, float hi) {
    ull d;
    asm("mov.b64 %0, {%1, %2};" : "=l"(d) : "f"(lo), "f"(hi));
    return d;
}
__device__ __forceinline__ void unpack2(ull v, float& lo, float& hi) {
    asm("mov.b64 {%0, %1}, %2;" : "=f"(lo), "=f"(hi) : "l"(v));
}

// ============================ K1: assign + hf partials ============================
__global__ __launch_bounds__(256) void k_assign_hf(
    const float* __restrict__ x, const float* __restrict__ edge_clf,
    float* __restrict__ assign, float* __restrict__ hfp)
{
    __shared__ float ecp4[16*32*4];  // [k4][e][kk] = ec[4k4+kk][e]
    __shared__ float xs[64][64];
    __shared__ float as[64][32];
    int tid = threadIdx.x;
    int b = blockIdx.x;
    int r0base = blockIdx.y * K1_CHUNK;
    int lane = tid & 31, warp = tid >> 5;

    // rank-1 mapping: 2 groups x 128 threads; thread owns 2e x 8d
    int group = tid >> 7;
    int gtid  = tid & 127;
    int e0    = (gtid >> 3) * 2;
    int dbase = (gtid & 7) * 8;

    for (int i = tid; i < 64*32; i += 256) {
        int k = i >> 5, e = i & 31;
        ecp4[(k>>2)*128 + e*4 + (k&3)] = edge_clf[i];
    }

    ull acc[8];
    #pragma unroll
    for (int j = 0; j < 8; j++) acc[j] = 0ull;

    const float* xb = x + (size_t)b*TN*DD;

    for (int s = 0; s < K1_STAGES; s++) {
        int r0 = r0base + s*K1_STAGE;
        __syncthreads();
        #pragma unroll
        for (int p = 0; p < 4; p++) {
            int row = p*16 + (tid >> 4);
            int q = (tid & 15) * 4;
            int gr = r0 + row;
            float4 v = make_float4(0.f,0.f,0.f,0.f);
            if (gr < TN) v = *(const float4*)(xb + (size_t)gr*DD + q);
            *(float4*)(&xs[row][q]) = v;
        }
        __syncthreads();
        // ---- logits via fma2 over k4 chunks: warp -> rows warp*8..+7, lane = e ----
        {
            ull v2[8];
            #pragma unroll
            for (int j = 0; j < 8; j++) v2[j] = 0ull;
            #pragma unroll 4
            for (int k4 = 0; k4 < 16; k4++) {
                ulonglong2 ev = *(const ulonglong2*)&ecp4[k4*128 + lane*4];
                #pragma unroll
                for (int j = 0; j < 8; j++) {
                    ulonglong2 xv = *(const ulonglong2*)&xs[warp*8 + j][4*k4];
                    v2[j] = fma2(xv.x, ev.x, v2[j]);
                    v2[j] = fma2(xv.y, ev.y, v2[j]);
                }
            }
            #pragma unroll
            for (int j = 0; j < 8; j++) {
                int r = warp*8 + j;
                int gr = r0 + r;
                float vlo, vhi;
                unpack2(v2[j], vlo, vhi);
                float v = vlo + vhi;
                float m = v;
                #pragma unroll
                for (int o = 16; o; o >>= 1) m = fmaxf(m, __shfl_xor_sync(0xffffffffu, m, o));
                float ex = __expf(v - m);
                float sm = ex;
                #pragma unroll
                for (int o = 16; o; o >>= 1) sm += __shfl_xor_sync(0xffffffffu, sm, o);
                float p = ex / sm;
                bool valid = (gr < TN);
                as[r][lane] = valid ? p : 0.f;
                if (valid) assign[((size_t)b*TN + gr)*EE + lane] = p;
            }
        }
        __syncthreads();
        // ---- rank-1: group g handles stage rows [g*32, g*32+32), 2e x 8d per thread ----
        #pragma unroll 4
        for (int rl = 0; rl < 32; rl++) {
            int r = group*32 + rl;
            ull a2 = *(const ull*)&as[r][e0];
            float a0, a1;
            unpack2(a2, a0, a1);
            ull ad0 = packdup(a0), ad1 = packdup(a1);
            ulonglong2 xlo = *(const ulonglong2*)&xs[r][dbase];
            ulonglong2 xhi = *(const ulonglong2*)&xs[r][dbase+4];
            acc[0] = fma2(ad0, xlo.x, acc[0]); acc[1] = fma2(ad0, xlo.y, acc[1]);
            acc[2] = fma2(ad0, xhi.x, acc[2]); acc[3] = fma2(ad0, xhi.y, acc[3]);
            acc[4] = fma2(ad1, xlo.x, acc[4]); acc[5] = fma2(ad1, xlo.y, acc[5]);
            acc[6] = fma2(ad1, xhi.x, acc[6]); acc[7] = fma2(ad1, xhi.y, acc[7]);
        }
    }

    // ---- combine the two row-groups and store partials ----
    __syncthreads();
    float* pbuf = &xs[0][0];   // reuse (2048 floats)
    if (group == 1) {
        *(ulonglong2*)&pbuf[e0*64 + dbase]       = make_ulonglong2(acc[0], acc[1]);
        *(ulonglong2*)&pbuf[e0*64 + dbase + 4]   = make_ulonglong2(acc[2], acc[3]);
        *(ulonglong2*)&pbuf[(e0+1)*64 + dbase]   = make_ulonglong2(acc[4], acc[5]);
        *(ulonglong2*)&pbuf[(e0+1)*64 + dbase+4] = make_ulonglong2(acc[6], acc[7]);
    }
    __syncthreads();
    if (group == 0) {
        float* hp = hfp + ((size_t)b*K1_BLOCKS_PER_B + blockIdx.y)*(EE*DD);
        #pragma unroll
        for (int ee = 0; ee < 2; ee++) {
            float4 o0, o1;
            float t0, t1;
            unpack2(acc[ee*4+0], t0, t1); o0.x = t0; o0.y = t1;
            unpack2(acc[ee*4+1], t0, t1); o0.z = t0; o0.w = t1;
            unpack2(acc[ee*4+2], t0, t1); o1.x = t0; o1.y = t1;
            unpack2(acc[ee*4+3], t0, t1); o1.z = t0; o1.w = t1;
            const float* pp = &pbuf[(e0+ee)*64 + dbase];
            float4 p0 = *(const float4*)pp;
            float4 p1 = *(const float4*)(pp + 4);
            o0.x += p0.x; o0.y += p0.y; o0.z += p0.z; o0.w += p0.w;
            o1.x += p1.x; o1.y += p1.y; o1.z += p1.z; o1.w += p1.w;
            *(float4*)(hp + (e0+ee)*64 + dbase)     = o0;
            *(float4*)(hp + (e0+ee)*64 + dbase + 4) = o1;
        }
    }
}

// ============================ K2: reduce partials + edge mix ============================
__global__ __launch_bounds__(256) void k_edge_mix(
    const float* __restrict__ hfp, const float* __restrict__ edge_map,
    float* __restrict__ ho)
{
    __shared__ float hfs[32][64];
    __shared__ float em[32][32];
    int tid = threadIdx.x;
    int b = blockIdx.x;
    float4 s0 = make_float4(0.f,0.f,0.f,0.f), s1 = make_float4(0.f,0.f,0.f,0.f);
    const float* pb = hfp + (size_t)b*K1_BLOCKS_PER_B*(EE*DD) + tid*8;
    #pragma unroll 2
    for (int c = 0; c < K1_BLOCKS_PER_B; c++) {
        float4 a0 = *(const float4*)(pb + (size_t)c*(EE*DD));
        float4 a1 = *(const float4*)(pb + (size_t)c*(EE*DD) + 4);
        s0.x += a0.x; s0.y += a0.y; s0.z += a0.z; s0.w += a0.w;
        s1.x += a1.x; s1.y += a1.y; s1.z += a1.z; s1.w += a1.w;
    }
    int e = tid >> 3, dbase = (tid & 7) * 8;
    *(float4*)&hfs[e][dbase]     = s0;
    *(float4*)&hfs[e][dbase + 4] = s1;
    for (int i = tid; i < 1024; i += 256) em[i>>5][i&31] = edge_map[i];
    __syncthreads();
    float o[8];
    #pragma unroll
    for (int j = 0; j < 8; j++) o[j] = 0.f;
    #pragma unroll
    for (int f = 0; f < 32; f++) {
        float w = em[e][f];
        #pragma unroll
        for (int j = 0; j < 8; j++) o[j] = fmaf(w, hfs[f][dbase + j], o[j]);
    }
    float* ob = ho + b*EE*DD + e*DD + dbase;
    #pragma unroll
    for (int j = 0; j < 8; j++) ob[j] = fmaxf(o[j], 0.f) + hfs[e][dbase + j];
}

// ============================ K3: fused output (unchanged from R5) ============================
#define K3_ROWS 64
#define K3_BLOCKS_PER_B ((TN + K3_ROWS - 1)/K3_ROWS)   // 135
#define K3_SMEM_FLOATS (8192 + 2048 + 384 + 4096 + 2048)

__global__ __launch_bounds__(256, 3) void k_fused_out(
    const float* __restrict__ x,
    const float* __restrict__ W1, const float* __restrict__ b1,
    const float* __restrict__ W2, const float* __restrict__ b2,
    const float* __restrict__ ln1g, const float* __restrict__ ln1b,
    const float* __restrict__ ln2g, const float* __restrict__ ln2b,
    const float* __restrict__ assign, const float* __restrict__ ho,
    float* __restrict__ out)
{
    extern __shared__ float smem[];
    float* w4s = smem;              // [k][128]
    float* hos = w4s + 8192;        // [e][64]
    float* prm = hos + 2048;        // [6][64]
    float* xms = prm + 384;         // [warp][8][64]
    float* ass = xms + 4096;        // [warp][8][32]

    int tid = threadIdx.x;
    int b = blockIdx.x;
    int lane = tid & 31, warp = tid >> 5;

    for (int i = tid; i < 4096; i += 256) {
        int k = i >> 6, c = i & 63;
        int p = c >> 1, q = c & 1;
        w4s[k*128 + p*4 + q]     = W1[i];
        w4s[k*128 + p*4 + 2 + q] = W2[i];
    }
    for (int i = tid; i < 2048; i += 256) hos[i] = ho[b*EE*DD + i];
    if (tid < 64) {
        prm[0*64 + tid] = b1[tid];   prm[1*64 + tid] = b2[tid];
        prm[2*64 + tid] = ln1g[tid]; prm[3*64 + tid] = ln1b[tid];
        prm[4*64 + tid] = ln2g[tid]; prm[5*64 + tid] = ln2b[tid];
    }
    __syncthreads();

    int rowbase = blockIdx.y * K3_ROWS + warp * 8;
    const float* xb = x + (size_t)b*TN*DD;
    const float* ab = assign + (size_t)b*TN*EE;
    float* ob = out + (size_t)b*TN*DD;
    float* xmw = xms + warp*8*64;
    float* asw = ass + warp*8*32;

    #pragma unroll
    for (int r = 0; r < 8; r++) {
        int row = rowbase + r;
        float2 xv = make_float2(0.f, 0.f), xp = make_float2(0.f, 0.f);
        float a = 0.f;
        if (row < TN) {
            xv = *(const float2*)(xb + (size_t)row*DD + 2*lane);
            if (row >= NN) xp = *(const float2*)(xb + (size_t)(row - NN)*DD + 2*lane);
            a = ab[(size_t)row*EE + lane];
        }
        *(float2*)(xmw + r*64 + 2*lane) = make_float2(0.5f*(xv.x + xp.x), 0.5f*(xv.y + xp.y));
        asw[r*32 + lane] = a;
    }
    __syncwarp();

    ull B1p = pack2(prm[0*64 + 2*lane], prm[0*64 + 2*lane + 1]);
    ull B2p = pack2(prm[1*64 + 2*lane], prm[1*64 + 2*lane + 1]);
    ull G1[8], G2[8];
    #pragma unroll
    for (int r = 0; r < 8; r++) { G1[r] = B1p; G2[r] = B2p; }

    #pragma unroll 2
    for (int k4 = 0; k4 < 16; k4++) {
        ulonglong2 wv0 = *(const ulonglong2*)&w4s[(4*k4+0)*128 + lane*4];
        ulonglong2 wv1 = *(const ulonglong2*)&w4s[(4*k4+1)*128 + lane*4];
        ulonglong2 wv2 = *(const ulonglong2*)&w4s[(4*k4+2)*128 + lane*4];
        ulonglong2 wv3 = *(const ulonglong2*)&w4s[(4*k4+3)*128 + lane*4];
        #pragma unroll
        for (int r = 0; r < 8; r++) {
            float4 mv = *(const float4*)(xmw + r*64 + 4*k4);
            ull m0 = packdup(mv.x), m1 = packdup(mv.y);
            ull m2 = packdup(mv.z), m3 = packdup(mv.w);
            G1[r] = fma2(wv0.x, m0, G1[r]); G2[r] = fma2(wv0.y, m0, G2[r]);
            G1[r] = fma2(wv1.x, m1, G1[r]); G2[r] = fma2(wv1.y, m1, G2[r]);
            G1[r] = fma2(wv2.x, m2, G1[r]); G2[r] = fma2(wv2.y, m2, G2[r]);
            G1[r] = fma2(wv3.x, m3, G1[r]); G2[r] = fma2(wv3.y, m3, G2[r]);
        }
    }

    ull Y[8];
    #pragma unroll
    for (int r = 0; r < 8; r++) Y[r] = 0ull;
    #pragma unroll 4
    for (int e2 = 0; e2 < 16; e2++) {
        ull H0 = *(const ull*)&hos[(2*e2)*64 + 2*lane];
        ull H1 = *(const ull*)&hos[(2*e2+1)*64 + 2*lane];
        #pragma unroll
        for (int r = 0; r < 8; r++) {
            float2 a2 = *(const float2*)(asw + r*32 + 2*e2);
            Y[r] = fma2(H0, packdup(a2.x), Y[r]);
            Y[r] = fma2(H1, packdup(a2.y), Y[r]);
        }
    }

    float g1w = prm[2*64 + 2*lane], g1w2 = prm[2*64 + 2*lane + 1];
    float b1w = prm[3*64 + 2*lane], b1w2 = prm[3*64 + 2*lane + 1];
    float g2w = prm[4*64 + 2*lane], g2w2 = prm[4*64 + 2*lane + 1];
    float b2w = prm[5*64 + 2*lane], b2w2 = prm[5*64 + 2*lane + 1];

    #pragma unroll
    for (int r = 0; r < 8; r++) {
        int row = rowbase + r;
        if (row >= TN) break;   // warp-uniform
        float2 xv = *(const float2*)(xb + (size_t)row*DD + 2*lane);
        float g1a, g1b, g2a, g2b, y0, y1;
        unpack2(G1[r], g1a, g1b);
        unpack2(G2[r], g2a, g2b);
        unpack2(Y[r], y0, y1);
        float f0 = fmaxf(g1a*g2a, 0.f) + g1a + xv.x;
        float f1 = fmaxf(g1b*g2b, 0.f) + g1b + xv.y;
        float s = f0 + f1, s2 = f0*f0 + f1*f1;
        #pragma unroll
        for (int o = 16; o; o >>= 1) {
            s  += __shfl_xor_sync(0xffffffffu, s,  o);
            s2 += __shfl_xor_sync(0xffffffffu, s2, o);
        }
        float mu = s * (1.f/64.f);
        float var = s2 * (1.f/64.f) - mu*mu;
        float rs = rsqrtf(var + 1e-5f);
        float o1a = (f0 - mu)*rs*g1w + b1w;
        float o1b = (f1 - mu)*rs*g1w2 + b1w2;

        float h0 = fmaxf(y0, 0.f) + xv.x;
        float h1 = fmaxf(y1, 0.f) + xv.y;
        s = h0 + h1; s2 = h0*h0 + h1*h1;
        #pragma unroll
        for (int o = 16; o; o >>= 1) {
            s  += __shfl_xor_sync(0xffffffffu, s,  o);
            s2 += __shfl_xor_sync(0xffffffffu, s2, o);
        }
        mu = s * (1.f/64.f);
        var = s2 * (1.f/64.f) - mu*mu;
        rs = rsqrtf(var + 1e-5f);
        float o2a = (h0 - mu)*rs*g2w + b2w;
        float o2b = (h1 - mu)*rs*g2w2 + b2w2;

        *(float2*)(ob + (size_t)row*DD + 2*lane) =
            make_float2(0.5f*(o1a + o2a), 0.5f*(o1b + o2b));
    }
}

extern "C" void kernel_launch(void* const* d_in, const int* in_sizes, int n_in,
                              void* d_out, int out_size) {
    const float* x    = (const float*)d_in[0];
    const float* W1   = (const float*)d_in[1];
    const float* b1   = (const float*)d_in[2];
    const float* W2   = (const float*)d_in[3];
    const float* b2   = (const float*)d_in[4];
    const float* ln1g = (const float*)d_in[5];
    const float* ln1b = (const float*)d_in[6];
    const float* eclf = (const float*)d_in[7];
    const float* emap = (const float*)d_in[8];
    const float* ln2g = (const float*)d_in[9];
    const float* ln2b = (const float*)d_in[10];

    float *bufA, *bufB, *assign, *hfp, *ho;
    cudaGetSymbolAddress((void**)&bufA,   g_bufA);
    cudaGetSymbolAddress((void**)&bufB,   g_bufB);
    cudaGetSymbolAddress((void**)&assign, g_assign);
    cudaGetSymbolAddress((void**)&hfp,    g_hfp);
    cudaGetSymbolAddress((void**)&ho,     g_ho);

    cudaFuncSetAttribute(k_fused_out, cudaFuncAttributeMaxDynamicSharedMemorySize,
                         K3_SMEM_FLOATS * (int)sizeof(float));

    const float* cur = x;
    float* outs[3] = { bufA, bufB, (float*)d_out };

    for (int i = 0; i < 3; i++) {
        dim3 g1(BN, K1_BLOCKS_PER_B);
        k_assign_hf<<<g1, 256>>>(cur, eclf, assign, hfp);
        k_edge_mix<<<BN, 256>>>(hfp, emap, ho);
        dim3 g3(BN, K3_BLOCKS_PER_B);
        k_fused_out<<<g3, 256, K3_SMEM_FLOATS * sizeof(float)>>>(
            cur, W1 + i*DD*DD, b1 + i*DD, W2 + i*DD*DD, b2 + i*DD,
            ln1g + i*DD, ln1b + i*DD, ln2g, ln2b,
            assign, ho, outs[i]);
        cur = outs[i];
    }
}

// round 7
// speedup vs baseline: 1.5611x; 1.0087x over previous
#include <cuda_runtime.h>

#define BN 64
#define TT 12
#define NN 716
#define DD 64
#define EE 32
#define TN 8592            // TT*NN
#define XELEMS 35192832    // BN*TN*DD

typedef unsigned long long ull;

#define K1_STAGE 64
#define K1_STAGES 4
#define K1_CHUNK (K1_STAGE*K1_STAGES)                     // 256
#define K1_BLOCKS_PER_B ((TN + K1_CHUNK - 1)/K1_CHUNK)    // 34

__device__ float g_bufA[XELEMS];
__device__ float g_bufB[XELEMS];
__device__ float g_assign[(size_t)BN*TN*EE];
__device__ float g_hfp[(size_t)BN*K1_BLOCKS_PER_B*EE*DD];   // per-chunk partials
__device__ float g_ho[BN*EE*DD];

__device__ __forceinline__ ull fma2(ull a, ull b, ull c) {
    ull d;
    asm("fma.rn.f32x2 %0, %1, %2, %3;" : "=l"(d) : "l"(a), "l"(b), "l"(c));
    return d;
}
__device__ __forceinline__ ull packdup(float m) {
    ull d;
    asm("mov.b64 %0, {%1, %1};" : "=l"(d) : "f"(m));
    return d;
}
__device__ __forceinline__ ull pack2(float lo, float hi) {
    ull d;
    asm("mov.b64 %0, {%1, %2};" : "=l"(d) : "f"(lo), "f"(hi));
    return d;
}
__device__ __forceinline__ void unpack2(ull v, float& lo, float& hi) {
    asm("mov.b64 {%0, %1}, %2;" : "=f"(lo), "=f"(hi) : "l"(v));
}

// ============================ K1: assign + hf partials ============================
__global__ __launch_bounds__(256) void k_assign_hf(
    const float* __restrict__ x, const float* __restrict__ edge_clf,
    float* __restrict__ assign, float* __restrict__ hfp)
{
    __shared__ float ecp4[16*32*4];  // [k4][e][kk] = ec[4k4+kk][e]
    __shared__ float xs[64][64];
    __shared__ float as[64][32];
    int tid = threadIdx.x;
    int b = blockIdx.x;
    int r0base = blockIdx.y * K1_CHUNK;
    int lane = tid & 31, warp = tid >> 5;

    // rank-1 mapping: 4 groups x 64 threads; thread owns 4e x 8d, group -> 16 rows/stage
    int group = tid >> 6;
    int gtid  = tid & 63;
    int e0    = (gtid >> 3) * 4;
    int dbase = (gtid & 7) * 8;

    for (int i = tid; i < 64*32; i += 256) {
        int k = i >> 5, e = i & 31;
        ecp4[(k>>2)*128 + e*4 + (k&3)] = edge_clf[i];
    }

    ull acc[16];
    #pragma unroll
    for (int j = 0; j < 16; j++) acc[j] = 0ull;

    const float* xb = x + (size_t)b*TN*DD;

    for (int s = 0; s < K1_STAGES; s++) {
        int r0 = r0base + s*K1_STAGE;
        __syncthreads();
        #pragma unroll
        for (int p = 0; p < 4; p++) {
            int row = p*16 + (tid >> 4);
            int q = (tid & 15) * 4;
            int gr = r0 + row;
            float4 v = make_float4(0.f,0.f,0.f,0.f);
            if (gr < TN) v = *(const float4*)(xb + (size_t)gr*DD + q);
            *(float4*)(&xs[row][q]) = v;
        }
        __syncthreads();
        // ---- logits via fma2 over k4 chunks: warp -> rows warp*8..+7, lane = e ----
        {
            ull v2[8];
            #pragma unroll
            for (int j = 0; j < 8; j++) v2[j] = 0ull;
            #pragma unroll 4
            for (int k4 = 0; k4 < 16; k4++) {
                ulonglong2 ev = *(const ulonglong2*)&ecp4[k4*128 + lane*4];
                #pragma unroll
                for (int j = 0; j < 8; j++) {
                    ulonglong2 xv = *(const ulonglong2*)&xs[warp*8 + j][4*k4];
                    v2[j] = fma2(xv.x, ev.x, v2[j]);
                    v2[j] = fma2(xv.y, ev.y, v2[j]);
                }
            }
            #pragma unroll
            for (int j = 0; j < 8; j++) {
                int r = warp*8 + j;
                int gr = r0 + r;
                float vlo, vhi;
                unpack2(v2[j], vlo, vhi);
                float v = vlo + vhi;
                float m = v;
                #pragma unroll
                for (int o = 16; o; o >>= 1) m = fmaxf(m, __shfl_xor_sync(0xffffffffu, m, o));
                float ex = __expf(v - m);
                float sm = ex;
                #pragma unroll
                for (int o = 16; o; o >>= 1) sm += __shfl_xor_sync(0xffffffffu, sm, o);
                float p = ex / sm;
                bool valid = (gr < TN);
                as[r][lane] = valid ? p : 0.f;
                if (valid) assign[((size_t)b*TN + gr)*EE + lane] = p;
            }
        }
        __syncthreads();
        // ---- rank-1: group g -> stage rows [g*16, g*16+16), 4e x 8d per thread ----
        #pragma unroll 4
        for (int rl = 0; rl < 16; rl++) {
            int r = group*16 + rl;
            float4 a4 = *(const float4*)&as[r][e0];
            ull ad0 = packdup(a4.x), ad1 = packdup(a4.y);
            ull ad2 = packdup(a4.z), ad3 = packdup(a4.w);
            ulonglong2 xlo = *(const ulonglong2*)&xs[r][dbase];
            ulonglong2 xhi = *(const ulonglong2*)&xs[r][dbase+4];
            acc[0]  = fma2(ad0, xlo.x, acc[0]);  acc[1]  = fma2(ad0, xlo.y, acc[1]);
            acc[2]  = fma2(ad0, xhi.x, acc[2]);  acc[3]  = fma2(ad0, xhi.y, acc[3]);
            acc[4]  = fma2(ad1, xlo.x, acc[4]);  acc[5]  = fma2(ad1, xlo.y, acc[5]);
            acc[6]  = fma2(ad1, xhi.x, acc[6]);  acc[7]  = fma2(ad1, xhi.y, acc[7]);
            acc[8]  = fma2(ad2, xlo.x, acc[8]);  acc[9]  = fma2(ad2, xlo.y, acc[9]);
            acc[10] = fma2(ad2, xhi.x, acc[10]); acc[11] = fma2(ad2, xhi.y, acc[11]);
            acc[12] = fma2(ad3, xlo.x, acc[12]); acc[13] = fma2(ad3, xlo.y, acc[13]);
            acc[14] = fma2(ad3, xhi.x, acc[14]); acc[15] = fma2(ad3, xhi.y, acc[15]);
        }
    }

    // ---- combine the four row-groups (ecp4 and xs are dead now) and store ----
    __syncthreads();
    // partial regions: group1 -> xs[0..2047], group2 -> xs[2048..4095], group3 -> ecp4[0..2047]
    if (group != 0) {
        float* pr = (group == 1) ? &xs[0][0] : (group == 2) ? &xs[32][0] : &ecp4[0];
        #pragma unroll
        for (int ee = 0; ee < 4; ee++) {
            *(ulonglong2*)&pr[(e0+ee)*64 + dbase]     = make_ulonglong2(acc[ee*4+0], acc[ee*4+1]);
            *(ulonglong2*)&pr[(e0+ee)*64 + dbase + 4] = make_ulonglong2(acc[ee*4+2], acc[ee*4+3]);
        }
    }
    __syncthreads();
    if (group == 0) {
        float* hp = hfp + ((size_t)b*K1_BLOCKS_PER_B + blockIdx.y)*(EE*DD);
        #pragma unroll
        for (int ee = 0; ee < 4; ee++) {
            float4 o0, o1;
            float t0, t1;
            unpack2(acc[ee*4+0], t0, t1); o0.x = t0; o0.y = t1;
            unpack2(acc[ee*4+1], t0, t1); o0.z = t0; o0.w = t1;
            unpack2(acc[ee*4+2], t0, t1); o1.x = t0; o1.y = t1;
            unpack2(acc[ee*4+3], t0, t1); o1.z = t0; o1.w = t1;
            int off = (e0+ee)*64 + dbase;
            float4 p10 = *(const float4*)&xs[0][off];   // note: xs is [64][64] flat
            float4 p11 = *(const float4*)(&xs[0][0] + off + 4);
            float4 p20 = *(const float4*)(&xs[32][0] + off);
            float4 p21 = *(const float4*)(&xs[32][0] + off + 4);
            float4 p30 = *(const float4*)(&ecp4[0] + off);
            float4 p31 = *(const float4*)(&ecp4[0] + off + 4);
            o0.x += p10.x + p20.x + p30.x; o0.y += p10.y + p20.y + p30.y;
            o0.z += p10.z + p20.z + p30.z; o0.w += p10.w + p20.w + p30.w;
            o1.x += p11.x + p21.x + p31.x; o1.y += p11.y + p21.y + p31.y;
            o1.z += p11.z + p21.z + p31.z; o1.w += p11.w + p21.w + p31.w;
            *(float4*)(hp + off)     = o0;
            *(float4*)(hp + off + 4) = o1;
        }
    }
}

// ============================ K2: reduce partials + edge mix ============================
__global__ __launch_bounds__(256) void k_edge_mix(
    const float* __restrict__ hfp, const float* __restrict__ edge_map,
    float* __restrict__ ho)
{
    __shared__ float hfs[32][64];
    __shared__ float em[32][32];
    int tid = threadIdx.x;
    int b = blockIdx.x;
    float4 s0 = make_float4(0.f,0.f,0.f,0.f), s1 = make_float4(0.f,0.f,0.f,0.f);
    const float* pb = hfp + (size_t)b*K1_BLOCKS_PER_B*(EE*DD) + tid*8;
    #pragma unroll 2
    for (int c = 0; c < K1_BLOCKS_PER_B; c++) {
        float4 a0 = *(const float4*)(pb + (size_t)c*(EE*DD));
        float4 a1 = *(const float4*)(pb + (size_t)c*(EE*DD) + 4);
        s0.x += a0.x; s0.y += a0.y; s0.z += a0.z; s0.w += a0.w;
        s1.x += a1.x; s1.y += a1.y; s1.z += a1.z; s1.w += a1.w;
    }
    int e = tid >> 3, dbase = (tid & 7) * 8;
    *(float4*)&hfs[e][dbase]     = s0;
    *(float4*)&hfs[e][dbase + 4] = s1;
    for (int i = tid; i < 1024; i += 256) em[i>>5][i&31] = edge_map[i];
    __syncthreads();
    float o[8];
    #pragma unroll
    for (int j = 0; j < 8; j++) o[j] = 0.f;
    #pragma unroll
    for (int f = 0; f < 32; f++) {
        float w = em[e][f];
        #pragma unroll
        for (int j = 0; j < 8; j++) o[j] = fmaf(w, hfs[f][dbase + j], o[j]);
    }
    float* ob = ho + b*EE*DD + e*DD + dbase;
    #pragma unroll
    for (int j = 0; j < 8; j++) ob[j] = fmaxf(o[j], 0.f) + hfs[e][dbase + j];
}

// ============================ K3: fused output ============================
// 8 warps/block, 8 rows/warp. Main GEMV loop is MOV-free: xm staged DUPLICATED
// in a phase-split half-buffer (16KB), restaged per k-half from register-held m.
#define K3_ROWS 64
#define K3_BLOCKS_PER_B ((TN + K3_ROWS - 1)/K3_ROWS)   // 135
#define K3_SMEM_FLOATS (8192 + 4096 + 2048 + 384 + 2048)  // w4s + xmd_half + hos + prm + ass

__global__ __launch_bounds__(256, 3) void k_fused_out(
    const float* __restrict__ x,
    const float* __restrict__ W1, const float* __restrict__ b1,
    const float* __restrict__ W2, const float* __restrict__ b2,
    const float* __restrict__ ln1g, const float* __restrict__ ln1b,
    const float* __restrict__ ln2g, const float* __restrict__ ln2b,
    const float* __restrict__ assign, const float* __restrict__ ho,
    float* __restrict__ out)
{
    extern __shared__ float smem[];
    float* w4s = smem;              // [k][128]
    float* xmd = w4s + 8192;        // [warp][8 rows][64]: duplicated m for current k-half
    float* hos = xmd + 4096;        // [e][64]
    float* prm = hos + 2048;        // [6][64]
    float* ass = prm + 384;         // [warp][8][32]

    int tid = threadIdx.x;
    int b = blockIdx.x;
    int lane = tid & 31, warp = tid >> 5;

    for (int i = tid; i < 4096; i += 256) {
        int k = i >> 6, c = i & 63;
        int p = c >> 1, q = c & 1;
        w4s[k*128 + p*4 + q]     = W1[i];
        w4s[k*128 + p*4 + 2 + q] = W2[i];
    }
    for (int i = tid; i < 2048; i += 256) hos[i] = ho[b*EE*DD + i];
    if (tid < 64) {
        prm[0*64 + tid] = b1[tid];   prm[1*64 + tid] = b2[tid];
        prm[2*64 + tid] = ln1g[tid]; prm[3*64 + tid] = ln1b[tid];
        prm[4*64 + tid] = ln2g[tid]; prm[5*64 + tid] = ln2b[tid];
    }
    __syncthreads();

    int rowbase = blockIdx.y * K3_ROWS + warp * 8;
    const float* xb = x + (size_t)b*TN*DD;
    const float* ab = assign + (size_t)b*TN*EE;
    float* ob = out + (size_t)b*TN*DD;
    float* xhw = xmd + warp*8*64;
    float* asw = ass + warp*8*32;

    // ---- prologue: windowed mean into registers, assign staged ----
    float2 mv[8];
    #pragma unroll
    for (int r = 0; r < 8; r++) {
        int row = rowbase + r;
        float2 xv = make_float2(0.f, 0.f), xp = make_float2(0.f, 0.f);
        float a = 0.f;
        if (row < TN) {
            xv = *(const float2*)(xb + (size_t)row*DD + 2*lane);
            if (row >= NN) xp = *(const float2*)(xb + (size_t)(row - NN)*DD + 2*lane);
            a = ab[(size_t)row*EE + lane];
        }
        mv[r] = make_float2(0.5f*(xv.x + xp.x), 0.5f*(xv.y + xp.y));
        asw[r*32 + lane] = a;
    }

    // ---- main GEMVs: phase-split duplicated xm, MOV-free fma2 inner loop ----
    ull B1p = pack2(prm[0*64 + 2*lane], prm[0*64 + 2*lane + 1]);
    ull B2p = pack2(prm[1*64 + 2*lane], prm[1*64 + 2*lane + 1]);
    ull G1[8], G2[8];
    #pragma unroll
    for (int r = 0; r < 8; r++) { G1[r] = B1p; G2[r] = B2p; }

    #pragma unroll
    for (int ph = 0; ph < 2; ph++) {
        __syncwarp();
        if ((lane >> 4) == ph) {
            int off = 4*lane - 64*ph;      // 0..60 for lanes in this phase
            #pragma unroll
            for (int r = 0; r < 8; r++)
                *(float4*)(xhw + r*64 + off) = make_float4(mv[r].x, mv[r].x, mv[r].y, mv[r].y);
        }
        __syncwarp();
        #pragma unroll
        for (int k4l = 0; k4l < 8; k4l++) {
            int k4 = 8*ph + k4l;
            ulonglong2 wv0 = *(const ulonglong2*)&w4s[(4*k4+0)*128 + lane*4];
            ulonglong2 wv1 = *(const ulonglong2*)&w4s[(4*k4+1)*128 + lane*4];
            ulonglong2 wv2 = *(const ulonglong2*)&w4s[(4*k4+2)*128 + lane*4];
            ulonglong2 wv3 = *(const ulonglong2*)&w4s[(4*k4+3)*128 + lane*4];
            #pragma unroll
            for (int r = 0; r < 8; r++) {
                ulonglong2 ma = *(const ulonglong2*)(xhw + r*64 + 8*k4l);     // dup(m0),dup(m1)
                ulonglong2 mb = *(const ulonglong2*)(xhw + r*64 + 8*k4l + 4); // dup(m2),dup(m3)
                G1[r] = fma2(wv0.x, ma.x, G1[r]); G2[r] = fma2(wv0.y, ma.x, G2[r]);
                G1[r] = fma2(wv1.x, ma.y, G1[r]); G2[r] = fma2(wv1.y, ma.y, G2[r]);
                G1[r] = fma2(wv2.x, mb.x, G1[r]); G2[r] = fma2(wv2.y, mb.x, G2[r]);
                G1[r] = fma2(wv3.x, mb.y, G1[r]); G2[r] = fma2(wv3.y, mb.y, G2[r]);
            }
        }
    }

    // ---- hyper: Y = assign @ ho ----
    ull Y[8];
    #pragma unroll
    for (int r = 0; r < 8; r++) Y[r] = 0ull;
    #pragma unroll 4
    for (int e2 = 0; e2 < 16; e2++) {
        ull H0 = *(const ull*)&hos[(2*e2)*64 + 2*lane];
        ull H1 = *(const ull*)&hos[(2*e2+1)*64 + 2*lane];
        #pragma unroll
        for (int r = 0; r < 8; r++) {
            float2 a2 = *(const float2*)(asw + r*32 + 2*e2);
            Y[r] = fma2(H0, packdup(a2.x), Y[r]);
            Y[r] = fma2(H1, packdup(a2.y), Y[r]);
        }
    }

    // ---- epilogue ----
    float g1w = prm[2*64 + 2*lane], g1w2 = prm[2*64 + 2*lane + 1];
    float b1w = prm[3*64 + 2*lane], b1w2 = prm[3*64 + 2*lane + 1];
    float g2w = prm[4*64 + 2*lane], g2w2 = prm[4*64 + 2*lane + 1];
    float b2w = prm[5*64 + 2*lane], b2w2 = prm[5*64 + 2*lane + 1];

    #pragma unroll
    for (int r = 0; r < 8; r++) {
        int row = rowbase + r;
        if (row >= TN) break;   // warp-uniform
        float2 xv = *(const float2*)(xb + (size_t)row*DD + 2*lane);
        float g1a, g1b, g2a, g2b, y0, y1;
        unpack2(G1[r], g1a, g1b);
        unpack2(G2[r], g2a, g2b);
        unpack2(Y[r], y0, y1);
        float f0 = fmaxf(g1a*g2a, 0.f) + g1a + xv.x;
        float f1 = fmaxf(g1b*g2b, 0.f) + g1b + xv.y;
        float s = f0 + f1, s2 = f0*f0 + f1*f1;
        #pragma unroll
        for (int o = 16; o; o >>= 1) {
            s  += __shfl_xor_sync(0xffffffffu, s,  o);
            s2 += __shfl_xor_sync(0xffffffffu, s2, o);
        }
        float mu = s * (1.f/64.f);
        float var = s2 * (1.f/64.f) - mu*mu;
        float rs = rsqrtf(var + 1e-5f);
        float o1a = (f0 - mu)*rs*g1w + b1w;
        float o1b = (f1 - mu)*rs*g1w2 + b1w2;

        float h0 = fmaxf(y0, 0.f) + xv.x;
        float h1 = fmaxf(y1, 0.f) + xv.y;
        s = h0 + h1; s2 = h0*h0 + h1*h1;
        #pragma unroll
        for (int o = 16; o; o >>= 1) {
            s  += __shfl_xor_sync(0xffffffffu, s,  o);
            s2 += __shfl_xor_sync(0xffffffffu, s2, o);
        }
        mu = s * (1.f/64.f);
        var = s2 * (1.f/64.f) - mu*mu;
        rs = rsqrtf(var + 1e-5f);
        float o2a = (h0 - mu)*rs*g2w + b2w;
        float o2b = (h1 - mu)*rs*g2w2 + b2w2;

        *(float2*)(ob + (size_t)row*DD + 2*lane) =
            make_float2(0.5f*(o1a + o2a), 0.5f*(o1b + o2b));
    }
}

extern "C" void kernel_launch(void* const* d_in, const int* in_sizes, int n_in,
                              void* d_out, int out_size) {
    const float* x    = (const float*)d_in[0];
    const float* W1   = (const float*)d_in[1];
    const float* b1   = (const float*)d_in[2];
    const float* W2   = (const float*)d_in[3];
    const float* b2   = (const float*)d_in[4];
    const float* ln1g = (const float*)d_in[5];
    const float* ln1b = (const float*)d_in[6];
    const float* eclf = (const float*)d_in[7];
    const float* emap = (const float*)d_in[8];
    const float* ln2g = (const float*)d_in[9];
    const float* ln2b = (const float*)d_in[10];

    float *bufA, *bufB, *assign, *hfp, *ho;
    cudaGetSymbolAddress((void**)&bufA,   g_bufA);
    cudaGetSymbolAddress((void**)&bufB,   g_bufB);
    cudaGetSymbolAddress((void**)&assign, g_assign);
    cudaGetSymbolAddress((void**)&hfp,    g_hfp);
    cudaGetSymbolAddress((void**)&ho,     g_ho);

    cudaFuncSetAttribute(k_fused_out, cudaFuncAttributeMaxDynamicSharedMemorySize,
                         K3_SMEM_FLOATS * (int)sizeof(float));

    const float* cur = x;
    float* outs[3] = { bufA, bufB, (float*)d_out };

    for (int i = 0; i < 3; i++) {
        dim3 g1(BN, K1_BLOCKS_PER_B);
        k_assign_hf<<<g1, 256>>>(cur, eclf, assign, hfp);
        k_edge_mix<<<BN, 256>>>(hfp, emap, ho);
        dim3 g3(BN, K3_BLOCKS_PER_B);
        k_fused_out<<<g3, 256, K3_SMEM_FLOATS * sizeof(float)>>>(
            cur, W1 + i*DD*DD, b1 + i*DD, W2 + i*DD*DD, b2 + i*DD,
            ln1g + i*DD, ln1b + i*DD, ln2g, ln2b,
            assign, ho, outs[i]);
        cur = outs[i];
    }
}

// round 8
// speedup vs baseline: 1.6856x; 1.0798x over previous
#include <cuda_runtime.h>

#define BN 64
#define TT 12
#define NN 716
#define DD 64
#define EE 32
#define TN 8592            // TT*NN
#define XELEMS 35192832    // BN*TN*DD

typedef unsigned long long ull;

#define K1_STAGE 64
#define K1_STAGES 4
#define K1_CHUNK (K1_STAGE*K1_STAGES)                     // 256
#define K1_BLOCKS_PER_B ((TN + K1_CHUNK - 1)/K1_CHUNK)    // 34

__device__ float g_bufA[XELEMS];
__device__ float g_bufB[XELEMS];
__device__ float g_assign[(size_t)BN*TN*EE];
__device__ float g_hfp[(size_t)BN*K1_BLOCKS_PER_B*EE*DD];   // per-chunk partials
__device__ float g_ho[BN*EE*DD];

__device__ __forceinline__ ull fma2(ull a, ull b, ull c) {
    ull d;
    asm("fma.rn.f32x2 %0, %1, %2, %3;" : "=l"(d) : "l"(a), "l"(b), "l"(c));
    return d;
}
__device__ __forceinline__ ull packdup(float m) {
    ull d;
    asm("mov.b64 %0, {%1, %1};" : "=l"(d) : "f"(m));
    return d;
}
__device__ __forceinline__ ull pack2(float lo, float hi) {
    ull d;
    asm("mov.b64 %0, {%1, %2};" : "=l"(d) : "f"(lo), "f"(hi));
    return d;
}
__device__ __forceinline__ void unpack2(ull v, float& lo, float& hi) {
    asm("mov.b64 {%0, %1}, %2;" : "=f"(lo), "=f"(hi) : "l"(v));
}

// ============================ K1: assign + hf partials (R7 version, verified 203us) ============================
__global__ __launch_bounds__(256) void k_assign_hf(
    const float* __restrict__ x, const float* __restrict__ edge_clf,
    float* __restrict__ assign, float* __restrict__ hfp)
{
    __shared__ float ecp4[16*32*4];  // [k4][e][kk] = ec[4k4+kk][e]
    __shared__ float xs[64][64];
    __shared__ float as[64][32];
    int tid = threadIdx.x;
    int b = blockIdx.x;
    int r0base = blockIdx.y * K1_CHUNK;
    int lane = tid & 31, warp = tid >> 5;

    // rank-1 mapping: 4 groups x 64 threads; thread owns 4e x 8d, group -> 16 rows/stage
    int group = tid >> 6;
    int gtid  = tid & 63;
    int e0    = (gtid >> 3) * 4;
    int dbase = (gtid & 7) * 8;

    for (int i = tid; i < 64*32; i += 256) {
        int k = i >> 5, e = i & 31;
        ecp4[(k>>2)*128 + e*4 + (k&3)] = edge_clf[i];
    }

    ull acc[16];
    #pragma unroll
    for (int j = 0; j < 16; j++) acc[j] = 0ull;

    const float* xb = x + (size_t)b*TN*DD;

    for (int s = 0; s < K1_STAGES; s++) {
        int r0 = r0base + s*K1_STAGE;
        __syncthreads();
        #pragma unroll
        for (int p = 0; p < 4; p++) {
            int row = p*16 + (tid >> 4);
            int q = (tid & 15) * 4;
            int gr = r0 + row;
            float4 v = make_float4(0.f,0.f,0.f,0.f);
            if (gr < TN) v = *(const float4*)(xb + (size_t)gr*DD + q);
            *(float4*)(&xs[row][q]) = v;
        }
        __syncthreads();
        // ---- logits via fma2 over k4 chunks: warp -> rows warp*8..+7, lane = e ----
        {
            ull v2[8];
            #pragma unroll
            for (int j = 0; j < 8; j++) v2[j] = 0ull;
            #pragma unroll 4
            for (int k4 = 0; k4 < 16; k4++) {
                ulonglong2 ev = *(const ulonglong2*)&ecp4[k4*128 + lane*4];
                #pragma unroll
                for (int j = 0; j < 8; j++) {
                    ulonglong2 xv = *(const ulonglong2*)&xs[warp*8 + j][4*k4];
                    v2[j] = fma2(xv.x, ev.x, v2[j]);
                    v2[j] = fma2(xv.y, ev.y, v2[j]);
                }
            }
            #pragma unroll
            for (int j = 0; j < 8; j++) {
                int r = warp*8 + j;
                int gr = r0 + r;
                float vlo, vhi;
                unpack2(v2[j], vlo, vhi);
                float v = vlo + vhi;
                float m = v;
                #pragma unroll
                for (int o = 16; o; o >>= 1) m = fmaxf(m, __shfl_xor_sync(0xffffffffu, m, o));
                float ex = __expf(v - m);
                float sm = ex;
                #pragma unroll
                for (int o = 16; o; o >>= 1) sm += __shfl_xor_sync(0xffffffffu, sm, o);
                float p = ex / sm;
                bool valid = (gr < TN);
                as[r][lane] = valid ? p : 0.f;
                if (valid) assign[((size_t)b*TN + gr)*EE + lane] = p;
            }
        }
        __syncthreads();
        // ---- rank-1: group g -> stage rows [g*16, g*16+16), 4e x 8d per thread ----
        #pragma unroll 4
        for (int rl = 0; rl < 16; rl++) {
            int r = group*16 + rl;
            float4 a4 = *(const float4*)&as[r][e0];
            ull ad0 = packdup(a4.x), ad1 = packdup(a4.y);
            ull ad2 = packdup(a4.z), ad3 = packdup(a4.w);
            ulonglong2 xlo = *(const ulonglong2*)&xs[r][dbase];
            ulonglong2 xhi = *(const ulonglong2*)&xs[r][dbase+4];
            acc[0]  = fma2(ad0, xlo.x, acc[0]);  acc[1]  = fma2(ad0, xlo.y, acc[1]);
            acc[2]  = fma2(ad0, xhi.x, acc[2]);  acc[3]  = fma2(ad0, xhi.y, acc[3]);
            acc[4]  = fma2(ad1, xlo.x, acc[4]);  acc[5]  = fma2(ad1, xlo.y, acc[5]);
            acc[6]  = fma2(ad1, xhi.x, acc[6]);  acc[7]  = fma2(ad1, xhi.y, acc[7]);
            acc[8]  = fma2(ad2, xlo.x, acc[8]);  acc[9]  = fma2(ad2, xlo.y, acc[9]);
            acc[10] = fma2(ad2, xhi.x, acc[10]); acc[11] = fma2(ad2, xhi.y, acc[11]);
            acc[12] = fma2(ad3, xlo.x, acc[12]); acc[13] = fma2(ad3, xlo.y, acc[13]);
            acc[14] = fma2(ad3, xhi.x, acc[14]); acc[15] = fma2(ad3, xhi.y, acc[15]);
        }
    }

    // ---- combine the four row-groups (ecp4 and xs are dead now) and store ----
    __syncthreads();
    if (group != 0) {
        float* pr = (group == 1) ? &xs[0][0] : (group == 2) ? &xs[32][0] : &ecp4[0];
        #pragma unroll
        for (int ee = 0; ee < 4; ee++) {
            *(ulonglong2*)&pr[(e0+ee)*64 + dbase]     = make_ulonglong2(acc[ee*4+0], acc[ee*4+1]);
            *(ulonglong2*)&pr[(e0+ee)*64 + dbase + 4] = make_ulonglong2(acc[ee*4+2], acc[ee*4+3]);
        }
    }
    __syncthreads();
    if (group == 0) {
        float* hp = hfp + ((size_t)b*K1_BLOCKS_PER_B + blockIdx.y)*(EE*DD);
        #pragma unroll
        for (int ee = 0; ee < 4; ee++) {
            float4 o0, o1;
            float t0, t1;
            unpack2(acc[ee*4+0], t0, t1); o0.x = t0; o0.y = t1;
            unpack2(acc[ee*4+1], t0, t1); o0.z = t0; o0.w = t1;
            unpack2(acc[ee*4+2], t0, t1); o1.x = t0; o1.y = t1;
            unpack2(acc[ee*4+3], t0, t1); o1.z = t0; o1.w = t1;
            int off = (e0+ee)*64 + dbase;
            float4 p10 = *(const float4*)(&xs[0][0] + off);
            float4 p11 = *(const float4*)(&xs[0][0] + off + 4);
            float4 p20 = *(const float4*)(&xs[32][0] + off);
            float4 p21 = *(const float4*)(&xs[32][0] + off + 4);
            float4 p30 = *(const float4*)(&ecp4[0] + off);
            float4 p31 = *(const float4*)(&ecp4[0] + off + 4);
            o0.x += p10.x + p20.x + p30.x; o0.y += p10.y + p20.y + p30.y;
            o0.z += p10.z + p20.z + p30.z; o0.w += p10.w + p20.w + p30.w;
            o1.x += p11.x + p21.x + p31.x; o1.y += p11.y + p21.y + p31.y;
            o1.z += p11.z + p21.z + p31.z; o1.w += p11.w + p21.w + p31.w;
            *(float4*)(hp + off)     = o0;
            *(float4*)(hp + off + 4) = o1;
        }
    }
}

// ============================ K2: reduce partials + edge mix ============================
__global__ __launch_bounds__(256) void k_edge_mix(
    const float* __restrict__ hfp, const float* __restrict__ edge_map,
    float* __restrict__ ho)
{
    __shared__ float hfs[32][64];
    __shared__ float em[32][32];
    int tid = threadIdx.x;
    int b = blockIdx.x;
    float4 s0 = make_float4(0.f,0.f,0.f,0.f), s1 = make_float4(0.f,0.f,0.f,0.f);
    const float* pb = hfp + (size_t)b*K1_BLOCKS_PER_B*(EE*DD) + tid*8;
    #pragma unroll 2
    for (int c = 0; c < K1_BLOCKS_PER_B; c++) {
        float4 a0 = *(const float4*)(pb + (size_t)c*(EE*DD));
        float4 a1 = *(const float4*)(pb + (size_t)c*(EE*DD) + 4);
        s0.x += a0.x; s0.y += a0.y; s0.z += a0.z; s0.w += a0.w;
        s1.x += a1.x; s1.y += a1.y; s1.z += a1.z; s1.w += a1.w;
    }
    int e = tid >> 3, dbase = (tid & 7) * 8;
    *(float4*)&hfs[e][dbase]     = s0;
    *(float4*)&hfs[e][dbase + 4] = s1;
    for (int i = tid; i < 1024; i += 256) em[i>>5][i&31] = edge_map[i];
    __syncthreads();
    float o[8];
    #pragma unroll
    for (int j = 0; j < 8; j++) o[j] = 0.f;
    #pragma unroll
    for (int f = 0; f < 32; f++) {
        float w = em[e][f];
        #pragma unroll
        for (int j = 0; j < 8; j++) o[j] = fmaf(w, hfs[f][dbase + j], o[j]);
    }
    float* ob = ho + b*EE*DD + e*DD + dbase;
    #pragma unroll
    for (int j = 0; j < 8; j++) ob[j] = fmaxf(o[j], 0.f) + hfs[e][dbase + j];
}

// ============================ K3: fused output (R6 version, verified ~359us/layer) ============================
#define K3_ROWS 64
#define K3_BLOCKS_PER_B ((TN + K3_ROWS - 1)/K3_ROWS)   // 135
#define K3_SMEM_FLOATS (8192 + 2048 + 384 + 4096 + 2048)

__global__ __launch_bounds__(256, 3) void k_fused_out(
    const float* __restrict__ x,
    const float* __restrict__ W1, const float* __restrict__ b1,
    const float* __restrict__ W2, const float* __restrict__ b2,
    const float* __restrict__ ln1g, const float* __restrict__ ln1b,
    const float* __restrict__ ln2g, const float* __restrict__ ln2b,
    const float* __restrict__ assign, const float* __restrict__ ho,
    float* __restrict__ out)
{
    extern __shared__ float smem[];
    float* w4s = smem;              // [k][128]
    float* hos = w4s + 8192;        // [e][64]
    float* prm = hos + 2048;        // [6][64]
    float* xms = prm + 384;         // [warp][8][64]
    float* ass = xms + 4096;        // [warp][8][32]

    int tid = threadIdx.x;
    int b = blockIdx.x;
    int lane = tid & 31, warp = tid >> 5;

    for (int i = tid; i < 4096; i += 256) {
        int k = i >> 6, c = i & 63;
        int p = c >> 1, q = c & 1;
        w4s[k*128 + p*4 + q]     = W1[i];
        w4s[k*128 + p*4 + 2 + q] = W2[i];
    }
    for (int i = tid; i < 2048; i += 256) hos[i] = ho[b*EE*DD + i];
    if (tid < 64) {
        prm[0*64 + tid] = b1[tid];   prm[1*64 + tid] = b2[tid];
        prm[2*64 + tid] = ln1g[tid]; prm[3*64 + tid] = ln1b[tid];
        prm[4*64 + tid] = ln2g[tid]; prm[5*64 + tid] = ln2b[tid];
    }
    __syncthreads();

    int rowbase = blockIdx.y * K3_ROWS + warp * 8;
    const float* xb = x + (size_t)b*TN*DD;
    const float* ab = assign + (size_t)b*TN*EE;
    float* ob = out + (size_t)b*TN*DD;
    float* xmw = xms + warp*8*64;
    float* asw = ass + warp*8*32;

    #pragma unroll
    for (int r = 0; r < 8; r++) {
        int row = rowbase + r;
        float2 xv = make_float2(0.f, 0.f), xp = make_float2(0.f, 0.f);
        float a = 0.f;
        if (row < TN) {
            xv = *(const float2*)(xb + (size_t)row*DD + 2*lane);
            if (row >= NN) xp = *(const float2*)(xb + (size_t)(row - NN)*DD + 2*lane);
            a = ab[(size_t)row*EE + lane];
        }
        *(float2*)(xmw + r*64 + 2*lane) = make_float2(0.5f*(xv.x + xp.x), 0.5f*(xv.y + xp.y));
        asw[r*32 + lane] = a;
    }
    __syncwarp();

    ull B1p = pack2(prm[0*64 + 2*lane], prm[0*64 + 2*lane + 1]);
    ull B2p = pack2(prm[1*64 + 2*lane], prm[1*64 + 2*lane + 1]);
    ull G1[8], G2[8];
    #pragma unroll
    for (int r = 0; r < 8; r++) { G1[r] = B1p; G2[r] = B2p; }

    #pragma unroll 2
    for (int k4 = 0; k4 < 16; k4++) {
        ulonglong2 wv0 = *(const ulonglong2*)&w4s[(4*k4+0)*128 + lane*4];
        ulonglong2 wv1 = *(const ulonglong2*)&w4s[(4*k4+1)*128 + lane*4];
        ulonglong2 wv2 = *(const ulonglong2*)&w4s[(4*k4+2)*128 + lane*4];
        ulonglong2 wv3 = *(const ulonglong2*)&w4s[(4*k4+3)*128 + lane*4];
        #pragma unroll
        for (int r = 0; r < 8; r++) {
            float4 mv = *(const float4*)(xmw + r*64 + 4*k4);
            ull m0 = packdup(mv.x), m1 = packdup(mv.y);
            ull m2 = packdup(mv.z), m3 = packdup(mv.w);
            G1[r] = fma2(wv0.x, m0, G1[r]); G2[r] = fma2(wv0.y, m0, G2[r]);
            G1[r] = fma2(wv1.x, m1, G1[r]); G2[r] = fma2(wv1.y, m1, G2[r]);
            G1[r] = fma2(wv2.x, m2, G1[r]); G2[r] = fma2(wv2.y, m2, G2[r]);
            G1[r] = fma2(wv3.x, m3, G1[r]); G2[r] = fma2(wv3.y, m3, G2[r]);
        }
    }

    ull Y[8];
    #pragma unroll
    for (int r = 0; r < 8; r++) Y[r] = 0ull;
    #pragma unroll 4
    for (int e2 = 0; e2 < 16; e2++) {
        ull H0 = *(const ull*)&hos[(2*e2)*64 + 2*lane];
        ull H1 = *(const ull*)&hos[(2*e2+1)*64 + 2*lane];
        #pragma unroll
        for (int r = 0; r < 8; r++) {
            float2 a2 = *(const float2*)(asw + r*32 + 2*e2);
            Y[r] = fma2(H0, packdup(a2.x), Y[r]);
            Y[r] = fma2(H1, packdup(a2.y), Y[r]);
        }
    }

    float g1w = prm[2*64 + 2*lane], g1w2 = prm[2*64 + 2*lane + 1];
    float b1w = prm[3*64 + 2*lane], b1w2 = prm[3*64 + 2*lane + 1];
    float g2w = prm[4*64 + 2*lane], g2w2 = prm[4*64 + 2*lane + 1];
    float b2w = prm[5*64 + 2*lane], b2w2 = prm[5*64 + 2*lane + 1];

    #pragma unroll
    for (int r = 0; r < 8; r++) {
        int row = rowbase + r;
        if (row >= TN) break;   // warp-uniform
        float2 xv = *(const float2*)(xb + (size_t)row*DD + 2*lane);
        float g1a, g1b, g2a, g2b, y0, y1;
        unpack2(G1[r], g1a, g1b);
        unpack2(G2[r], g2a, g2b);
        unpack2(Y[r], y0, y1);
        float f0 = fmaxf(g1a*g2a, 0.f) + g1a + xv.x;
        float f1 = fmaxf(g1b*g2b, 0.f) + g1b + xv.y;
        float s = f0 + f1, s2 = f0*f0 + f1*f1;
        #pragma unroll
        for (int o = 16; o; o >>= 1) {
            s  += __shfl_xor_sync(0xffffffffu, s,  o);
            s2 += __shfl_xor_sync(0xffffffffu, s2, o);
        }
        float mu = s * (1.f/64.f);
        float var = s2 * (1.f/64.f) - mu*mu;
        float rs = rsqrtf(var + 1e-5f);
        float o1a = (f0 - mu)*rs*g1w + b1w;
        float o1b = (f1 - mu)*rs*g1w2 + b1w2;

        float h0 = fmaxf(y0, 0.f) + xv.x;
        float h1 = fmaxf(y1, 0.f) + xv.y;
        s = h0 + h1; s2 = h0*h0 + h1*h1;
        #pragma unroll
        for (int o = 16; o; o >>= 1) {
            s  += __shfl_xor_sync(0xffffffffu, s,  o);
            s2 += __shfl_xor_sync(0xffffffffu, s2, o);
        }
        mu = s * (1.f/64.f);
        var = s2 * (1.f/64.f) - mu*mu;
        rs = rsqrtf(var + 1e-5f);
        float o2a = (h0 - mu)*rs*g2w + b2w;
        float o2b = (h1 - mu)*rs*g2w2 + b2w2;

        *(float2*)(ob + (size_t)row*DD + 2*lane) =
            make_float2(0.5f*(o1a + o2a), 0.5f*(o1b + o2b));
    }
}

extern "C" void kernel_launch(void* const* d_in, const int* in_sizes, int n_in,
                              void* d_out, int out_size) {
    const float* x    = (const float*)d_in[0];
    const float* W1   = (const float*)d_in[1];
    const float* b1   = (const float*)d_in[2];
    const float* W2   = (const float*)d_in[3];
    const float* b2   = (const float*)d_in[4];
    const float* ln1g = (const float*)d_in[5];
    const float* ln1b = (const float*)d_in[6];
    const float* eclf = (const float*)d_in[7];
    const float* emap = (const float*)d_in[8];
    const float* ln2g = (const float*)d_in[9];
    const float* ln2b = (const float*)d_in[10];

    float *bufA, *bufB, *assign, *hfp, *ho;
    cudaGetSymbolAddress((void**)&bufA,   g_bufA);
    cudaGetSymbolAddress((void**)&bufB,   g_bufB);
    cudaGetSymbolAddress((void**)&assign, g_assign);
    cudaGetSymbolAddress((void**)&hfp,    g_hfp);
    cudaGetSymbolAddress((void**)&ho,     g_ho);

    cudaFuncSetAttribute(k_fused_out, cudaFuncAttributeMaxDynamicSharedMemorySize,
                         K3_SMEM_FLOATS * (int)sizeof(float));

    const float* cur = x;
    float* outs[3] = { bufA, bufB, (float*)d_out };

    for (int i = 0; i < 3; i++) {
        dim3 g1(BN, K1_BLOCKS_PER_B);
        k_assign_hf<<<g1, 256>>>(cur, eclf, assign, hfp);
        k_edge_mix<<<BN, 256>>>(hfp, emap, ho);
        dim3 g3(BN, K3_BLOCKS_PER_B);
        k_fused_out<<<g3, 256, K3_SMEM_FLOATS * sizeof(float)>>>(
            cur, W1 + i*DD*DD, b1 + i*DD, W2 + i*DD*DD, b2 + i*DD,
            ln1g + i*DD, ln1b + i*DD, ln2g, ln2b,
            assign, ho, outs[i]);
        cur = outs[i];
    }
}

// round 10
// speedup vs baseline: 1.7231x; 1.0223x over previous
#include <cuda_runtime.h>

#define BN 64
#define TT 12
#define NN 716
#define DD 64
#define EE 32
#define TN 8592            // TT*NN
#define XELEMS 35192832    // BN*TN*DD

typedef unsigned long long ull;

#define K1_STAGE 64
#define K1_STAGES 4
#define K1_CHUNK (K1_STAGE*K1_STAGES)                     // 256
#define K1_BLOCKS_PER_B ((TN + K1_CHUNK - 1)/K1_CHUNK)    // 34

__device__ float g_bufA[XELEMS];
__device__ float g_bufB[XELEMS];
__device__ float g_assign[(size_t)BN*TN*EE];
__device__ float g_hfp[(size_t)BN*K1_BLOCKS_PER_B*EE*DD];   // per-chunk partials
__device__ float g_ho[BN*EE*DD];

__device__ __forceinline__ ull fma2(ull a, ull b, ull c) {
    ull d;
    asm("fma.rn.f32x2 %0, %1, %2, %3;" : "=l"(d) : "l"(a), "l"(b), "l"(c));
    return d;
}
__device__ __forceinline__ ull packdup(float m) {
    ull d;
    asm("mov.b64 %0, {%1, %1};" : "=l"(d) : "f"(m));
    return d;
}
__device__ __forceinline__ ull pack2(float lo, float hi) {
    ull d;
    asm("mov.b64 %0, {%1, %2};" : "=l"(d) : "f"(lo), "f"(hi));
    return d;
}
__device__ __forceinline__ void unpack2(ull v, float& lo, float& hi) {
    asm("mov.b64 {%0, %1}, %2;" : "=f"(lo), "=f"(hi) : "l"(v));
}

// ============================ K1: assign + hf partials ============================
__global__ __launch_bounds__(256) void k_assign_hf(
    const float* __restrict__ x, const float* __restrict__ edge_clf,
    float* __restrict__ assign, float* __restrict__ hfp)
{
    __shared__ float ecp4[16*32*4];  // [k4][e][kk] = ec[4k4+kk][e]
    __shared__ float xs[64][64];
    __shared__ float as[64][32];
    int tid = threadIdx.x;
    int b = blockIdx.x;
    int r0base = blockIdx.y * K1_CHUNK;
    int lane = tid & 31, warp = tid >> 5;

    // rank-1 mapping: 4 groups x 64 threads; thread owns 4e x 8d, group -> 16 rows/stage
    int group = tid >> 6;
    int gtid  = tid & 63;
    int e0    = (gtid >> 3) * 4;
    int dbase = (gtid & 7) * 8;

    for (int i = tid; i < 64*32; i += 256) {
        int k = i >> 5, e = i & 31;
        ecp4[(k>>2)*128 + e*4 + (k&3)] = edge_clf[i];
    }

    ull acc[16];
    #pragma unroll
    for (int j = 0; j < 16; j++) acc[j] = 0ull;

    const float* xb = x + (size_t)b*TN*DD;

    for (int s = 0; s < K1_STAGES; s++) {
        int r0 = r0base + s*K1_STAGE;
        __syncthreads();
        #pragma unroll
        for (int p = 0; p < 4; p++) {
            int row = p*16 + (tid >> 4);
            int q = (tid & 15) * 4;
            int gr = r0 + row;
            float4 v = make_float4(0.f,0.f,0.f,0.f);
            if (gr < TN) v = *(const float4*)(xb + (size_t)gr*DD + q);
            *(float4*)(&xs[row][q]) = v;
        }
        __syncthreads();
        // ---- logits via fma2 over k4 chunks: warp -> rows warp*8..+7, lane = e ----
        {
            ull v2[8];
            #pragma unroll
            for (int j = 0; j < 8; j++) v2[j] = 0ull;
            #pragma unroll 4
            for (int k4 = 0; k4 < 16; k4++) {
                ulonglong2 ev = *(const ulonglong2*)&ecp4[k4*128 + lane*4];
                #pragma unroll
                for (int j = 0; j < 8; j++) {
                    ulonglong2 xv = *(const ulonglong2*)&xs[warp*8 + j][4*k4];
                    v2[j] = fma2(xv.x, ev.x, v2[j]);
                    v2[j] = fma2(xv.y, ev.y, v2[j]);
                }
            }
            // ---- softmax: interleaved chains, 4 rows at a time ----
            #pragma unroll
            for (int jg = 0; jg < 2; jg++) {
                float vv[4], mm[4], ee[4], ss[4];
                #pragma unroll
                for (int j = 0; j < 4; j++) {
                    float vlo, vhi;
                    unpack2(v2[jg*4 + j], vlo, vhi);
                    vv[j] = vlo + vhi;
                    mm[j] = vv[j];
                }
                #pragma unroll
                for (int o = 16; o; o >>= 1) {
                    #pragma unroll
                    for (int j = 0; j < 4; j++)
                        mm[j] = fmaxf(mm[j], __shfl_xor_sync(0xffffffffu, mm[j], o));
                }
                #pragma unroll
                for (int j = 0; j < 4; j++) { ee[j] = __expf(vv[j] - mm[j]); ss[j] = ee[j]; }
                #pragma unroll
                for (int o = 16; o; o >>= 1) {
                    #pragma unroll
                    for (int j = 0; j < 4; j++)
                        ss[j] += __shfl_xor_sync(0xffffffffu, ss[j], o);
                }
                #pragma unroll
                for (int j = 0; j < 4; j++) {
                    int r = warp*8 + jg*4 + j;
                    int gr = r0 + r;
                    float p = ee[j] / ss[j];
                    bool valid = (gr < TN);
                    as[r][lane] = valid ? p : 0.f;
                    if (valid) assign[((size_t)b*TN + gr)*EE + lane] = p;
                }
            }
        }
        __syncthreads();
        // ---- rank-1: group g -> stage rows [g*16, g*16+16), 4e x 8d per thread ----
        #pragma unroll 4
        for (int rl = 0; rl < 16; rl++) {
            int r = group*16 + rl;
            float4 a4 = *(const float4*)&as[r][e0];
            ull ad0 = packdup(a4.x), ad1 = packdup(a4.y);
            ull ad2 = packdup(a4.z), ad3 = packdup(a4.w);
            ulonglong2 xlo = *(const ulonglong2*)&xs[r][dbase];
            ulonglong2 xhi = *(const ulonglong2*)&xs[r][dbase+4];
            acc[0]  = fma2(ad0, xlo.x, acc[0]);  acc[1]  = fma2(ad0, xlo.y, acc[1]);
            acc[2]  = fma2(ad0, xhi.x, acc[2]);  acc[3]  = fma2(ad0, xhi.y, acc[3]);
            acc[4]  = fma2(ad1, xlo.x, acc[4]);  acc[5]  = fma2(ad1, xlo.y, acc[5]);
            acc[6]  = fma2(ad1, xhi.x, acc[6]);  acc[7]  = fma2(ad1, xhi.y, acc[7]);
            acc[8]  = fma2(ad2, xlo.x, acc[8]);  acc[9]  = fma2(ad2, xlo.y, acc[9]);
            acc[10] = fma2(ad2, xhi.x, acc[10]); acc[11] = fma2(ad2, xhi.y, acc[11]);
            acc[12] = fma2(ad3, xlo.x, acc[12]); acc[13] = fma2(ad3, xlo.y, acc[13]);
            acc[14] = fma2(ad3, xhi.x, acc[14]); acc[15] = fma2(ad3, xhi.y, acc[15]);
        }
    }

    // ---- combine the four row-groups (ecp4 and xs are dead now) and store ----
    __syncthreads();
    if (group != 0) {
        float* pr = (group == 1) ? &xs[0][0] : (group == 2) ? &xs[32][0] : &ecp4[0];
        #pragma unroll
        for (int ee = 0; ee < 4; ee++) {
            *(ulonglong2*)&pr[(e0+ee)*64 + dbase]     = make_ulonglong2(acc[ee*4+0], acc[ee*4+1]);
            *(ulonglong2*)&pr[(e0+ee)*64 + dbase + 4] = make_ulonglong2(acc[ee*4+2], acc[ee*4+3]);
        }
    }
    __syncthreads();
    if (group == 0) {
        float* hp = hfp + ((size_t)b*K1_BLOCKS_PER_B + blockIdx.y)*(EE*DD);
        #pragma unroll
        for (int ee = 0; ee < 4; ee++) {
            float4 o0, o1;
            float t0, t1;
            unpack2(acc[ee*4+0], t0, t1); o0.x = t0; o0.y = t1;
            unpack2(acc[ee*4+1], t0, t1); o0.z = t0; o0.w = t1;
            unpack2(acc[ee*4+2], t0, t1); o1.x = t0; o1.y = t1;
            unpack2(acc[ee*4+3], t0, t1); o1.z = t0; o1.w = t1;
            int off = (e0+ee)*64 + dbase;
            float4 p10 = *(const float4*)(&xs[0][0] + off);
            float4 p11 = *(const float4*)(&xs[0][0] + off + 4);
            float4 p20 = *(const float4*)(&xs[32][0] + off);
            float4 p21 = *(const float4*)(&xs[32][0] + off + 4);
            float4 p30 = *(const float4*)(&ecp4[0] + off);
            float4 p31 = *(const float4*)(&ecp4[0] + off + 4);
            o0.x += p10.x + p20.x + p30.x; o0.y += p10.y + p20.y + p30.y;
            o0.z += p10.z + p20.z + p30.z; o0.w += p10.w + p20.w + p30.w;
            o1.x += p11.x + p21.x + p31.x; o1.y += p11.y + p21.y + p31.y;
            o1.z += p11.z + p21.z + p31.z; o1.w += p11.w + p21.w + p31.w;
            *(float4*)(hp + off)     = o0;
            *(float4*)(hp + off + 4) = o1;
        }
    }
}

// ============================ K2: reduce partials + edge mix ============================
__global__ __launch_bounds__(256) void k_edge_mix(
    const float* __restrict__ hfp, const float* __restrict__ edge_map,
    float* __restrict__ ho)
{
    __shared__ float hfs[32][64];
    __shared__ float em[32][32];
    int tid = threadIdx.x;
    int b = blockIdx.x;
    float4 s0 = make_float4(0.f,0.f,0.f,0.f), s1 = make_float4(0.f,0.f,0.f,0.f);
    const float* pb = hfp + (size_t)b*K1_BLOCKS_PER_B*(EE*DD) + tid*8;
    #pragma unroll 2
    for (int c = 0; c < K1_BLOCKS_PER_B; c++) {
        float4 a0 = *(const float4*)(pb + (size_t)c*(EE*DD));
        float4 a1 = *(const float4*)(pb + (size_t)c*(EE*DD) + 4);
        s0.x += a0.x; s0.y += a0.y; s0.z += a0.z; s0.w += a0.w;
        s1.x += a1.x; s1.y += a1.y; s1.z += a1.z; s1.w += a1.w;
    }
    int e = tid >> 3, dbase = (tid & 7) * 8;
    *(float4*)&hfs[e][dbase]     = s0;
    *(float4*)&hfs[e][dbase + 4] = s1;
    for (int i = tid; i < 1024; i += 256) em[i>>5][i&31] = edge_map[i];
    __syncthreads();
    float o[8];
    #pragma unroll
    for (int j = 0; j < 8; j++) o[j] = 0.f;
    #pragma unroll
    for (int f = 0; f < 32; f++) {
        float w = em[e][f];
        #pragma unroll
        for (int j = 0; j < 8; j++) o[j] = fmaf(w, hfs[f][dbase + j], o[j]);
    }
    float* ob = ho + b*EE*DD + e*DD + dbase;
    #pragma unroll
    for (int j = 0; j < 8; j++) ob[j] = fmaxf(o[j], 0.f) + hfs[e][dbase + j];
}

// ============================ K3: fused output ============================
#define K3_ROWS 64
#define K3_BLOCKS_PER_B ((TN + K3_ROWS - 1)/K3_ROWS)   // 135
#define K3_SMEM_FLOATS (8192 + 2048 + 384 + 4096 + 2048)

__global__ __launch_bounds__(256, 3) void k_fused_out(
    const float* __restrict__ x,
    const float* __restrict__ W1, const float* __restrict__ b1,
    const float* __restrict__ W2, const float* __restrict__ b2,
    const float* __restrict__ ln1g, const float* __restrict__ ln1b,
    const float* __restrict__ ln2g, const float* __restrict__ ln2b,
    const float* __restrict__ assign, const float* __restrict__ ho,
    float* __restrict__ out)
{
    extern __shared__ float smem[];
    float* w4s = smem;              // [k][128]
    float* hos = w4s + 8192;        // [e][64]
    float* prm = hos + 2048;        // [6][64]
    float* xms = prm + 384;         // [warp][8][64]
    float* ass = xms + 4096;        // [warp][8][32]

    int tid = threadIdx.x;
    int b = blockIdx.x;
    int lane = tid & 31, warp = tid >> 5;

    for (int i = tid; i < 4096; i += 256) {
        int k = i >> 6, c = i & 63;
        int p = c >> 1, q = c & 1;
        w4s[k*128 + p*4 + q]     = W1[i];
        w4s[k*128 + p*4 + 2 + q] = W2[i];
    }
    for (int i = tid; i < 2048; i += 256) hos[i] = ho[b*EE*DD + i];
    if (tid < 64) {
        prm[0*64 + tid] = b1[tid];   prm[1*64 + tid] = b2[tid];
        prm[2*64 + tid] = ln1g[tid]; prm[3*64 + tid] = ln1b[tid];
        prm[4*64 + tid] = ln2g[tid]; prm[5*64 + tid] = ln2b[tid];
    }
    __syncthreads();

    int rowbase = blockIdx.y * K3_ROWS + warp * 8;
    const float* xb = x + (size_t)b*TN*DD;
    const float* ab = assign + (size_t)b*TN*EE;
    float* ob = out + (size_t)b*TN*DD;
    float* xmw = xms + warp*8*64;
    float* asw = ass + warp*8*32;

    #pragma unroll
    for (int r = 0; r < 8; r++) {
        int row = rowbase + r;
        float2 xv = make_float2(0.f, 0.f), xp = make_float2(0.f, 0.f);
        float a = 0.f;
        if (row < TN) {
            xv = *(const float2*)(xb + (size_t)row*DD + 2*lane);
            if (row >= NN) xp = *(const float2*)(xb + (size_t)(row - NN)*DD + 2*lane);
            a = ab[(size_t)row*EE + lane];
        }
        *(float2*)(xmw + r*64 + 2*lane) = make_float2(0.5f*(xv.x + xp.x), 0.5f*(xv.y + xp.y));
        asw[r*32 + lane] = a;
    }
    __syncwarp();

    ull B1p = pack2(prm[0*64 + 2*lane], prm[0*64 + 2*lane + 1]);
    ull B2p = pack2(prm[1*64 + 2*lane], prm[1*64 + 2*lane + 1]);
    ull G1[8], G2[8];
    #pragma unroll
    for (int r = 0; r < 8; r++) { G1[r] = B1p; G2[r] = B2p; }

    #pragma unroll 2
    for (int k4 = 0; k4 < 16; k4++) {
        ulonglong2 wv0 = *(const ulonglong2*)&w4s[(4*k4+0)*128 + lane*4];
        ulonglong2 wv1 = *(const ulonglong2*)&w4s[(4*k4+1)*128 + lane*4];
        ulonglong2 wv2 = *(const ulonglong2*)&w4s[(4*k4+2)*128 + lane*4];
        ulonglong2 wv3 = *(const ulonglong2*)&w4s[(4*k4+3)*128 + lane*4];
        #pragma unroll
        for (int r = 0; r < 8; r++) {
            float4 mv = *(const float4*)(xmw + r*64 + 4*k4);
            ull m0 = packdup(mv.x), m1 = packdup(mv.y);
            ull m2 = packdup(mv.z), m3 = packdup(mv.w);
            G1[r] = fma2(wv0.x, m0, G1[r]); G2[r] = fma2(wv0.y, m0, G2[r]);
            G1[r] = fma2(wv1.x, m1, G1[r]); G2[r] = fma2(wv1.y, m1, G2[r]);
            G1[r] = fma2(wv2.x, m2, G1[r]); G2[r] = fma2(wv2.y, m2, G2[r]);
            G1[r] = fma2(wv3.x, m3, G1[r]); G2[r] = fma2(wv3.y, m3, G2[r]);
        }
    }

    ull Y[8];
    #pragma unroll
    for (int r = 0; r < 8; r++) Y[r] = 0ull;
    #pragma unroll 4
    for (int e2 = 0; e2 < 16; e2++) {
        ull H0 = *(const ull*)&hos[(2*e2)*64 + 2*lane];
        ull H1 = *(const ull*)&hos[(2*e2+1)*64 + 2*lane];
        #pragma unroll
        for (int r = 0; r < 8; r++) {
            float2 a2 = *(const float2*)(asw + r*32 + 2*e2);
            Y[r] = fma2(H0, packdup(a2.x), Y[r]);
            Y[r] = fma2(H1, packdup(a2.y), Y[r]);
        }
    }

    float g1w = prm[2*64 + 2*lane], g1w2 = prm[2*64 + 2*lane + 1];
    float b1w = prm[3*64 + 2*lane], b1w2 = prm[3*64 + 2*lane + 1];
    float g2w = prm[4*64 + 2*lane], g2w2 = prm[4*64 + 2*lane + 1];
    float b2w = prm[5*64 + 2*lane], b2w2 = prm[5*64 + 2*lane + 1];

    // ---- epilogue: 2 rows at a time, 8 interleaved reduction chains ----
    #pragma unroll
    for (int rg = 0; rg < 4; rg++) {
        float f0[2], f1[2], h0[2], h1[2], s[2], s2[2], t[2], t2[2];
        #pragma unroll
        for (int j = 0; j < 2; j++) {
            int r = rg*2 + j;
            int row = rowbase + r;
            float2 xv = make_float2(0.f, 0.f);
            if (row < TN) xv = *(const float2*)(xb + (size_t)row*DD + 2*lane);
            float g1a, g1b, g2a, g2b, y0, y1;
            unpack2(G1[r], g1a, g1b);
            unpack2(G2[r], g2a, g2b);
            unpack2(Y[r], y0, y1);
            f0[j] = fmaxf(g1a*g2a, 0.f) + g1a + xv.x;
            f1[j] = fmaxf(g1b*g2b, 0.f) + g1b + xv.y;
            h0[j] = fmaxf(y0, 0.f) + xv.x;
            h1[j] = fmaxf(y1, 0.f) + xv.y;
            s[j]  = f0[j] + f1[j];   s2[j] = f0[j]*f0[j] + f1[j]*f1[j];
            t[j]  = h0[j] + h1[j];   t2[j] = h0[j]*h0[j] + h1[j]*h1[j];
        }
        #pragma unroll
        for (int o = 16; o; o >>= 1) {
            #pragma unroll
            for (int j = 0; j < 2; j++) {
                s[j]  += __shfl_xor_sync(0xffffffffu, s[j],  o);
                s2[j] += __shfl_xor_sync(0xffffffffu, s2[j], o);
                t[j]  += __shfl_xor_sync(0xffffffffu, t[j],  o);
                t2[j] += __shfl_xor_sync(0xffffffffu, t2[j], o);
            }
        }
        #pragma unroll
        for (int j = 0; j < 2; j++) {
            int row = rowbase + rg*2 + j;
            float mu = s[j] * (1.f/64.f);
            float var = s2[j] * (1.f/64.f) - mu*mu;
            float rs = rsqrtf(var + 1e-5f);
            float o1a = (f0[j] - mu)*rs*g1w + b1w;
            float o1b = (f1[j] - mu)*rs*g1w2 + b1w2;
            float mu2 = t[j] * (1.f/64.f);
            float var2 = t2[j] * (1.f/64.f) - mu2*mu2;
            float rs2 = rsqrtf(var2 + 1e-5f);
            float o2a = (h0[j] - mu2)*rs2*g2w + b2w;
            float o2b = (h1[j] - mu2)*rs2*g2w2 + b2w2;
            if (row < TN)
                *(float2*)(ob + (size_t)row*DD + 2*lane) =
                    make_float2(0.5f*(o1a + o2a), 0.5f*(o1b + o2b));
        }
    }
}

extern "C" void kernel_launch(void* const* d_in, const int* in_sizes, int n_in,
                              void* d_out, int out_size) {
    const float* x    = (const float*)d_in[0];
    const float* W1   = (const float*)d_in[1];
    const float* b1   = (const float*)d_in[2];
    const float* W2   = (const float*)d_in[3];
    const float* b2   = (const float*)d_in[4];
    const float* ln1g = (const float*)d_in[5];
    const float* ln1b = (const float*)d_in[6];
    const float* eclf = (const float*)d_in[7];
    const float* emap = (const float*)d_in[8];
    const float* ln2g = (const float*)d_in[9];
    const float* ln2b = (const float*)d_in[10];

    float *bufA, *bufB, *assign, *hfp, *ho;
    cudaGetSymbolAddress((void**)&bufA,   g_bufA);
    cudaGetSymbolAddress((void**)&bufB,   g_bufB);
    cudaGetSymbolAddress((void**)&assign, g_assign);
    cudaGetSymbolAddress((void**)&hfp,    g_hfp);
    cudaGetSymbolAddress((void**)&ho,     g_ho);

    cudaFuncSetAttribute(k_fused_out, cudaFuncAttributeMaxDynamicSharedMemorySize,
                         K3_SMEM_FLOATS * (int)sizeof(float));

    const float* cur = x;
    float* outs[3] = { bufA, bufB, (float*)d_out };

    for (int i = 0; i < 3; i++) {
        dim3 g1(BN, K1_BLOCKS_PER_B);
        k_assign_hf<<<g1, 256>>>(cur, eclf, assign, hfp);
        k_edge_mix<<<BN, 256>>>(hfp, emap, ho);
        dim3 g3(BN, K3_BLOCKS_PER_B);
        k_fused_out<<<g3, 256, K3_SMEM_FLOATS * sizeof(float)>>>(
            cur, W1 + i*DD*DD, b1 + i*DD, W2 + i*DD*DD, b2 + i*DD,
            ln1g + i*DD, ln1b + i*DD, ln2g, ln2b,
            assign, ho, outs[i]);
        cur = outs[i];
    }
}

// round 11
// speedup vs baseline: 1.7398x; 1.0096x over previous
#include <cuda_runtime.h>

#define BN 64
#define TT 12
#define NN 716
#define DD 64
#define EE 32
#define TN 8592            // TT*NN
#define XELEMS 35192832    // BN*TN*DD

typedef unsigned long long ull;

#define K1_STAGE 64
#define K1_STAGES 4
#define K1_CHUNK (K1_STAGE*K1_STAGES)                     // 256
#define K1_BLOCKS_PER_B ((TN + K1_CHUNK - 1)/K1_CHUNK)    // 34

__device__ float g_bufA[XELEMS];
__device__ float g_bufB[XELEMS];
__device__ float g_assign[(size_t)BN*TN*EE];
__device__ float g_hfp[(size_t)BN*K1_BLOCKS_PER_B*EE*DD];   // per-chunk partials
__device__ float g_ho[BN*EE*DD];

__device__ __forceinline__ ull fma2(ull a, ull b, ull c) {
    ull d;
    asm("fma.rn.f32x2 %0, %1, %2, %3;" : "=l"(d) : "l"(a), "l"(b), "l"(c));
    return d;
}
__device__ __forceinline__ ull packdup(float m) {
    ull d;
    asm("mov.b64 %0, {%1, %1};" : "=l"(d) : "f"(m));
    return d;
}
__device__ __forceinline__ ull pack2(float lo, float hi) {
    ull d;
    asm("mov.b64 %0, {%1, %2};" : "=l"(d) : "f"(lo), "f"(hi));
    return d;
}
__device__ __forceinline__ void unpack2(ull v, float& lo, float& hi) {
    asm("mov.b64 {%0, %1}, %2;" : "=f"(lo), "=f"(hi) : "l"(v));
}

// ============================ K1: assign + hf partials ============================
__global__ __launch_bounds__(256) void k_assign_hf(
    const float* __restrict__ x, const float* __restrict__ edge_clf,
    float* __restrict__ assign, float* __restrict__ hfp)
{
    __shared__ float ecp4[16*32*4];  // [k4][e][kk] = ec[4k4+kk][e]
    __shared__ float xs[64][64];
    __shared__ float as[64][32];
    int tid = threadIdx.x;
    int b = blockIdx.x;
    int r0base = blockIdx.y * K1_CHUNK;
    int lane = tid & 31, warp = tid >> 5;

    // rank-1 mapping: 4 groups x 64 threads; thread owns 4e x 8d, group -> 16 rows/stage
    int group = tid >> 6;
    int gtid  = tid & 63;
    int e0    = (gtid >> 3) * 4;
    int dbase = (gtid & 7) * 8;

    for (int i = tid; i < 64*32; i += 256) {
        int k = i >> 5, e = i & 31;
        ecp4[(k>>2)*128 + e*4 + (k&3)] = edge_clf[i];
    }

    ull acc[16];
    #pragma unroll
    for (int j = 0; j < 16; j++) acc[j] = 0ull;

    const float* xb = x + (size_t)b*TN*DD;

    for (int s = 0; s < K1_STAGES; s++) {
        int r0 = r0base + s*K1_STAGE;
        __syncthreads();
        #pragma unroll
        for (int p = 0; p < 4; p++) {
            int row = p*16 + (tid >> 4);
            int q = (tid & 15) * 4;
            int gr = r0 + row;
            float4 v = make_float4(0.f,0.f,0.f,0.f);
            if (gr < TN) v = *(const float4*)(xb + (size_t)gr*DD + q);
            *(float4*)(&xs[row][q]) = v;
        }
        __syncthreads();
        // ---- logits via fma2 over k4 chunks: warp -> rows warp*8..+7, lane = e ----
        {
            ull v2[8];
            #pragma unroll
            for (int j = 0; j < 8; j++) v2[j] = 0ull;
            #pragma unroll 4
            for (int k4 = 0; k4 < 16; k4++) {
                ulonglong2 ev = *(const ulonglong2*)&ecp4[k4*128 + lane*4];
                #pragma unroll
                for (int j = 0; j < 8; j++) {
                    ulonglong2 xv = *(const ulonglong2*)&xs[warp*8 + j][4*k4];
                    v2[j] = fma2(xv.x, ev.x, v2[j]);
                    v2[j] = fma2(xv.y, ev.y, v2[j]);
                }
            }
            // ---- softmax: interleaved chains, 4 rows at a time ----
            #pragma unroll
            for (int jg = 0; jg < 2; jg++) {
                float vv[4], mm[4], ee[4], ss[4];
                #pragma unroll
                for (int j = 0; j < 4; j++) {
                    float vlo, vhi;
                    unpack2(v2[jg*4 + j], vlo, vhi);
                    vv[j] = vlo + vhi;
                    mm[j] = vv[j];
                }
                #pragma unroll
                for (int o = 16; o; o >>= 1) {
                    #pragma unroll
                    for (int j = 0; j < 4; j++)
                        mm[j] = fmaxf(mm[j], __shfl_xor_sync(0xffffffffu, mm[j], o));
                }
                #pragma unroll
                for (int j = 0; j < 4; j++) { ee[j] = __expf(vv[j] - mm[j]); ss[j] = ee[j]; }
                #pragma unroll
                for (int o = 16; o; o >>= 1) {
                    #pragma unroll
                    for (int j = 0; j < 4; j++)
                        ss[j] += __shfl_xor_sync(0xffffffffu, ss[j], o);
                }
                #pragma unroll
                for (int j = 0; j < 4; j++) {
                    int r = warp*8 + jg*4 + j;
                    int gr = r0 + r;
                    float p = ee[j] / ss[j];
                    bool valid = (gr < TN);
                    as[r][lane] = valid ? p : 0.f;
                    if (valid) assign[((size_t)b*TN + gr)*EE + lane] = p;
                }
            }
        }
        __syncthreads();
        // ---- rank-1: group g -> stage rows [g*16, g*16+16), 4e x 8d per thread ----
        #pragma unroll 4
        for (int rl = 0; rl < 16; rl++) {
            int r = group*16 + rl;
            float4 a4 = *(const float4*)&as[r][e0];
            ull ad0 = packdup(a4.x), ad1 = packdup(a4.y);
            ull ad2 = packdup(a4.z), ad3 = packdup(a4.w);
            ulonglong2 xlo = *(const ulonglong2*)&xs[r][dbase];
            ulonglong2 xhi = *(const ulonglong2*)&xs[r][dbase+4];
            acc[0]  = fma2(ad0, xlo.x, acc[0]);  acc[1]  = fma2(ad0, xlo.y, acc[1]);
            acc[2]  = fma2(ad0, xhi.x, acc[2]);  acc[3]  = fma2(ad0, xhi.y, acc[3]);
            acc[4]  = fma2(ad1, xlo.x, acc[4]);  acc[5]  = fma2(ad1, xlo.y, acc[5]);
            acc[6]  = fma2(ad1, xhi.x, acc[6]);  acc[7]  = fma2(ad1, xhi.y, acc[7]);
            acc[8]  = fma2(ad2, xlo.x, acc[8]);  acc[9]  = fma2(ad2, xlo.y, acc[9]);
            acc[10] = fma2(ad2, xhi.x, acc[10]); acc[11] = fma2(ad2, xhi.y, acc[11]);
            acc[12] = fma2(ad3, xlo.x, acc[12]); acc[13] = fma2(ad3, xlo.y, acc[13]);
            acc[14] = fma2(ad3, xhi.x, acc[14]); acc[15] = fma2(ad3, xhi.y, acc[15]);
        }
    }

    // ---- combine the four row-groups (ecp4 and xs are dead now) and store ----
    __syncthreads();
    if (group != 0) {
        float* pr = (group == 1) ? &xs[0][0] : (group == 2) ? &xs[32][0] : &ecp4[0];
        #pragma unroll
        for (int ee = 0; ee < 4; ee++) {
            *(ulonglong2*)&pr[(e0+ee)*64 + dbase]     = make_ulonglong2(acc[ee*4+0], acc[ee*4+1]);
            *(ulonglong2*)&pr[(e0+ee)*64 + dbase + 4] = make_ulonglong2(acc[ee*4+2], acc[ee*4+3]);
        }
    }
    __syncthreads();
    if (group == 0) {
        float* hp = hfp + ((size_t)b*K1_BLOCKS_PER_B + blockIdx.y)*(EE*DD);
        #pragma unroll
        for (int ee = 0; ee < 4; ee++) {
            float4 o0, o1;
            float t0, t1;
            unpack2(acc[ee*4+0], t0, t1); o0.x = t0; o0.y = t1;
            unpack2(acc[ee*4+1], t0, t1); o0.z = t0; o0.w = t1;
            unpack2(acc[ee*4+2], t0, t1); o1.x = t0; o1.y = t1;
            unpack2(acc[ee*4+3], t0, t1); o1.z = t0; o1.w = t1;
            int off = (e0+ee)*64 + dbase;
            float4 p10 = *(const float4*)(&xs[0][0] + off);
            float4 p11 = *(const float4*)(&xs[0][0] + off + 4);
            float4 p20 = *(const float4*)(&xs[32][0] + off);
            float4 p21 = *(const float4*)(&xs[32][0] + off + 4);
            float4 p30 = *(const float4*)(&ecp4[0] + off);
            float4 p31 = *(const float4*)(&ecp4[0] + off + 4);
            o0.x += p10.x + p20.x + p30.x; o0.y += p10.y + p20.y + p30.y;
            o0.z += p10.z + p20.z + p30.z; o0.w += p10.w + p20.w + p30.w;
            o1.x += p11.x + p21.x + p31.x; o1.y += p11.y + p21.y + p31.y;
            o1.z += p11.z + p21.z + p31.z; o1.w += p11.w + p21.w + p31.w;
            *(float4*)(hp + off)     = o0;
            *(float4*)(hp + off + 4) = o1;
        }
    }
}

// ============================ K2: reduce partials + edge mix ============================
__global__ __launch_bounds__(256) void k_edge_mix(
    const float* __restrict__ hfp, const float* __restrict__ edge_map,
    float* __restrict__ ho)
{
    __shared__ float hfs[32][64];
    __shared__ float em[32][32];
    int tid = threadIdx.x;
    int b = blockIdx.x;
    float4 s0 = make_float4(0.f,0.f,0.f,0.f), s1 = make_float4(0.f,0.f,0.f,0.f);
    const float* pb = hfp + (size_t)b*K1_BLOCKS_PER_B*(EE*DD) + tid*8;
    #pragma unroll 2
    for (int c = 0; c < K1_BLOCKS_PER_B; c++) {
        float4 a0 = *(const float4*)(pb + (size_t)c*(EE*DD));
        float4 a1 = *(const float4*)(pb + (size_t)c*(EE*DD) + 4);
        s0.x += a0.x; s0.y += a0.y; s0.z += a0.z; s0.w += a0.w;
        s1.x += a1.x; s1.y += a1.y; s1.z += a1.z; s1.w += a1.w;
    }
    int e = tid >> 3, dbase = (tid & 7) * 8;
    *(float4*)&hfs[e][dbase]     = s0;
    *(float4*)&hfs[e][dbase + 4] = s1;
    for (int i = tid; i < 1024; i += 256) em[i>>5][i&31] = edge_map[i];
    __syncthreads();
    float o[8];
    #pragma unroll
    for (int j = 0; j < 8; j++) o[j] = 0.f;
    #pragma unroll
    for (int f = 0; f < 32; f++) {
        float w = em[e][f];
        #pragma unroll
        for (int j = 0; j < 8; j++) o[j] = fmaf(w, hfs[f][dbase + j], o[j]);
    }
    float* ob = ho + b*EE*DD + e*DD + dbase;
    #pragma unroll
    for (int j = 0; j < 8; j++) ob[j] = fmaxf(o[j], 0.f) + hfs[e][dbase + j];
}

// ============================ K3: fused output (128 rows/block, 2 sub-tiles) ============================
#define K3_ROWS 128
#define K3_BLOCKS_PER_B ((TN + K3_ROWS - 1)/K3_ROWS)   // 68
#define K3_SMEM_FLOATS (8192 + 2048 + 384 + 4096 + 2048)

__global__ __launch_bounds__(256, 3) void k_fused_out(
    const float* __restrict__ x,
    const float* __restrict__ W1, const float* __restrict__ b1,
    const float* __restrict__ W2, const float* __restrict__ b2,
    const float* __restrict__ ln1g, const float* __restrict__ ln1b,
    const float* __restrict__ ln2g, const float* __restrict__ ln2b,
    const float* __restrict__ assign, const float* __restrict__ ho,
    float* __restrict__ out)
{
    extern __shared__ float smem[];
    float* w4s = smem;              // [k][128]
    float* hos = w4s + 8192;        // [e][64]
    float* prm = hos + 2048;        // [6][64]
    float* xms = prm + 384;         // [warp][8][64]
    float* ass = xms + 4096;        // [warp][8][32]

    int tid = threadIdx.x;
    int b = blockIdx.x;
    int lane = tid & 31, warp = tid >> 5;

    for (int i = tid; i < 4096; i += 256) {
        int k = i >> 6, c = i & 63;
        int p = c >> 1, q = c & 1;
        w4s[k*128 + p*4 + q]     = W1[i];
        w4s[k*128 + p*4 + 2 + q] = W2[i];
    }
    for (int i = tid; i < 2048; i += 256) hos[i] = ho[b*EE*DD + i];
    if (tid < 64) {
        prm[0*64 + tid] = b1[tid];   prm[1*64 + tid] = b2[tid];
        prm[2*64 + tid] = ln1g[tid]; prm[3*64 + tid] = ln1b[tid];
        prm[4*64 + tid] = ln2g[tid]; prm[5*64 + tid] = ln2b[tid];
    }
    __syncthreads();

    const float* xb = x + (size_t)b*TN*DD;
    const float* ab = assign + (size_t)b*TN*EE;
    float* ob = out + (size_t)b*TN*DD;
    float* xmw = xms + warp*8*64;
    float* asw = ass + warp*8*32;

    ull B1p = pack2(prm[0*64 + 2*lane], prm[0*64 + 2*lane + 1]);
    ull B2p = pack2(prm[1*64 + 2*lane], prm[1*64 + 2*lane + 1]);
    float g1w = prm[2*64 + 2*lane], g1w2 = prm[2*64 + 2*lane + 1];
    float b1w = prm[3*64 + 2*lane], b1w2 = prm[3*64 + 2*lane + 1];
    float g2w = prm[4*64 + 2*lane], g2w2 = prm[4*64 + 2*lane + 1];
    float b2w = prm[5*64 + 2*lane], b2w2 = prm[5*64 + 2*lane + 1];

    for (int half = 0; half < 2; half++) {
        int rowbase = blockIdx.y * K3_ROWS + half * 64 + warp * 8;

        __syncwarp();
        #pragma unroll
        for (int r = 0; r < 8; r++) {
            int row = rowbase + r;
            float2 xv = make_float2(0.f, 0.f), xp = make_float2(0.f, 0.f);
            float a = 0.f;
            if (row < TN) {
                xv = *(const float2*)(xb + (size_t)row*DD + 2*lane);
                if (row >= NN) xp = *(const float2*)(xb + (size_t)(row - NN)*DD + 2*lane);
                a = ab[(size_t)row*EE + lane];
            }
            *(float2*)(xmw + r*64 + 2*lane) = make_float2(0.5f*(xv.x + xp.x), 0.5f*(xv.y + xp.y));
            asw[r*32 + lane] = a;
        }
        __syncwarp();

        ull G1[8], G2[8];
        #pragma unroll
        for (int r = 0; r < 8; r++) { G1[r] = B1p; G2[r] = B2p; }

        #pragma unroll 2
        for (int k4 = 0; k4 < 16; k4++) {
            ulonglong2 wv0 = *(const ulonglong2*)&w4s[(4*k4+0)*128 + lane*4];
            ulonglong2 wv1 = *(const ulonglong2*)&w4s[(4*k4+1)*128 + lane*4];
            ulonglong2 wv2 = *(const ulonglong2*)&w4s[(4*k4+2)*128 + lane*4];
            ulonglong2 wv3 = *(const ulonglong2*)&w4s[(4*k4+3)*128 + lane*4];
            #pragma unroll
            for (int r = 0; r < 8; r++) {
                float4 mv = *(const float4*)(xmw + r*64 + 4*k4);
                ull m0 = packdup(mv.x), m1 = packdup(mv.y);
                ull m2 = packdup(mv.z), m3 = packdup(mv.w);
                G1[r] = fma2(wv0.x, m0, G1[r]); G2[r] = fma2(wv0.y, m0, G2[r]);
                G1[r] = fma2(wv1.x, m1, G1[r]); G2[r] = fma2(wv1.y, m1, G2[r]);
                G1[r] = fma2(wv2.x, m2, G1[r]); G2[r] = fma2(wv2.y, m2, G2[r]);
                G1[r] = fma2(wv3.x, m3, G1[r]); G2[r] = fma2(wv3.y, m3, G2[r]);
            }
        }

        ull Y[8];
        #pragma unroll
        for (int r = 0; r < 8; r++) Y[r] = 0ull;
        #pragma unroll 4
        for (int e2 = 0; e2 < 16; e2++) {
            ull H0 = *(const ull*)&hos[(2*e2)*64 + 2*lane];
            ull H1 = *(const ull*)&hos[(2*e2+1)*64 + 2*lane];
            #pragma unroll
            for (int r = 0; r < 8; r++) {
                float2 a2 = *(const float2*)(asw + r*32 + 2*e2);
                Y[r] = fma2(H0, packdup(a2.x), Y[r]);
                Y[r] = fma2(H1, packdup(a2.y), Y[r]);
            }
        }

        // ---- epilogue: 2 rows at a time, 8 interleaved reduction chains ----
        #pragma unroll
        for (int rg = 0; rg < 4; rg++) {
            float f0[2], f1[2], h0[2], h1[2], s[2], s2[2], t[2], t2[2];
            #pragma unroll
            for (int j = 0; j < 2; j++) {
                int r = rg*2 + j;
                int row = rowbase + r;
                float2 xv = make_float2(0.f, 0.f);
                if (row < TN) xv = *(const float2*)(xb + (size_t)row*DD + 2*lane);
                float g1a, g1b, g2a, g2b, y0, y1;
                unpack2(G1[r], g1a, g1b);
                unpack2(G2[r], g2a, g2b);
                unpack2(Y[r], y0, y1);
                f0[j] = fmaxf(g1a*g2a, 0.f) + g1a + xv.x;
                f1[j] = fmaxf(g1b*g2b, 0.f) + g1b + xv.y;
                h0[j] = fmaxf(y0, 0.f) + xv.x;
                h1[j] = fmaxf(y1, 0.f) + xv.y;
                s[j]  = f0[j] + f1[j];   s2[j] = f0[j]*f0[j] + f1[j]*f1[j];
                t[j]  = h0[j] + h1[j];   t2[j] = h0[j]*h0[j] + h1[j]*h1[j];
            }
            #pragma unroll
            for (int o = 16; o; o >>= 1) {
                #pragma unroll
                for (int j = 0; j < 2; j++) {
                    s[j]  += __shfl_xor_sync(0xffffffffu, s[j],  o);
                    s2[j] += __shfl_xor_sync(0xffffffffu, s2[j], o);
                    t[j]  += __shfl_xor_sync(0xffffffffu, t[j],  o);
                    t2[j] += __shfl_xor_sync(0xffffffffu, t2[j], o);
                }
            }
            #pragma unroll
            for (int j = 0; j < 2; j++) {
                int row = rowbase + rg*2 + j;
                float mu = s[j] * (1.f/64.f);
                float var = s2[j] * (1.f/64.f) - mu*mu;
                float rs = rsqrtf(var + 1e-5f);
                float o1a = (f0[j] - mu)*rs*g1w + b1w;
                float o1b = (f1[j] - mu)*rs*g1w2 + b1w2;
                float mu2 = t[j] * (1.f/64.f);
                float var2 = t2[j] * (1.f/64.f) - mu2*mu2;
                float rs2 = rsqrtf(var2 + 1e-5f);
                float o2a = (h0[j] - mu2)*rs2*g2w + b2w;
                float o2b = (h1[j] - mu2)*rs2*g2w2 + b2w2;
                if (row < TN)
                    *(float2*)(ob + (size_t)row*DD + 2*lane) =
                        make_float2(0.5f*(o1a + o2a), 0.5f*(o1b + o2b));
            }
        }
    }
}

extern "C" void kernel_launch(void* const* d_in, const int* in_sizes, int n_in,
                              void* d_out, int out_size) {
    const float* x    = (const float*)d_in[0];
    const float* W1   = (const float*)d_in[1];
    const float* b1   = (const float*)d_in[2];
    const float* W2   = (const float*)d_in[3];
    const float* b2   = (const float*)d_in[4];
    const float* ln1g = (const float*)d_in[5];
    const float* ln1b = (const float*)d_in[6];
    const float* eclf = (const float*)d_in[7];
    const float* emap = (const float*)d_in[8];
    const float* ln2g = (const float*)d_in[9];
    const float* ln2b = (const float*)d_in[10];

    float *bufA, *bufB, *assign, *hfp, *ho;
    cudaGetSymbolAddress((void**)&bufA,   g_bufA);
    cudaGetSymbolAddress((void**)&bufB,   g_bufB);
    cudaGetSymbolAddress((void**)&assign, g_assign);
    cudaGetSymbolAddress((void**)&hfp,    g_hfp);
    cudaGetSymbolAddress((void**)&ho,     g_ho);

    cudaFuncSetAttribute(k_fused_out, cudaFuncAttributeMaxDynamicSharedMemorySize,
                         K3_SMEM_FLOATS * (int)sizeof(float));

    const float* cur = x;
    float* outs[3] = { bufA, bufB, (float*)d_out };

    for (int i = 0; i < 3; i++) {
        dim3 g1(BN, K1_BLOCKS_PER_B);
        k_assign_hf<<<g1, 256>>>(cur, eclf, assign, hfp);
        k_edge_mix<<<BN, 256>>>(hfp, emap, ho);
        dim3 g3(BN, K3_BLOCKS_PER_B);
        k_fused_out<<<g3, 256, K3_SMEM_FLOATS * sizeof(float)>>>(
            cur, W1 + i*DD*DD, b1 + i*DD, W2 + i*DD*DD, b2 + i*DD,
            ln1g + i*DD, ln1b + i*DD, ln2g, ln2b,
            assign, ho, outs[i]);
        cur = outs[i];
    }
}

// round 13
// speedup vs baseline: 1.7731x; 1.0192x over previous
#include <cuda_runtime.h>
#include <cuda_bf16.h>
#include <cstdint>

#define BN 64
#define TT 12
#define NN 716
#define DD 64
#define EE 32
#define TN 8592            // TT*NN
#define XELEMS 35192832    // BN*TN*DD

typedef unsigned long long ull;

#define K1_STAGE 64
#define K1_STAGES 4
#define K1_CHUNK (K1_STAGE*K1_STAGES)                     // 256
#define K1_BLOCKS_PER_B ((TN + K1_CHUNK - 1)/K1_CHUNK)    // 34

__device__ float g_bufA[XELEMS];
__device__ float g_bufB[XELEMS];
__device__ float g_assign[(size_t)BN*TN*EE];
__device__ float g_hfp[(size_t)BN*K1_BLOCKS_PER_B*EE*DD];
__device__ float g_ho[BN*EE*DD];
// B fragments: [layer][split(2)][ktile(4)][ntile(16)][lane(32)][reg(2)] u32
__device__ uint32_t g_wbf[3*2*4*16*32*2];

__device__ __forceinline__ ull fma2(ull a, ull b, ull c) {
    ull d;
    asm("fma.rn.f32x2 %0, %1, %2, %3;" : "=l"(d) : "l"(a), "l"(b), "l"(c));
    return d;
}
__device__ __forceinline__ ull packdup(float m) {
    ull d;
    asm("mov.b64 %0, {%1, %1};" : "=l"(d) : "f"(m));
    return d;
}
__device__ __forceinline__ ull pack2(float lo, float hi) {
    ull d;
    asm("mov.b64 %0, {%1, %2};" : "=l"(d) : "f"(lo), "f"(hi));
    return d;
}
__device__ __forceinline__ void unpack2(ull v, float& lo, float& hi) {
    asm("mov.b64 {%0, %1}, %2;" : "=f"(lo), "=f"(hi) : "l"(v));
}
__device__ __forceinline__ void mma_bf16(float* d, uint32_t a0, uint32_t a1, uint32_t a2, uint32_t a3,
                                         uint32_t b0, uint32_t b1) {
    asm volatile("mma.sync.aligned.m16n8k16.row.col.f32.bf16.bf16.f32 "
        "{%0,%1,%2,%3}, {%4,%5,%6,%7}, {%8,%9}, {%0,%1,%2,%3};"
        : "+f"(d[0]), "+f"(d[1]), "+f"(d[2]), "+f"(d[3])
        : "r"(a0), "r"(a1), "r"(a2), "r"(a3), "r"(b0), "r"(b1));
}
__device__ __forceinline__ uint32_t pack_bf2(float a, float b) {
    __nv_bfloat162 t;
    t.x = __float2bfloat16_rn(a);
    t.y = __float2bfloat16_rn(b);
    return *(uint32_t*)&t;
}

// ============================ prep: W -> B fragments (hi/lo bf16) ============================
__global__ __launch_bounds__(256) void k_prep_w(const float* __restrict__ W1,
                                                const float* __restrict__ W2,
                                                uint32_t* __restrict__ wbf) {
    int layer = blockIdx.x;
    const float* w1 = W1 + layer*DD*DD;
    const float* w2 = W2 + layer*DD*DD;
    uint32_t* out = wbf + (size_t)layer*8192;
    for (int i = threadIdx.x; i < 4096; i += 256) {
        int lane  = i & 31;
        int ntile = (i >> 5) & 15;
        int ktile = (i >> 9) & 3;
        int split = i >> 11;
        int k0 = ktile*16 + (lane & 3)*2;
        int n  = ntile*8 + (lane >> 2);
        float v[4];
        #pragma unroll
        for (int q = 0; q < 4; q++) {
            int k = k0 + (q >> 1)*8 + (q & 1);
            v[q] = (n < 64) ? w1[k*64 + n] : w2[k*64 + (n - 64)];
        }
        uint32_t r0, r1;
        if (split == 0) {
            r0 = pack_bf2(v[0], v[1]);
            r1 = pack_bf2(v[2], v[3]);
        } else {
            float l[4];
            #pragma unroll
            for (int q = 0; q < 4; q++)
                l[q] = v[q] - __bfloat162float(__float2bfloat16_rn(v[q]));
            r0 = pack_bf2(l[0], l[1]);
            r1 = pack_bf2(l[2], l[3]);
        }
        out[i*2 + 0] = r0;
        out[i*2 + 1] = r1;
    }
}

// ============================ K1: assign + hf partials (R11, verified) ============================
__global__ __launch_bounds__(256) void k_assign_hf(
    const float* __restrict__ x, const float* __restrict__ edge_clf,
    float* __restrict__ assign, float* __restrict__ hfp)
{
    __shared__ float ecp4[16*32*4];
    __shared__ float xs[64][64];
    __shared__ float as[64][32];
    int tid = threadIdx.x;
    int b = blockIdx.x;
    int r0base = blockIdx.y * K1_CHUNK;
    int lane = tid & 31, warp = tid >> 5;
    int group = tid >> 6;
    int gtid  = tid & 63;
    int e0    = (gtid >> 3) * 4;
    int dbase = (gtid & 7) * 8;

    for (int i = tid; i < 64*32; i += 256) {
        int k = i >> 5, e = i & 31;
        ecp4[(k>>2)*128 + e*4 + (k&3)] = edge_clf[i];
    }
    ull acc[16];
    #pragma unroll
    for (int j = 0; j < 16; j++) acc[j] = 0ull;
    const float* xb = x + (size_t)b*TN*DD;

    for (int s = 0; s < K1_STAGES; s++) {
        int r0 = r0base + s*K1_STAGE;
        __syncthreads();
        #pragma unroll
        for (int p = 0; p < 4; p++) {
            int row = p*16 + (tid >> 4);
            int q = (tid & 15) * 4;
            int gr = r0 + row;
            float4 v = make_float4(0.f,0.f,0.f,0.f);
            if (gr < TN) v = *(const float4*)(xb + (size_t)gr*DD + q);
            *(float4*)(&xs[row][q]) = v;
        }
        __syncthreads();
        {
            ull v2[8];
            #pragma unroll
            for (int j = 0; j < 8; j++) v2[j] = 0ull;
            #pragma unroll 4
            for (int k4 = 0; k4 < 16; k4++) {
                ulonglong2 ev = *(const ulonglong2*)&ecp4[k4*128 + lane*4];
                #pragma unroll
                for (int j = 0; j < 8; j++) {
                    ulonglong2 xv = *(const ulonglong2*)&xs[warp*8 + j][4*k4];
                    v2[j] = fma2(xv.x, ev.x, v2[j]);
                    v2[j] = fma2(xv.y, ev.y, v2[j]);
                }
            }
            #pragma unroll
            for (int jg = 0; jg < 2; jg++) {
                float vv[4], mm[4], ee[4], ss[4];
                #pragma unroll
                for (int j = 0; j < 4; j++) {
                    float vlo, vhi;
                    unpack2(v2[jg*4 + j], vlo, vhi);
                    vv[j] = vlo + vhi;
                    mm[j] = vv[j];
                }
                #pragma unroll
                for (int o = 16; o; o >>= 1) {
                    #pragma unroll
                    for (int j = 0; j < 4; j++)
                        mm[j] = fmaxf(mm[j], __shfl_xor_sync(0xffffffffu, mm[j], o));
                }
                #pragma unroll
                for (int j = 0; j < 4; j++) { ee[j] = __expf(vv[j] - mm[j]); ss[j] = ee[j]; }
                #pragma unroll
                for (int o = 16; o; o >>= 1) {
                    #pragma unroll
                    for (int j = 0; j < 4; j++)
                        ss[j] += __shfl_xor_sync(0xffffffffu, ss[j], o);
                }
                #pragma unroll
                for (int j = 0; j < 4; j++) {
                    int r = warp*8 + jg*4 + j;
                    int gr = r0 + r;
                    float p = ee[j] / ss[j];
                    bool valid = (gr < TN);
                    as[r][lane] = valid ? p : 0.f;
                    if (valid) assign[((size_t)b*TN + gr)*EE + lane] = p;
                }
            }
        }
        __syncthreads();
        #pragma unroll 4
        for (int rl = 0; rl < 16; rl++) {
            int r = group*16 + rl;
            float4 a4 = *(const float4*)&as[r][e0];
            ull ad0 = packdup(a4.x), ad1 = packdup(a4.y);
            ull ad2 = packdup(a4.z), ad3 = packdup(a4.w);
            ulonglong2 xlo = *(const ulonglong2*)&xs[r][dbase];
            ulonglong2 xhi = *(const ulonglong2*)&xs[r][dbase+4];
            acc[0]  = fma2(ad0, xlo.x, acc[0]);  acc[1]  = fma2(ad0, xlo.y, acc[1]);
            acc[2]  = fma2(ad0, xhi.x, acc[2]);  acc[3]  = fma2(ad0, xhi.y, acc[3]);
            acc[4]  = fma2(ad1, xlo.x, acc[4]);  acc[5]  = fma2(ad1, xlo.y, acc[5]);
            acc[6]  = fma2(ad1, xhi.x, acc[6]);  acc[7]  = fma2(ad1, xhi.y, acc[7]);
            acc[8]  = fma2(ad2, xlo.x, acc[8]);  acc[9]  = fma2(ad2, xlo.y, acc[9]);
            acc[10] = fma2(ad2, xhi.x, acc[10]); acc[11] = fma2(ad2, xhi.y, acc[11]);
            acc[12] = fma2(ad3, xlo.x, acc[12]); acc[13] = fma2(ad3, xlo.y, acc[13]);
            acc[14] = fma2(ad3, xhi.x, acc[14]); acc[15] = fma2(ad3, xhi.y, acc[15]);
        }
    }

    __syncthreads();
    if (group != 0) {
        float* pr = (group == 1) ? &xs[0][0] : (group == 2) ? &xs[32][0] : &ecp4[0];
        #pragma unroll
        for (int ee = 0; ee < 4; ee++) {
            *(ulonglong2*)&pr[(e0+ee)*64 + dbase]     = make_ulonglong2(acc[ee*4+0], acc[ee*4+1]);
            *(ulonglong2*)&pr[(e0+ee)*64 + dbase + 4] = make_ulonglong2(acc[ee*4+2], acc[ee*4+3]);
        }
    }
    __syncthreads();
    if (group == 0) {
        float* hp = hfp + ((size_t)b*K1_BLOCKS_PER_B + blockIdx.y)*(EE*DD);
        #pragma unroll
        for (int ee = 0; ee < 4; ee++) {
            float4 o0, o1;
            float t0, t1;
            unpack2(acc[ee*4+0], t0, t1); o0.x = t0; o0.y = t1;
            unpack2(acc[ee*4+1], t0, t1); o0.z = t0; o0.w = t1;
            unpack2(acc[ee*4+2], t0, t1); o1.x = t0; o1.y = t1;
            unpack2(acc[ee*4+3], t0, t1); o1.z = t0; o1.w = t1;
            int off = (e0+ee)*64 + dbase;
            float4 p10 = *(const float4*)(&xs[0][0] + off);
            float4 p11 = *(const float4*)(&xs[0][0] + off + 4);
            float4 p20 = *(const float4*)(&xs[32][0] + off);
            float4 p21 = *(const float4*)(&xs[32][0] + off + 4);
            float4 p30 = *(const float4*)(&ecp4[0] + off);
            float4 p31 = *(const float4*)(&ecp4[0] + off + 4);
            o0.x += p10.x + p20.x + p30.x; o0.y += p10.y + p20.y + p30.y;
            o0.z += p10.z + p20.z + p30.z; o0.w += p10.w + p20.w + p30.w;
            o1.x += p11.x + p21.x + p31.x; o1.y += p11.y + p21.y + p31.y;
            o1.z += p11.z + p21.z + p31.z; o1.w += p11.w + p21.w + p31.w;
            *(float4*)(hp + off)     = o0;
            *(float4*)(hp + off + 4) = o1;
        }
    }
}

// ============================ K2 ============================
__global__ __launch_bounds__(256) void k_edge_mix(
    const float* __restrict__ hfp, const float* __restrict__ edge_map,
    float* __restrict__ ho)
{
    __shared__ float hfs[32][64];
    __shared__ float em[32][32];
    int tid = threadIdx.x;
    int b = blockIdx.x;
    float4 s0 = make_float4(0.f,0.f,0.f,0.f), s1 = make_float4(0.f,0.f,0.f,0.f);
    const float* pb = hfp + (size_t)b*K1_BLOCKS_PER_B*(EE*DD) + tid*8;
    #pragma unroll 2
    for (int c = 0; c < K1_BLOCKS_PER_B; c++) {
        float4 a0 = *(const float4*)(pb + (size_t)c*(EE*DD));
        float4 a1 = *(const float4*)(pb + (size_t)c*(EE*DD) + 4);
        s0.x += a0.x; s0.y += a0.y; s0.z += a0.z; s0.w += a0.w;
        s1.x += a1.x; s1.y += a1.y; s1.z += a1.z; s1.w += a1.w;
    }
    int e = tid >> 3, dbase = (tid & 7) * 8;
    *(float4*)&hfs[e][dbase]     = s0;
    *(float4*)&hfs[e][dbase + 4] = s1;
    for (int i = tid; i < 1024; i += 256) em[i>>5][i&31] = edge_map[i];
    __syncthreads();
    float o[8];
    #pragma unroll
    for (int j = 0; j < 8; j++) o[j] = 0.f;
    #pragma unroll
    for (int f = 0; f < 32; f++) {
        float w = em[e][f];
        #pragma unroll
        for (int j = 0; j < 8; j++) o[j] = fmaf(w, hfs[f][dbase + j], o[j]);
    }
    float* ob = ho + b*EE*DD + e*DD + dbase;
    #pragma unroll
    for (int j = 0; j < 8; j++) ob[j] = fmaxf(o[j], 0.f) + hfs[e][dbase + j];
}

// ============================ K3: HMMA (mma.sync bf16 split) + fused epilogue ============================
#define K3_ROWS 64
#define K3_BLOCKS_PER_B ((TN + K3_ROWS - 1)/K3_ROWS)   // 135
#define GSTRIDE 132
// smem float layout: [gsm 64*132 = 8448 | hos 2048 | ass 2048 | prm 384]
// afrag (hi 2048 + lo 2048 u32) occupies gsm[0..4095] until the MMA completes.
#define K3_SMEM_FLOATS (8448 + 2048 + 2048 + 384)

__global__ __launch_bounds__(256, 3) void k_fused_out(
    const float* __restrict__ x,
    const uint32_t* __restrict__ wbf,   // this layer's 8192-u32 B fragments
    const float* __restrict__ b1, const float* __restrict__ b2,
    const float* __restrict__ ln1g, const float* __restrict__ ln1b,
    const float* __restrict__ ln2g, const float* __restrict__ ln2b,
    const float* __restrict__ assign, const float* __restrict__ ho,
    float* __restrict__ out)
{
    extern __shared__ float smem[];
    float* gsm  = smem;                 // [64][GSTRIDE]
    uint32_t* afrag = (uint32_t*)smem;  // hi [0..2047], lo [2048..4095]
    float* hos  = smem + 8448;          // [32][64]
    float* assf = hos + 2048;           // [64][32]
    float* prm  = assf + 2048;          // [6][64]

    int tid = threadIdx.x;
    int b = blockIdx.x;
    int base = blockIdx.y * K3_ROWS;
    int lane = tid & 31, warp = tid >> 5;
    const float* xb = x + (size_t)b*TN*DD;

    // ---- stage A fragments (xm hi/lo bf16 in mma register layout) ----
    for (int i = tid; i < 64*32; i += 256) {
        int lr = i >> 5, kp = i & 31, k = kp*2;
        int row = base + lr;
        float2 xv = make_float2(0.f, 0.f), xp = make_float2(0.f, 0.f);
        if (row < TN) {
            xv = *(const float2*)(xb + (size_t)row*DD + k);
            if (row >= NN) xp = *(const float2*)(xb + (size_t)(row - NN)*DD + k);
        }
        float m0 = 0.5f*(xv.x + xp.x), m1 = 0.5f*(xv.y + xp.y);
        float h0f = __bfloat162float(__float2bfloat16_rn(m0));
        float h1f = __bfloat162float(__float2bfloat16_rn(m1));
        int mtile = lr >> 4, row_in = lr & 15;
        int ktile = k >> 4,  col_in = k & 15;
        int reg  = ((col_in >> 3) << 1) | (row_in >> 3);
        int fl   = (row_in & 7)*4 + ((col_in & 7) >> 1);
        int off  = ((mtile*4 + ktile)*32 + fl)*4 + reg;
        afrag[off]        = pack_bf2(m0, m1);
        afrag[2048 + off] = pack_bf2(m0 - h0f, m1 - h1f);
    }
    // ---- stage assign / hos / prm ----
    for (int i = tid; i < 64*32; i += 256) {
        int lr = i >> 5, e = i & 31;
        int row = base + lr;
        assf[i] = (row < TN) ? assign[((size_t)b*TN + row)*EE + e] : 0.f;
    }
    for (int i = tid; i < 2048; i += 256) hos[i] = ho[b*EE*DD + i];
    if (tid < 64) {
        prm[0*64 + tid] = b1[tid];   prm[1*64 + tid] = b2[tid];
        prm[2*64 + tid] = ln1g[tid]; prm[3*64 + tid] = ln1b[tid];
        prm[4*64 + tid] = ln2g[tid]; prm[5*64 + tid] = ln2b[tid];
    }
    __syncthreads();

    // ---- MMA: D[64x128] = Ahi*Bhi + Ahi*Blo + Alo*Bhi ----
    // warp w: mtile = w&3 (rows), nhalf = w>>2 (8 ntiles of 8 cols)
    int mtile = warp & 3;
    int nh = warp >> 2;
    float d[8][4];
    #pragma unroll
    for (int j = 0; j < 8; j++)
        #pragma unroll
        for (int q = 0; q < 4; q++) d[j][q] = 0.f;

    #pragma unroll
    for (int pass = 0; pass < 3; pass++) {
        int sa = (pass == 2) ? 1 : 0;
        int sb = (pass == 1) ? 1 : 0;
        #pragma unroll
        for (int ktile = 0; ktile < 4; ktile++) {
            uint4 av = *(const uint4*)&afrag[sa*2048 + ((mtile*4 + ktile)*32 + lane)*4];
            #pragma unroll
            for (int j = 0; j < 8; j++) {
                int ntile = nh*8 + j;
                uint2 bv = __ldg((const uint2*)(wbf + (((sb*4 + ktile)*16 + ntile)*32 + lane)*2));
                mma_bf16(d[j], av.x, av.y, av.z, av.w, bv.x, bv.y);
            }
        }
    }
    __syncthreads();   // afrag dead; gsm region reusable

    // ---- store D fragments to gsm[row][col] ----
    {
        int r0 = mtile*16 + (lane >> 2);
        int cb = (lane & 3)*2;
        #pragma unroll
        for (int j = 0; j < 8; j++) {
            int cn = (nh*8 + j)*8 + cb;
            *(float2*)&gsm[r0*GSTRIDE + cn]       = make_float2(d[j][0], d[j][1]);
            *(float2*)&gsm[(r0+8)*GSTRIDE + cn]   = make_float2(d[j][2], d[j][3]);
        }
    }
    __syncthreads();

    // ---- epilogue: warp -> rows warp*8..+7 (R11 structure) ----
    float b1a = prm[0*64 + 2*lane], b1b = prm[0*64 + 2*lane + 1];
    float b2a = prm[1*64 + 2*lane], b2b = prm[1*64 + 2*lane + 1];
    float g1w = prm[2*64 + 2*lane], g1w2 = prm[2*64 + 2*lane + 1];
    float w1b = prm[3*64 + 2*lane], w1b2 = prm[3*64 + 2*lane + 1];
    float g2w = prm[4*64 + 2*lane], g2w2 = prm[4*64 + 2*lane + 1];
    float w2b = prm[5*64 + 2*lane], w2b2 = prm[5*64 + 2*lane + 1];
    float* ob = out + (size_t)b*TN*DD;
    int lrbase = warp*8;

    // hyper Y for 8 rows
    ull Y[8];
    #pragma unroll
    for (int r = 0; r < 8; r++) Y[r] = 0ull;
    #pragma unroll 4
    for (int e2 = 0; e2 < 16; e2++) {
        ull H0 = *(const ull*)&hos[(2*e2)*64 + 2*lane];
        ull H1 = *(const ull*)&hos[(2*e2+1)*64 + 2*lane];
        #pragma unroll
        for (int r = 0; r < 8; r++) {
            float2 a2 = *(const float2*)&assf[(lrbase + r)*32 + 2*e2];
            Y[r] = fma2(H0, packdup(a2.x), Y[r]);
            Y[r] = fma2(H1, packdup(a2.y), Y[r]);
        }
    }

    #pragma unroll
    for (int rg = 0; rg < 4; rg++) {
        float f0[2], f1[2], h0[2], h1[2], s[2], s2[2], t[2], t2[2];
        #pragma unroll
        for (int j = 0; j < 2; j++) {
            int lr = lrbase + rg*2 + j;
            int row = base + lr;
            float2 xv = make_float2(0.f, 0.f);
            if (row < TN) xv = *(const float2*)(xb + (size_t)row*DD + 2*lane);
            float2 gv1 = *(const float2*)&gsm[lr*GSTRIDE + 2*lane];
            float2 gv2 = *(const float2*)&gsm[lr*GSTRIDE + 64 + 2*lane];
            float g1a = gv1.x + b1a, g1b = gv1.y + b1b;
            float g2a = gv2.x + b2a, g2b = gv2.y + b2b;
            float y0, y1;
            unpack2(Y[rg*2 + j], y0, y1);
            f0[j] = fmaxf(g1a*g2a, 0.f) + g1a + xv.x;
            f1[j] = fmaxf(g1b*g2b, 0.f) + g1b + xv.y;
            h0[j] = fmaxf(y0, 0.f) + xv.x;
            h1[j] = fmaxf(y1, 0.f) + xv.y;
            s[j]  = f0[j] + f1[j];   s2[j] = f0[j]*f0[j] + f1[j]*f1[j];
            t[j]  = h0[j] + h1[j];   t2[j] = h0[j]*h0[j] + h1[j]*h1[j];
        }
        #pragma unroll
        for (int o = 16; o; o >>= 1) {
            #pragma unroll
            for (int j = 0; j < 2; j++) {
                s[j]  += __shfl_xor_sync(0xffffffffu, s[j],  o);
                s2[j] += __shfl_xor_sync(0xffffffffu, s2[j], o);
                t[j]  += __shfl_xor_sync(0xffffffffu, t[j],  o);
                t2[j] += __shfl_xor_sync(0xffffffffu, t2[j], o);
            }
        }
        #pragma unroll
        for (int j = 0; j < 2; j++) {
            int row = base + lrbase + rg*2 + j;
            float mu = s[j] * (1.f/64.f);
            float var = s2[j] * (1.f/64.f) - mu*mu;
            float rs = rsqrtf(var + 1e-5f);
            float o1a = (f0[j] - mu)*rs*g1w + w1b;
            float o1b = (f1[j] - mu)*rs*g1w2 + w1b2;
            float mu2 = t[j] * (1.f/64.f);
            float var2 = t2[j] * (1.f/64.f) - mu2*mu2;
            float rs2 = rsqrtf(var2 + 1e-5f);
            float o2a = (h0[j] - mu2)*rs2*g2w + w2b;
            float o2b = (h1[j] - mu2)*rs2*g2w2 + w2b2;
            if (row < TN)
                *(float2*)(ob + (size_t)row*DD + 2*lane) =
                    make_float2(0.5f*(o1a + o2a), 0.5f*(o1b + o2b));
        }
    }
}

extern "C" void kernel_launch(void* const* d_in, const int* in_sizes, int n_in,
                              void* d_out, int out_size) {
    const float* x    = (const float*)d_in[0];
    const float* W1   = (const float*)d_in[1];
    const float* b1   = (const float*)d_in[2];
    const float* W2   = (const float*)d_in[3];
    const float* b2   = (const float*)d_in[4];
    const float* ln1g = (const float*)d_in[5];
    const float* ln1b = (const float*)d_in[6];
    const float* eclf = (const float*)d_in[7];
    const float* emap = (const float*)d_in[8];
    const float* ln2g = (const float*)d_in[9];
    const float* ln2b = (const float*)d_in[10];

    float *bufA, *bufB, *assign, *hfp, *ho;
    uint32_t* wbf;
    cudaGetSymbolAddress((void**)&bufA,   g_bufA);
    cudaGetSymbolAddress((void**)&bufB,   g_bufB);
    cudaGetSymbolAddress((void**)&assign, g_assign);
    cudaGetSymbolAddress((void**)&hfp,    g_hfp);
    cudaGetSymbolAddress((void**)&ho,     g_ho);
    cudaGetSymbolAddress((void**)&wbf,    g_wbf);

    cudaFuncSetAttribute(k_fused_out, cudaFuncAttributeMaxDynamicSharedMemorySize,
                         K3_SMEM_FLOATS * (int)sizeof(float));

    k_prep_w<<<3, 256>>>(W1, W2, wbf);

    const float* cur = x;
    float* outs[3] = { bufA, bufB, (float*)d_out };

    for (int i = 0; i < 3; i++) {
        dim3 g1(BN, K1_BLOCKS_PER_B);
        k_assign_hf<<<g1, 256>>>(cur, eclf, assign, hfp);
        k_edge_mix<<<BN, 256>>>(hfp, emap, ho);
        dim3 g3(BN, K3_BLOCKS_PER_B);
        k_fused_out<<<g3, 256, K3_SMEM_FLOATS * sizeof(float)>>>(
            cur, wbf + (size_t)i*8192, b1 + i*DD, b2 + i*DD,
            ln1g + i*DD, ln1b + i*DD, ln2g, ln2b,
            assign, ho, outs[i]);
        cur = outs[i];
    }
}

// round 14
// speedup vs baseline: 1.9400x; 1.0941x over previous
#include <cuda_runtime.h>
#include <cuda_bf16.h>
#include <cstdint>

#define BN 64
#define TT 12
#define NN 716
#define DD 64
#define EE 32
#define TN 8592            // TT*NN
#define XELEMS 35192832    // BN*TN*DD

typedef unsigned long long ull;

#define K1_STAGE 64
#define K1_STAGES 4
#define K1_CHUNK (K1_STAGE*K1_STAGES)                     // 256
#define K1_BLOCKS_PER_B ((TN + K1_CHUNK - 1)/K1_CHUNK)    // 34

__device__ float g_bufA[XELEMS];
__device__ float g_bufB[XELEMS];
__device__ float g_assign[(size_t)BN*TN*EE];
__device__ float g_hfp[(size_t)BN*K1_BLOCKS_PER_B*EE*DD];
__device__ float g_ho[BN*EE*DD];
// GEMV B fragments: [layer][split(2)][ktile(4)][ntile(16)][lane(32)][reg(2)] u32
__device__ uint32_t g_wbf[3*2*4*16*32*2];
// hyper B fragments: [b][split(2)][ktile(2)][ntile(8)][lane(32)][reg(2)] u32
__device__ uint32_t g_hof[(size_t)BN*2048];

__device__ __forceinline__ ull fma2(ull a, ull b, ull c) {
    ull d;
    asm("fma.rn.f32x2 %0, %1, %2, %3;" : "=l"(d) : "l"(a), "l"(b), "l"(c));
    return d;
}
__device__ __forceinline__ ull packdup(float m) {
    ull d;
    asm("mov.b64 %0, {%1, %1};" : "=l"(d) : "f"(m));
    return d;
}
__device__ __forceinline__ ull pack2(float lo, float hi) {
    ull d;
    asm("mov.b64 %0, {%1, %2};" : "=l"(d) : "f"(lo), "f"(hi));
    return d;
}
__device__ __forceinline__ void unpack2(ull v, float& lo, float& hi) {
    asm("mov.b64 {%0, %1}, %2;" : "=f"(lo), "=f"(hi) : "l"(v));
}
__device__ __forceinline__ void mma_bf16(float* d, uint32_t a0, uint32_t a1, uint32_t a2, uint32_t a3,
                                         uint32_t b0, uint32_t b1) {
    asm volatile("mma.sync.aligned.m16n8k16.row.col.f32.bf16.bf16.f32 "
        "{%0,%1,%2,%3}, {%4,%5,%6,%7}, {%8,%9}, {%0,%1,%2,%3};"
        : "+f"(d[0]), "+f"(d[1]), "+f"(d[2]), "+f"(d[3])
        : "r"(a0), "r"(a1), "r"(a2), "r"(a3), "r"(b0), "r"(b1));
}
__device__ __forceinline__ uint32_t pack_bf2(float a, float b) {
    __nv_bfloat162 t;
    t.x = __float2bfloat16_rn(a);
    t.y = __float2bfloat16_rn(b);
    return *(uint32_t*)&t;
}

// ============================ prep: W -> B fragments (hi/lo bf16) ============================
__global__ __launch_bounds__(256) void k_prep_w(const float* __restrict__ W1,
                                                const float* __restrict__ W2,
                                                uint32_t* __restrict__ wbf) {
    int layer = blockIdx.x;
    const float* w1 = W1 + layer*DD*DD;
    const float* w2 = W2 + layer*DD*DD;
    uint32_t* out = wbf + (size_t)layer*8192;
    for (int i = threadIdx.x; i < 4096; i += 256) {
        int lane  = i & 31;
        int ntile = (i >> 5) & 15;
        int ktile = (i >> 9) & 3;
        int split = i >> 11;
        int k0 = ktile*16 + (lane & 3)*2;
        int n  = ntile*8 + (lane >> 2);
        float v[4];
        #pragma unroll
        for (int q = 0; q < 4; q++) {
            int k = k0 + (q >> 1)*8 + (q & 1);
            v[q] = (n < 64) ? w1[k*64 + n] : w2[k*64 + (n - 64)];
        }
        uint32_t r0, r1;
        if (split == 0) {
            r0 = pack_bf2(v[0], v[1]);
            r1 = pack_bf2(v[2], v[3]);
        } else {
            float l[4];
            #pragma unroll
            for (int q = 0; q < 4; q++)
                l[q] = v[q] - __bfloat162float(__float2bfloat16_rn(v[q]));
            r0 = pack_bf2(l[0], l[1]);
            r1 = pack_bf2(l[2], l[3]);
        }
        out[i*2 + 0] = r0;
        out[i*2 + 1] = r1;
    }
}

// ============================ K1: assign + hf partials (R11, verified) ============================
__global__ __launch_bounds__(256) void k_assign_hf(
    const float* __restrict__ x, const float* __restrict__ edge_clf,
    float* __restrict__ assign, float* __restrict__ hfp)
{
    __shared__ float ecp4[16*32*4];
    __shared__ float xs[64][64];
    __shared__ float as[64][32];
    int tid = threadIdx.x;
    int b = blockIdx.x;
    int r0base = blockIdx.y * K1_CHUNK;
    int lane = tid & 31, warp = tid >> 5;
    int group = tid >> 6;
    int gtid  = tid & 63;
    int e0    = (gtid >> 3) * 4;
    int dbase = (gtid & 7) * 8;

    for (int i = tid; i < 64*32; i += 256) {
        int k = i >> 5, e = i & 31;
        ecp4[(k>>2)*128 + e*4 + (k&3)] = edge_clf[i];
    }
    ull acc[16];
    #pragma unroll
    for (int j = 0; j < 16; j++) acc[j] = 0ull;
    const float* xb = x + (size_t)b*TN*DD;

    for (int s = 0; s < K1_STAGES; s++) {
        int r0 = r0base + s*K1_STAGE;
        __syncthreads();
        #pragma unroll
        for (int p = 0; p < 4; p++) {
            int row = p*16 + (tid >> 4);
            int q = (tid & 15) * 4;
            int gr = r0 + row;
            float4 v = make_float4(0.f,0.f,0.f,0.f);
            if (gr < TN) v = *(const float4*)(xb + (size_t)gr*DD + q);
            *(float4*)(&xs[row][q]) = v;
        }
        __syncthreads();
        {
            ull v2[8];
            #pragma unroll
            for (int j = 0; j < 8; j++) v2[j] = 0ull;
            #pragma unroll 4
            for (int k4 = 0; k4 < 16; k4++) {
                ulonglong2 ev = *(const ulonglong2*)&ecp4[k4*128 + lane*4];
                #pragma unroll
                for (int j = 0; j < 8; j++) {
                    ulonglong2 xv = *(const ulonglong2*)&xs[warp*8 + j][4*k4];
                    v2[j] = fma2(xv.x, ev.x, v2[j]);
                    v2[j] = fma2(xv.y, ev.y, v2[j]);
                }
            }
            #pragma unroll
            for (int jg = 0; jg < 2; jg++) {
                float vv[4], mm[4], ee[4], ss[4];
                #pragma unroll
                for (int j = 0; j < 4; j++) {
                    float vlo, vhi;
                    unpack2(v2[jg*4 + j], vlo, vhi);
                    vv[j] = vlo + vhi;
                    mm[j] = vv[j];
                }
                #pragma unroll
                for (int o = 16; o; o >>= 1) {
                    #pragma unroll
                    for (int j = 0; j < 4; j++)
                        mm[j] = fmaxf(mm[j], __shfl_xor_sync(0xffffffffu, mm[j], o));
                }
                #pragma unroll
                for (int j = 0; j < 4; j++) { ee[j] = __expf(vv[j] - mm[j]); ss[j] = ee[j]; }
                #pragma unroll
                for (int o = 16; o; o >>= 1) {
                    #pragma unroll
                    for (int j = 0; j < 4; j++)
                        ss[j] += __shfl_xor_sync(0xffffffffu, ss[j], o);
                }
                #pragma unroll
                for (int j = 0; j < 4; j++) {
                    int r = warp*8 + jg*4 + j;
                    int gr = r0 + r;
                    float p = ee[j] / ss[j];
                    bool valid = (gr < TN);
                    as[r][lane] = valid ? p : 0.f;
                    if (valid) assign[((size_t)b*TN + gr)*EE + lane] = p;
                }
            }
        }
        __syncthreads();
        #pragma unroll 4
        for (int rl = 0; rl < 16; rl++) {
            int r = group*16 + rl;
            float4 a4 = *(const float4*)&as[r][e0];
            ull ad0 = packdup(a4.x), ad1 = packdup(a4.y);
            ull ad2 = packdup(a4.z), ad3 = packdup(a4.w);
            ulonglong2 xlo = *(const ulonglong2*)&xs[r][dbase];
            ulonglong2 xhi = *(const ulonglong2*)&xs[r][dbase+4];
            acc[0]  = fma2(ad0, xlo.x, acc[0]);  acc[1]  = fma2(ad0, xlo.y, acc[1]);
            acc[2]  = fma2(ad0, xhi.x, acc[2]);  acc[3]  = fma2(ad0, xhi.y, acc[3]);
            acc[4]  = fma2(ad1, xlo.x, acc[4]);  acc[5]  = fma2(ad1, xlo.y, acc[5]);
            acc[6]  = fma2(ad1, xhi.x, acc[6]);  acc[7]  = fma2(ad1, xhi.y, acc[7]);
            acc[8]  = fma2(ad2, xlo.x, acc[8]);  acc[9]  = fma2(ad2, xlo.y, acc[9]);
            acc[10] = fma2(ad2, xhi.x, acc[10]); acc[11] = fma2(ad2, xhi.y, acc[11]);
            acc[12] = fma2(ad3, xlo.x, acc[12]); acc[13] = fma2(ad3, xlo.y, acc[13]);
            acc[14] = fma2(ad3, xhi.x, acc[14]); acc[15] = fma2(ad3, xhi.y, acc[15]);
        }
    }

    __syncthreads();
    if (group != 0) {
        float* pr = (group == 1) ? &xs[0][0] : (group == 2) ? &xs[32][0] : &ecp4[0];
        #pragma unroll
        for (int ee = 0; ee < 4; ee++) {
            *(ulonglong2*)&pr[(e0+ee)*64 + dbase]     = make_ulonglong2(acc[ee*4+0], acc[ee*4+1]);
            *(ulonglong2*)&pr[(e0+ee)*64 + dbase + 4] = make_ulonglong2(acc[ee*4+2], acc[ee*4+3]);
        }
    }
    __syncthreads();
    if (group == 0) {
        float* hp = hfp + ((size_t)b*K1_BLOCKS_PER_B + blockIdx.y)*(EE*DD);
        #pragma unroll
        for (int ee = 0; ee < 4; ee++) {
            float4 o0, o1;
            float t0, t1;
            unpack2(acc[ee*4+0], t0, t1); o0.x = t0; o0.y = t1;
            unpack2(acc[ee*4+1], t0, t1); o0.z = t0; o0.w = t1;
            unpack2(acc[ee*4+2], t0, t1); o1.x = t0; o1.y = t1;
            unpack2(acc[ee*4+3], t0, t1); o1.z = t0; o1.w = t1;
            int off = (e0+ee)*64 + dbase;
            float4 p10 = *(const float4*)(&xs[0][0] + off);
            float4 p11 = *(const float4*)(&xs[0][0] + off + 4);
            float4 p20 = *(const float4*)(&xs[32][0] + off);
            float4 p21 = *(const float4*)(&xs[32][0] + off + 4);
            float4 p30 = *(const float4*)(&ecp4[0] + off);
            float4 p31 = *(const float4*)(&ecp4[0] + off + 4);
            o0.x += p10.x + p20.x + p30.x; o0.y += p10.y + p20.y + p30.y;
            o0.z += p10.z + p20.z + p30.z; o0.w += p10.w + p20.w + p30.w;
            o1.x += p11.x + p21.x + p31.x; o1.y += p11.y + p21.y + p31.y;
            o1.z += p11.z + p21.z + p31.z; o1.w += p11.w + p21.w + p31.w;
            *(float4*)(hp + off)     = o0;
            *(float4*)(hp + off + 4) = o1;
        }
    }
}

// ============================ K2: reduce + edge mix + emit ho fragments ============================
__global__ __launch_bounds__(256) void k_edge_mix(
    const float* __restrict__ hfp, const float* __restrict__ edge_map,
    float* __restrict__ ho, uint32_t* __restrict__ hof)
{
    __shared__ float hfs[32][64];
    __shared__ float em[32][32];
    __shared__ float hos2[32][64];
    int tid = threadIdx.x;
    int b = blockIdx.x;
    float4 s0 = make_float4(0.f,0.f,0.f,0.f), s1 = make_float4(0.f,0.f,0.f,0.f);
    const float* pb = hfp + (size_t)b*K1_BLOCKS_PER_B*(EE*DD) + tid*8;
    #pragma unroll 2
    for (int c = 0; c < K1_BLOCKS_PER_B; c++) {
        float4 a0 = *(const float4*)(pb + (size_t)c*(EE*DD));
        float4 a1 = *(const float4*)(pb + (size_t)c*(EE*DD) + 4);
        s0.x += a0.x; s0.y += a0.y; s0.z += a0.z; s0.w += a0.w;
        s1.x += a1.x; s1.y += a1.y; s1.z += a1.z; s1.w += a1.w;
    }
    int e = tid >> 3, dbase = (tid & 7) * 8;
    *(float4*)&hfs[e][dbase]     = s0;
    *(float4*)&hfs[e][dbase + 4] = s1;
    for (int i = tid; i < 1024; i += 256) em[i>>5][i&31] = edge_map[i];
    __syncthreads();
    float o[8];
    #pragma unroll
    for (int j = 0; j < 8; j++) o[j] = 0.f;
    #pragma unroll
    for (int f = 0; f < 32; f++) {
        float w = em[e][f];
        #pragma unroll
        for (int j = 0; j < 8; j++) o[j] = fmaf(w, hfs[f][dbase + j], o[j]);
    }
    float* ob = ho + b*EE*DD + e*DD + dbase;
    #pragma unroll
    for (int j = 0; j < 8; j++) {
        float v = fmaxf(o[j], 0.f) + hfs[e][dbase + j];
        ob[j] = v;
        hos2[e][dbase + j] = v;
    }
    __syncthreads();
    // emit ho B-fragments: [split(2)][ktile(2)][ntile(8)][lane(32)][reg(2)]
    uint32_t* hb = hof + (size_t)b*2048;
    for (int i = tid; i < 2048; i += 256) {
        int reg   = i & 1;
        int lane2 = (i >> 1) & 31;
        int ntile = (i >> 6) & 7;
        int ktile = (i >> 9) & 1;
        int split = i >> 10;
        int k = ktile*16 + (lane2 & 3)*2 + reg*8;
        int n = ntile*8 + (lane2 >> 2);
        float v0 = hos2[k][n], v1 = hos2[k+1][n];
        uint32_t val;
        if (split == 0) val = pack_bf2(v0, v1);
        else {
            float l0 = v0 - __bfloat162float(__float2bfloat16_rn(v0));
            float l1 = v1 - __bfloat162float(__float2bfloat16_rn(v1));
            val = pack_bf2(l0, l1);
        }
        hb[((split*2 + ktile)*8 + ntile)*64 + lane2*2 + reg] = val;
    }
}

// ============================ K3: dual HMMA (GEMV + hyper) + fused epilogue ============================
#define K3_ROWS 64
#define K3_BLOCKS_PER_B ((TN + K3_ROWS - 1)/K3_ROWS)   // 135
#define GSTRIDE 196
// smem: gsm[64][196] (12544 fl; afrag u32[0..4095], pfrag u32[4096..6143] live pre-MMA) + prm 384
#define K3_SMEM_FLOATS (64*GSTRIDE + 384)

__global__ __launch_bounds__(256, 3) void k_fused_out(
    const float* __restrict__ x,
    const uint32_t* __restrict__ wbf,   // this layer's 8192-u32 GEMV B fragments
    const uint32_t* __restrict__ hof,   // per-batch hyper B fragments
    const float* __restrict__ b1, const float* __restrict__ b2,
    const float* __restrict__ ln1g, const float* __restrict__ ln1b,
    const float* __restrict__ ln2g, const float* __restrict__ ln2b,
    const float* __restrict__ assign,
    float* __restrict__ out)
{
    extern __shared__ float smem[];
    float* gsm  = smem;                  // [64][GSTRIDE]
    uint32_t* afrag = (uint32_t*)smem;   // xm hi [0..2047], lo [2048..4095]
    uint32_t* pfrag = (uint32_t*)smem + 4096;  // assign hi [0..1023], lo [1024..2047]
    float* prm  = smem + 64*GSTRIDE;     // [6][64]

    int tid = threadIdx.x;
    int b = blockIdx.x;
    int base = blockIdx.y * K3_ROWS;
    int lane = tid & 31, warp = tid >> 5;
    const float* xb = x + (size_t)b*TN*DD;
    const float* ab = assign + (size_t)b*TN*EE;

    // ---- stage xm A-fragments (hi/lo) ----
    for (int i = tid; i < 64*32; i += 256) {
        int lr = i >> 5, kp = i & 31, k = kp*2;
        int row = base + lr;
        float2 xv = make_float2(0.f, 0.f), xp = make_float2(0.f, 0.f);
        if (row < TN) {
            xv = *(const float2*)(xb + (size_t)row*DD + k);
            if (row >= NN) xp = *(const float2*)(xb + (size_t)(row - NN)*DD + k);
        }
        float m0 = 0.5f*(xv.x + xp.x), m1 = 0.5f*(xv.y + xp.y);
        float h0f = __bfloat162float(__float2bfloat16_rn(m0));
        float h1f = __bfloat162float(__float2bfloat16_rn(m1));
        int mtile = lr >> 4, row_in = lr & 15;
        int ktile = k >> 4,  col_in = k & 15;
        int reg  = ((col_in >> 3) << 1) | (row_in >> 3);
        int fl   = (row_in & 7)*4 + ((col_in & 7) >> 1);
        int off  = ((mtile*4 + ktile)*32 + fl)*4 + reg;
        afrag[off]        = pack_bf2(m0, m1);
        afrag[2048 + off] = pack_bf2(m0 - h0f, m1 - h1f);
    }
    // ---- stage assign A-fragments (hi/lo), K=32 ----
    for (int i = tid; i < 64*16; i += 256) {
        int lr = i >> 4, kp = i & 15, k = kp*2;
        int row = base + lr;
        float a0 = 0.f, a1 = 0.f;
        if (row < TN) {
            float2 av = *(const float2*)(ab + (size_t)row*EE + k);
            a0 = av.x; a1 = av.y;
        }
        float h0f = __bfloat162float(__float2bfloat16_rn(a0));
        float h1f = __bfloat162float(__float2bfloat16_rn(a1));
        int mtile = lr >> 4, row_in = lr & 15;
        int ktile = k >> 4,  col_in = k & 15;
        int reg  = ((col_in >> 3) << 1) | (row_in >> 3);
        int fl   = (row_in & 7)*4 + ((col_in & 7) >> 1);
        int off  = ((mtile*2 + ktile)*32 + fl)*4 + reg;
        pfrag[off]        = pack_bf2(a0, a1);
        pfrag[1024 + off] = pack_bf2(a0 - h0f, a1 - h1f);
    }
    if (tid < 64) {
        prm[0*64 + tid] = b1[tid];   prm[1*64 + tid] = b2[tid];
        prm[2*64 + tid] = ln1g[tid]; prm[3*64 + tid] = ln1b[tid];
        prm[4*64 + tid] = ln2g[tid]; prm[5*64 + tid] = ln2b[tid];
    }
    __syncthreads();

    int mtile = warp & 3;
    int nh = warp >> 2;

    // ---- GEMV MMA: D[64x128] = Ahi*Bhi + Ahi*Blo + Alo*Bhi ----
    float d[8][4];
    #pragma unroll
    for (int j = 0; j < 8; j++)
        #pragma unroll
        for (int q = 0; q < 4; q++) d[j][q] = 0.f;
    #pragma unroll
    for (int pass = 0; pass < 3; pass++) {
        int sa = (pass == 2) ? 1 : 0;
        int sb = (pass == 1) ? 1 : 0;
        #pragma unroll
        for (int ktile = 0; ktile < 4; ktile++) {
            uint4 av = *(const uint4*)&afrag[sa*2048 + ((mtile*4 + ktile)*32 + lane)*4];
            #pragma unroll
            for (int j = 0; j < 8; j++) {
                int ntile = nh*8 + j;
                uint2 bv = __ldg((const uint2*)(wbf + (((sb*4 + ktile)*16 + ntile)*32 + lane)*2));
                mma_bf16(d[j], av.x, av.y, av.z, av.w, bv.x, bv.y);
            }
        }
    }

    // ---- hyper MMA: Y[64x64] = Phi*Hhi + Phi*Hlo + Plo*Hhi ----
    const uint32_t* hofb = hof + (size_t)b*2048;
    float dY[4][4];
    #pragma unroll
    for (int j = 0; j < 4; j++)
        #pragma unroll
        for (int q = 0; q < 4; q++) dY[j][q] = 0.f;
    #pragma unroll
    for (int pass = 0; pass < 3; pass++) {
        int sa = (pass == 2) ? 1 : 0;
        int sb = (pass == 1) ? 1 : 0;
        #pragma unroll
        for (int ktile = 0; ktile < 2; ktile++) {
            uint4 av = *(const uint4*)&pfrag[sa*1024 + ((mtile*2 + ktile)*32 + lane)*4];
            #pragma unroll
            for (int j = 0; j < 4; j++) {
                int ntile = nh*4 + j;
                uint2 bv = __ldg((const uint2*)(hofb + (((sb*2 + ktile)*8 + ntile)*32 + lane)*2));
                mma_bf16(dY[j], av.x, av.y, av.z, av.w, bv.x, bv.y);
            }
        }
    }
    __syncthreads();   // afrag/pfrag dead; gsm reusable

    // ---- store D and Y fragments to gsm ----
    {
        int r0 = mtile*16 + (lane >> 2);
        int cb = (lane & 3)*2;
        #pragma unroll
        for (int j = 0; j < 8; j++) {
            int cn = (nh*8 + j)*8 + cb;
            *(float2*)&gsm[r0*GSTRIDE + cn]     = make_float2(d[j][0], d[j][1]);
            *(float2*)&gsm[(r0+8)*GSTRIDE + cn] = make_float2(d[j][2], d[j][3]);
        }
        #pragma unroll
        for (int j = 0; j < 4; j++) {
            int cn = 128 + (nh*4 + j)*8 + cb;
            *(float2*)&gsm[r0*GSTRIDE + cn]     = make_float2(dY[j][0], dY[j][1]);
            *(float2*)&gsm[(r0+8)*GSTRIDE + cn] = make_float2(dY[j][2], dY[j][3]);
        }
    }
    __syncthreads();

    // ---- epilogue: warp -> rows warp*8..+7 ----
    float b1a = prm[0*64 + 2*lane], b1b = prm[0*64 + 2*lane + 1];
    float b2a = prm[1*64 + 2*lane], b2b = prm[1*64 + 2*lane + 1];
    float g1w = prm[2*64 + 2*lane], g1w2 = prm[2*64 + 2*lane + 1];
    float w1b = prm[3*64 + 2*lane], w1b2 = prm[3*64 + 2*lane + 1];
    float g2w = prm[4*64 + 2*lane], g2w2 = prm[4*64 + 2*lane + 1];
    float w2b = prm[5*64 + 2*lane], w2b2 = prm[5*64 + 2*lane + 1];
    float* ob = out + (size_t)b*TN*DD;
    int lrbase = warp*8;

    #pragma unroll
    for (int rg = 0; rg < 4; rg++) {
        float f0[2], f1[2], h0[2], h1[2], s[2], s2[2], t[2], t2[2];
        #pragma unroll
        for (int j = 0; j < 2; j++) {
            int lr = lrbase + rg*2 + j;
            int row = base + lr;
            float2 xv = make_float2(0.f, 0.f);
            if (row < TN) xv = *(const float2*)(xb + (size_t)row*DD + 2*lane);
            float2 gv1 = *(const float2*)&gsm[lr*GSTRIDE + 2*lane];
            float2 gv2 = *(const float2*)&gsm[lr*GSTRIDE + 64 + 2*lane];
            float2 yv  = *(const float2*)&gsm[lr*GSTRIDE + 128 + 2*lane];
            float g1a = gv1.x + b1a, g1b = gv1.y + b1b;
            float g2a = gv2.x + b2a, g2b = gv2.y + b2b;
            f0[j] = fmaxf(g1a*g2a, 0.f) + g1a + xv.x;
            f1[j] = fmaxf(g1b*g2b, 0.f) + g1b + xv.y;
            h0[j] = fmaxf(yv.x, 0.f) + xv.x;
            h1[j] = fmaxf(yv.y, 0.f) + xv.y;
            s[j]  = f0[j] + f1[j];   s2[j] = f0[j]*f0[j] + f1[j]*f1[j];
            t[j]  = h0[j] + h1[j];   t2[j] = h0[j]*h0[j] + h1[j]*h1[j];
        }
        #pragma unroll
        for (int o = 16; o; o >>= 1) {
            #pragma unroll
            for (int j = 0; j < 2; j++) {
                s[j]  += __shfl_xor_sync(0xffffffffu, s[j],  o);
                s2[j] += __shfl_xor_sync(0xffffffffu, s2[j], o);
                t[j]  += __shfl_xor_sync(0xffffffffu, t[j],  o);
                t2[j] += __shfl_xor_sync(0xffffffffu, t2[j], o);
            }
        }
        #pragma unroll
        for (int j = 0; j < 2; j++) {
            int row = base + lrbase + rg*2 + j;
            float mu = s[j] * (1.f/64.f);
            float var = s2[j] * (1.f/64.f) - mu*mu;
            float rs = rsqrtf(var + 1e-5f);
            float o1a = (f0[j] - mu)*rs*g1w + w1b;
            float o1b = (f1[j] - mu)*rs*g1w2 + w1b2;
            float mu2 = t[j] * (1.f/64.f);
            float var2 = t2[j] * (1.f/64.f) - mu2*mu2;
            float rs2 = rsqrtf(var2 + 1e-5f);
            float o2a = (h0[j] - mu2)*rs2*g2w + w2b;
            float o2b = (h1[j] - mu2)*rs2*g2w2 + w2b2;
            if (row < TN)
                *(float2*)(ob + (size_t)row*DD + 2*lane) =
                    make_float2(0.5f*(o1a + o2a), 0.5f*(o1b + o2b));
        }
    }
}

extern "C" void kernel_launch(void* const* d_in, const int* in_sizes, int n_in,
                              void* d_out, int out_size) {
    const float* x    = (const float*)d_in[0];
    const float* W1   = (const float*)d_in[1];
    const float* b1   = (const float*)d_in[2];
    const float* W2   = (const float*)d_in[3];
    const float* b2   = (const float*)d_in[4];
    const float* ln1g = (const float*)d_in[5];
    const float* ln1b = (const float*)d_in[6];
    const float* eclf = (const float*)d_in[7];
    const float* emap = (const float*)d_in[8];
    const float* ln2g = (const float*)d_in[9];
    const float* ln2b = (const float*)d_in[10];

    float *bufA, *bufB, *assign, *hfp, *ho;
    uint32_t *wbf, *hof;
    cudaGetSymbolAddress((void**)&bufA,   g_bufA);
    cudaGetSymbolAddress((void**)&bufB,   g_bufB);
    cudaGetSymbolAddress((void**)&assign, g_assign);
    cudaGetSymbolAddress((void**)&hfp,    g_hfp);
    cudaGetSymbolAddress((void**)&ho,     g_ho);
    cudaGetSymbolAddress((void**)&wbf,    g_wbf);
    cudaGetSymbolAddress((void**)&hof,    g_hof);

    cudaFuncSetAttribute(k_fused_out, cudaFuncAttributeMaxDynamicSharedMemorySize,
                         K3_SMEM_FLOATS * (int)sizeof(float));

    k_prep_w<<<3, 256>>>(W1, W2, wbf);

    const float* cur = x;
    float* outs[3] = { bufA, bufB, (float*)d_out };

    for (int i = 0; i < 3; i++) {
        dim3 g1(BN, K1_BLOCKS_PER_B);
        k_assign_hf<<<g1, 256>>>(cur, eclf, assign, hfp);
        k_edge_mix<<<BN, 256>>>(hfp, emap, ho, hof);
        dim3 g3(BN, K3_BLOCKS_PER_B);
        k_fused_out<<<g3, 256, K3_SMEM_FLOATS * sizeof(float)>>>(
            cur, wbf + (size_t)i*8192, hof, b1 + i*DD, b2 + i*DD,
            ln1g + i*DD, ln1b + i*DD, ln2g, ln2b,
            assign, outs[i]);
        cur = outs[i];
    }
}

// round 15
// speedup vs baseline: 1.9948x; 1.0282x over previous
#include <cuda_runtime.h>
#include <cuda_bf16.h>
#include <cstdint>

#define BN 64
#define TT 12
#define NN 716
#define DD 64
#define EE 32
#define TN 8592            // TT*NN
#define XELEMS 35192832    // BN*TN*DD

typedef unsigned long long ull;

#define K1_STAGE 64
#define K1_STAGES 4
#define K1_CHUNK (K1_STAGE*K1_STAGES)                     // 256
#define K1_BLOCKS_PER_B ((TN + K1_CHUNK - 1)/K1_CHUNK)    // 34

__device__ float g_bufA[XELEMS];
__device__ float g_bufB[XELEMS];
__device__ float g_assign[(size_t)BN*TN*EE];
__device__ float g_hfp[(size_t)BN*K1_BLOCKS_PER_B*EE*DD];
__device__ float g_ho[BN*EE*DD];
// GEMV B fragments: [layer][split(2)][ktile(4)][ntile(16)][lane(32)][reg(2)] u32
__device__ uint32_t g_wbf[3*2*4*16*32*2];
// hyper B fragments: [b][split(2)][ktile(2)][ntile(8)][lane(32)][reg(2)] u32
__device__ uint32_t g_hof[(size_t)BN*2048];

__device__ __forceinline__ ull fma2(ull a, ull b, ull c) {
    ull d;
    asm("fma.rn.f32x2 %0, %1, %2, %3;" : "=l"(d) : "l"(a), "l"(b), "l"(c));
    return d;
}
__device__ __forceinline__ ull packdup(float m) {
    ull d;
    asm("mov.b64 %0, {%1, %1};" : "=l"(d) : "f"(m));
    return d;
}
__device__ __forceinline__ ull pack2(float lo, float hi) {
    ull d;
    asm("mov.b64 %0, {%1, %2};" : "=l"(d) : "f"(lo), "f"(hi));
    return d;
}
__device__ __forceinline__ void unpack2(ull v, float& lo, float& hi) {
    asm("mov.b64 {%0, %1}, %2;" : "=f"(lo), "=f"(hi) : "l"(v));
}
__device__ __forceinline__ void mma_bf16(float* d, uint32_t a0, uint32_t a1, uint32_t a2, uint32_t a3,
                                         uint32_t b0, uint32_t b1) {
    asm volatile("mma.sync.aligned.m16n8k16.row.col.f32.bf16.bf16.f32 "
        "{%0,%1,%2,%3}, {%4,%5,%6,%7}, {%8,%9}, {%0,%1,%2,%3};"
        : "+f"(d[0]), "+f"(d[1]), "+f"(d[2]), "+f"(d[3])
        : "r"(a0), "r"(a1), "r"(a2), "r"(a3), "r"(b0), "r"(b1));
}
__device__ __forceinline__ uint32_t pack_bf2(float a, float b) {
    __nv_bfloat162 t;
    t.x = __float2bfloat16_rn(a);
    t.y = __float2bfloat16_rn(b);
    return *(uint32_t*)&t;
}
__device__ __forceinline__ float bf16lo(float v) {
    return v - __bfloat162float(__float2bfloat16_rn(v));
}

// ============================ prep: W -> B fragments (hi/lo bf16) ============================
__global__ __launch_bounds__(256) void k_prep_w(const float* __restrict__ W1,
                                                const float* __restrict__ W2,
                                                uint32_t* __restrict__ wbf) {
    int layer = blockIdx.x;
    const float* w1 = W1 + layer*DD*DD;
    const float* w2 = W2 + layer*DD*DD;
    uint32_t* out = wbf + (size_t)layer*8192;
    for (int i = threadIdx.x; i < 4096; i += 256) {
        int lane  = i & 31;
        int ntile = (i >> 5) & 15;
        int ktile = (i >> 9) & 3;
        int split = i >> 11;
        int k0 = ktile*16 + (lane & 3)*2;
        int n  = ntile*8 + (lane >> 2);
        float v[4];
        #pragma unroll
        for (int q = 0; q < 4; q++) {
            int k = k0 + (q >> 1)*8 + (q & 1);
            v[q] = (n < 64) ? w1[k*64 + n] : w2[k*64 + (n - 64)];
        }
        uint32_t r0, r1;
        if (split == 0) {
            r0 = pack_bf2(v[0], v[1]);
            r1 = pack_bf2(v[2], v[3]);
        } else {
            r0 = pack_bf2(bf16lo(v[0]), bf16lo(v[1]));
            r1 = pack_bf2(bf16lo(v[2]), bf16lo(v[3]));
        }
        out[i*2 + 0] = r0;
        out[i*2 + 1] = r1;
    }
}

// ============================ K1: assign + hf partials (rank-1 via HMMA) ============================
// dyn smem: ecp4[2048] | xs[4096] | as_[2048] | atf u32[2048] | bxf u32[4096]  = 57344 B
#define K1_SMEM_FLOATS 14336

__global__ __launch_bounds__(256, 4) void k_assign_hf(
    const float* __restrict__ x, const float* __restrict__ edge_clf,
    float* __restrict__ assign, float* __restrict__ hfp)
{
    extern __shared__ float sm1[];
    float* ecp4 = sm1;                    // [k4][e][kk]
    float* xs   = sm1 + 2048;             // [64][64]
    float* as_  = sm1 + 6144;             // [64][32]
    uint32_t* atf = (uint32_t*)(sm1 + 8192);   // [split2][(mtile*4+ktile)*32+fl][4]
    uint32_t* bxf = (uint32_t*)(sm1 + 10240);  // [split2][(ktile*8+ntile)*32+lane][2]

    int tid = threadIdx.x;
    int b = blockIdx.x;
    int r0base = blockIdx.y * K1_CHUNK;
    int lane = tid & 31, warp = tid >> 5;

    for (int i = tid; i < 64*32; i += 256) {
        int k = i >> 5, e = i & 31;
        ecp4[(k>>2)*128 + e*4 + (k&3)] = edge_clf[i];
    }

    // D accumulators: warp w -> mtile = w>>2, ntiles (w&3)*2 + {0,1}
    float D0[4], D1[4];
    #pragma unroll
    for (int q = 0; q < 4; q++) { D0[q] = 0.f; D1[q] = 0.f; }
    int mtile = warp >> 2;
    int nt0 = (warp & 3) * 2;

    const float* xb = x + (size_t)b*TN*DD;

    for (int s = 0; s < K1_STAGES; s++) {
        int r0 = r0base + s*K1_STAGE;
        __syncthreads();
        #pragma unroll
        for (int p = 0; p < 4; p++) {
            int row = p*16 + (tid >> 4);
            int q = (tid & 15) * 4;
            int gr = r0 + row;
            float4 v = make_float4(0.f,0.f,0.f,0.f);
            if (gr < TN) v = *(const float4*)(xb + (size_t)gr*DD + q);
            *(float4*)(&xs[row*64 + q]) = v;
        }
        __syncthreads();
        // ---- logits via fma2: warp -> rows warp*8..+7, lane = e ----
        {
            ull v2[8];
            #pragma unroll
            for (int j = 0; j < 8; j++) v2[j] = 0ull;
            #pragma unroll 4
            for (int k4 = 0; k4 < 16; k4++) {
                ulonglong2 ev = *(const ulonglong2*)&ecp4[k4*128 + lane*4];
                #pragma unroll
                for (int j = 0; j < 8; j++) {
                    ulonglong2 xv = *(const ulonglong2*)&xs[(warp*8 + j)*64 + 4*k4];
                    v2[j] = fma2(xv.x, ev.x, v2[j]);
                    v2[j] = fma2(xv.y, ev.y, v2[j]);
                }
            }
            #pragma unroll
            for (int jg = 0; jg < 2; jg++) {
                float vv[4], mm[4], ee[4], ss[4];
                #pragma unroll
                for (int j = 0; j < 4; j++) {
                    float vlo, vhi;
                    unpack2(v2[jg*4 + j], vlo, vhi);
                    vv[j] = vlo + vhi;
                    mm[j] = vv[j];
                }
                #pragma unroll
                for (int o = 16; o; o >>= 1) {
                    #pragma unroll
                    for (int j = 0; j < 4; j++)
                        mm[j] = fmaxf(mm[j], __shfl_xor_sync(0xffffffffu, mm[j], o));
                }
                #pragma unroll
                for (int j = 0; j < 4; j++) { ee[j] = __expf(vv[j] - mm[j]); ss[j] = ee[j]; }
                #pragma unroll
                for (int o = 16; o; o >>= 1) {
                    #pragma unroll
                    for (int j = 0; j < 4; j++)
                        ss[j] += __shfl_xor_sync(0xffffffffu, ss[j], o);
                }
                #pragma unroll
                for (int j = 0; j < 4; j++) {
                    int r = warp*8 + jg*4 + j;
                    int gr = r0 + r;
                    float p = ee[j] / ss[j];
                    bool valid = (gr < TN);
                    as_[r*32 + lane] = valid ? p : 0.f;
                    if (valid) assign[((size_t)b*TN + gr)*EE + lane] = p;
                }
            }
        }
        __syncthreads();
        // ---- stage atf: slot = tid (mtile2 x ktile4 x fl32) ----
        {
            int fl = tid & 31, kt = (tid >> 5) & 3, mt = tid >> 7;
            int e0 = mt*16 + (fl >> 2);
            int e1 = e0 + 8;
            int rb = kt*16 + (fl & 3)*2;
            float a00 = as_[rb*32 + e0],     a01 = as_[(rb+1)*32 + e0];
            float a10 = as_[rb*32 + e1],     a11 = as_[(rb+1)*32 + e1];
            float a02 = as_[(rb+8)*32 + e0], a03 = as_[(rb+9)*32 + e0];
            float a12 = as_[(rb+8)*32 + e1], a13 = as_[(rb+9)*32 + e1];
            uint4 hi, lo;
            hi.x = pack_bf2(a00, a01); lo.x = pack_bf2(bf16lo(a00), bf16lo(a01));
            hi.y = pack_bf2(a10, a11); lo.y = pack_bf2(bf16lo(a10), bf16lo(a11));
            hi.z = pack_bf2(a02, a03); lo.z = pack_bf2(bf16lo(a02), bf16lo(a03));
            hi.w = pack_bf2(a12, a13); lo.w = pack_bf2(bf16lo(a12), bf16lo(a13));
            int off = ((mt*4 + kt)*32 + fl)*4;
            *(uint4*)&atf[off]        = hi;
            *(uint4*)&atf[1024 + off] = lo;
        }
        // ---- stage bxf: 4 slots/thread (ktile4 x ntile8 x lane32) ----
        #pragma unroll
        for (int ii = 0; ii < 4; ii++) {
            int slot = tid + ii*256;
            int ln2 = slot & 31, ntl = (slot >> 5) & 7, kt = slot >> 8;
            int n = ntl*8 + (ln2 >> 2);
            int k0 = kt*16 + (ln2 & 3)*2;
            float v0 = xs[k0*64 + n],     v1 = xs[(k0+1)*64 + n];
            float v2 = xs[(k0+8)*64 + n], v3 = xs[(k0+9)*64 + n];
            int off = ((kt*8 + ntl)*32 + ln2)*2;
            bxf[off]     = pack_bf2(v0, v1);
            bxf[off + 1] = pack_bf2(v2, v3);
            bxf[2048 + off]     = pack_bf2(bf16lo(v0), bf16lo(v1));
            bxf[2048 + off + 1] = pack_bf2(bf16lo(v2), bf16lo(v3));
        }
        __syncthreads();
        // ---- MMA: D += asT(hi/lo) @ xs(hi/lo), 3-pass split ----
        #pragma unroll
        for (int pass = 0; pass < 3; pass++) {
            int sa = (pass == 2) ? 1 : 0;
            int sb = (pass == 1) ? 1 : 0;
            #pragma unroll
            for (int kt = 0; kt < 4; kt++) {
                uint4 av = *(const uint4*)&atf[sa*1024 + ((mtile*4 + kt)*32 + lane)*4];
                uint2 bv0 = *(const uint2*)&bxf[sb*2048 + ((kt*8 + nt0)*32 + lane)*2];
                uint2 bv1 = *(const uint2*)&bxf[sb*2048 + ((kt*8 + nt0 + 1)*32 + lane)*2];
                mma_bf16(D0, av.x, av.y, av.z, av.w, bv0.x, bv0.y);
                mma_bf16(D1, av.x, av.y, av.z, av.w, bv1.x, bv1.y);
            }
        }
    }

    // ---- store hf partials from D fragments ----
    float* hp = hfp + ((size_t)b*K1_BLOCKS_PER_B + blockIdx.y)*(EE*DD);
    int e0 = mtile*16 + (lane >> 2);
    int d0 = nt0*8 + (lane & 3)*2;
    *(float2*)(hp + e0*64 + d0)         = make_float2(D0[0], D0[1]);
    *(float2*)(hp + (e0+8)*64 + d0)     = make_float2(D0[2], D0[3]);
    *(float2*)(hp + e0*64 + d0 + 8)     = make_float2(D1[0], D1[1]);
    *(float2*)(hp + (e0+8)*64 + d0 + 8) = make_float2(D1[2], D1[3]);
}

// ============================ K2: reduce + edge mix + emit ho fragments ============================
__global__ __launch_bounds__(256) void k_edge_mix(
    const float* __restrict__ hfp, const float* __restrict__ edge_map,
    float* __restrict__ ho, uint32_t* __restrict__ hof)
{
    __shared__ float hfs[32][64];
    __shared__ float em[32][32];
    __shared__ float hos2[32][64];
    int tid = threadIdx.x;
    int b = blockIdx.x;
    float4 s0 = make_float4(0.f,0.f,0.f,0.f), s1 = make_float4(0.f,0.f,0.f,0.f);
    const float* pb = hfp + (size_t)b*K1_BLOCKS_PER_B*(EE*DD) + tid*8;
    #pragma unroll 2
    for (int c = 0; c < K1_BLOCKS_PER_B; c++) {
        float4 a0 = *(const float4*)(pb + (size_t)c*(EE*DD));
        float4 a1 = *(const float4*)(pb + (size_t)c*(EE*DD) + 4);
        s0.x += a0.x; s0.y += a0.y; s0.z += a0.z; s0.w += a0.w;
        s1.x += a1.x; s1.y += a1.y; s1.z += a1.z; s1.w += a1.w;
    }
    int e = tid >> 3, dbase = (tid & 7) * 8;
    *(float4*)&hfs[e][dbase]     = s0;
    *(float4*)&hfs[e][dbase + 4] = s1;
    for (int i = tid; i < 1024; i += 256) em[i>>5][i&31] = edge_map[i];
    __syncthreads();
    float o[8];
    #pragma unroll
    for (int j = 0; j < 8; j++) o[j] = 0.f;
    #pragma unroll
    for (int f = 0; f < 32; f++) {
        float w = em[e][f];
        #pragma unroll
        for (int j = 0; j < 8; j++) o[j] = fmaf(w, hfs[f][dbase + j], o[j]);
    }
    float* ob = ho + b*EE*DD + e*DD + dbase;
    #pragma unroll
    for (int j = 0; j < 8; j++) {
        float v = fmaxf(o[j], 0.f) + hfs[e][dbase + j];
        ob[j] = v;
        hos2[e][dbase + j] = v;
    }
    __syncthreads();
    uint32_t* hb = hof + (size_t)b*2048;
    for (int i = tid; i < 2048; i += 256) {
        int reg   = i & 1;
        int lane2 = (i >> 1) & 31;
        int ntile = (i >> 6) & 7;
        int ktile = (i >> 9) & 1;
        int split = i >> 10;
        int k = ktile*16 + (lane2 & 3)*2 + reg*8;
        int n = ntile*8 + (lane2 >> 2);
        float v0 = hos2[k][n], v1 = hos2[k+1][n];
        uint32_t val;
        if (split == 0) val = pack_bf2(v0, v1);
        else val = pack_bf2(bf16lo(v0), bf16lo(v1));
        hb[((split*2 + ktile)*8 + ntile)*64 + lane2*2 + reg] = val;
    }
}

// ============================ K3: dual HMMA (GEMV + hyper) + fused epilogue (R14) ============================
#define K3_ROWS 64
#define K3_BLOCKS_PER_B ((TN + K3_ROWS - 1)/K3_ROWS)   // 135
#define GSTRIDE 196
#define K3_SMEM_FLOATS (64*GSTRIDE + 384)

__global__ __launch_bounds__(256, 3) void k_fused_out(
    const float* __restrict__ x,
    const uint32_t* __restrict__ wbf,
    const uint32_t* __restrict__ hof,
    const float* __restrict__ b1, const float* __restrict__ b2,
    const float* __restrict__ ln1g, const float* __restrict__ ln1b,
    const float* __restrict__ ln2g, const float* __restrict__ ln2b,
    const float* __restrict__ assign,
    float* __restrict__ out)
{
    extern __shared__ float smem[];
    float* gsm  = smem;
    uint32_t* afrag = (uint32_t*)smem;
    uint32_t* pfrag = (uint32_t*)smem + 4096;
    float* prm  = smem + 64*GSTRIDE;

    int tid = threadIdx.x;
    int b = blockIdx.x;
    int base = blockIdx.y * K3_ROWS;
    int lane = tid & 31, warp = tid >> 5;
    const float* xb = x + (size_t)b*TN*DD;
    const float* ab = assign + (size_t)b*TN*EE;

    for (int i = tid; i < 64*32; i += 256) {
        int lr = i >> 5, kp = i & 31, k = kp*2;
        int row = base + lr;
        float2 xv = make_float2(0.f, 0.f), xp = make_float2(0.f, 0.f);
        if (row < TN) {
            xv = *(const float2*)(xb + (size_t)row*DD + k);
            if (row >= NN) xp = *(const float2*)(xb + (size_t)(row - NN)*DD + k);
        }
        float m0 = 0.5f*(xv.x + xp.x), m1 = 0.5f*(xv.y + xp.y);
        int mtile = lr >> 4, row_in = lr & 15;
        int ktile = k >> 4,  col_in = k & 15;
        int reg  = ((col_in >> 3) << 1) | (row_in >> 3);
        int fl   = (row_in & 7)*4 + ((col_in & 7) >> 1);
        int off  = ((mtile*4 + ktile)*32 + fl)*4 + reg;
        afrag[off]        = pack_bf2(m0, m1);
        afrag[2048 + off] = pack_bf2(bf16lo(m0), bf16lo(m1));
    }
    for (int i = tid; i < 64*16; i += 256) {
        int lr = i >> 4, kp = i & 15, k = kp*2;
        int row = base + lr;
        float a0 = 0.f, a1 = 0.f;
        if (row < TN) {
            float2 av = *(const float2*)(ab + (size_t)row*EE + k);
            a0 = av.x; a1 = av.y;
        }
        int mtile = lr >> 4, row_in = lr & 15;
        int ktile = k >> 4,  col_in = k & 15;
        int reg  = ((col_in >> 3) << 1) | (row_in >> 3);
        int fl   = (row_in & 7)*4 + ((col_in & 7) >> 1);
        int off  = ((mtile*2 + ktile)*32 + fl)*4 + reg;
        pfrag[off]        = pack_bf2(a0, a1);
        pfrag[1024 + off] = pack_bf2(bf16lo(a0), bf16lo(a1));
    }
    if (tid < 64) {
        prm[0*64 + tid] = b1[tid];   prm[1*64 + tid] = b2[tid];
        prm[2*64 + tid] = ln1g[tid]; prm[3*64 + tid] = ln1b[tid];
        prm[4*64 + tid] = ln2g[tid]; prm[5*64 + tid] = ln2b[tid];
    }
    __syncthreads();

    int mtile = warp & 3;
    int nh = warp >> 2;

    float d[8][4];
    #pragma unroll
    for (int j = 0; j < 8; j++)
        #pragma unroll
        for (int q = 0; q < 4; q++) d[j][q] = 0.f;
    #pragma unroll
    for (int pass = 0; pass < 3; pass++) {
        int sa = (pass == 2) ? 1 : 0;
        int sb = (pass == 1) ? 1 : 0;
        #pragma unroll
        for (int ktile = 0; ktile < 4; ktile++) {
            uint4 av = *(const uint4*)&afrag[sa*2048 + ((mtile*4 + ktile)*32 + lane)*4];
            #pragma unroll
            for (int j = 0; j < 8; j++) {
                int ntile = nh*8 + j;
                uint2 bv = __ldg((const uint2*)(wbf + (((sb*4 + ktile)*16 + ntile)*32 + lane)*2));
                mma_bf16(d[j], av.x, av.y, av.z, av.w, bv.x, bv.y);
            }
        }
    }

    const uint32_t* hofb = hof + (size_t)b*2048;
    float dY[4][4];
    #pragma unroll
    for (int j = 0; j < 4; j++)
        #pragma unroll
        for (int q = 0; q < 4; q++) dY[j][q] = 0.f;
    #pragma unroll
    for (int pass = 0; pass < 3; pass++) {
        int sa = (pass == 2) ? 1 : 0;
        int sb = (pass == 1) ? 1 : 0;
        #pragma unroll
        for (int ktile = 0; ktile < 2; ktile++) {
            uint4 av = *(const uint4*)&pfrag[sa*1024 + ((mtile*2 + ktile)*32 + lane)*4];
            #pragma unroll
            for (int j = 0; j < 4; j++) {
                int ntile = nh*4 + j;
                uint2 bv = __ldg((const uint2*)(hofb + (((sb*2 + ktile)*8 + ntile)*32 + lane)*2));
                mma_bf16(dY[j], av.x, av.y, av.z, av.w, bv.x, bv.y);
            }
        }
    }
    __syncthreads();

    {
        int r0 = mtile*16 + (lane >> 2);
        int cb = (lane & 3)*2;
        #pragma unroll
        for (int j = 0; j < 8; j++) {
            int cn = (nh*8 + j)*8 + cb;
            *(float2*)&gsm[r0*GSTRIDE + cn]     = make_float2(d[j][0], d[j][1]);
            *(float2*)&gsm[(r0+8)*GSTRIDE + cn] = make_float2(d[j][2], d[j][3]);
        }
        #pragma unroll
        for (int j = 0; j < 4; j++) {
            int cn = 128 + (nh*4 + j)*8 + cb;
            *(float2*)&gsm[r0*GSTRIDE + cn]     = make_float2(dY[j][0], dY[j][1]);
            *(float2*)&gsm[(r0+8)*GSTRIDE + cn] = make_float2(dY[j][2], dY[j][3]);
        }
    }
    __syncthreads();

    float b1a = prm[0*64 + 2*lane], b1b = prm[0*64 + 2*lane + 1];
    float b2a = prm[1*64 + 2*lane], b2b = prm[1*64 + 2*lane + 1];
    float g1w = prm[2*64 + 2*lane], g1w2 = prm[2*64 + 2*lane + 1];
    float w1b = prm[3*64 + 2*lane], w1b2 = prm[3*64 + 2*lane + 1];
    float g2w = prm[4*64 + 2*lane], g2w2 = prm[4*64 + 2*lane + 1];
    float w2b = prm[5*64 + 2*lane], w2b2 = prm[5*64 + 2*lane + 1];
    float* ob = out + (size_t)b*TN*DD;
    int lrbase = warp*8;

    #pragma unroll
    for (int rg = 0; rg < 4; rg++) {
        float f0[2], f1[2], h0[2], h1[2], s[2], s2[2], t[2], t2[2];
        #pragma unroll
        for (int j = 0; j < 2; j++) {
            int lr = lrbase + rg*2 + j;
            int row = base + lr;
            float2 xv = make_float2(0.f, 0.f);
            if (row < TN) xv = *(const float2*)(xb + (size_t)row*DD + 2*lane);
            float2 gv1 = *(const float2*)&gsm[lr*GSTRIDE + 2*lane];
            float2 gv2 = *(const float2*)&gsm[lr*GSTRIDE + 64 + 2*lane];
            float2 yv  = *(const float2*)&gsm[lr*GSTRIDE + 128 + 2*lane];
            float g1a = gv1.x + b1a, g1b = gv1.y + b1b;
            float g2a = gv2.x + b2a, g2b = gv2.y + b2b;
            f0[j] = fmaxf(g1a*g2a, 0.f) + g1a + xv.x;
            f1[j] = fmaxf(g1b*g2b, 0.f) + g1b + xv.y;
            h0[j] = fmaxf(yv.x, 0.f) + xv.x;
            h1[j] = fmaxf(yv.y, 0.f) + xv.y;
            s[j]  = f0[j] + f1[j];   s2[j] = f0[j]*f0[j] + f1[j]*f1[j];
            t[j]  = h0[j] + h1[j];   t2[j] = h0[j]*h0[j] + h1[j]*h1[j];
        }
        #pragma unroll
        for (int o = 16; o; o >>= 1) {
            #pragma unroll
            for (int j = 0; j < 2; j++) {
                s[j]  += __shfl_xor_sync(0xffffffffu, s[j],  o);
                s2[j] += __shfl_xor_sync(0xffffffffu, s2[j], o);
                t[j]  += __shfl_xor_sync(0xffffffffu, t[j],  o);
                t2[j] += __shfl_xor_sync(0xffffffffu, t2[j], o);
            }
        }
        #pragma unroll
        for (int j = 0; j < 2; j++) {
            int row = base + lrbase + rg*2 + j;
            float mu = s[j] * (1.f/64.f);
            float var = s2[j] * (1.f/64.f) - mu*mu;
            float rs = rsqrtf(var + 1e-5f);
            float o1a = (f0[j] - mu)*rs*g1w + w1b;
            float o1b = (f1[j] - mu)*rs*g1w2 + w1b2;
            float mu2 = t[j] * (1.f/64.f);
            float var2 = t2[j] * (1.f/64.f) - mu2*mu2;
            float rs2 = rsqrtf(var2 + 1e-5f);
            float o2a = (h0[j] - mu2)*rs2*g2w + w2b;
            float o2b = (h1[j] - mu2)*rs2*g2w2 + w2b2;
            if (row < TN)
                *(float2*)(ob + (size_t)row*DD + 2*lane) =
                    make_float2(0.5f*(o1a + o2a), 0.5f*(o1b + o2b));
        }
    }
}

extern "C" void kernel_launch(void* const* d_in, const int* in_sizes, int n_in,
                              void* d_out, int out_size) {
    const float* x    = (const float*)d_in[0];
    const float* W1   = (const float*)d_in[1];
    const float* b1   = (const float*)d_in[2];
    const float* W2   = (const float*)d_in[3];
    const float* b2   = (const float*)d_in[4];
    const float* ln1g = (const float*)d_in[5];
    const float* ln1b = (const float*)d_in[6];
    const float* eclf = (const float*)d_in[7];
    const float* emap = (const float*)d_in[8];
    const float* ln2g = (const float*)d_in[9];
    const float* ln2b = (const float*)d_in[10];

    float *bufA, *bufB, *assign, *hfp, *ho;
    uint32_t *wbf, *hof;
    cudaGetSymbolAddress((void**)&bufA,   g_bufA);
    cudaGetSymbolAddress((void**)&bufB,   g_bufB);
    cudaGetSymbolAddress((void**)&assign, g_assign);
    cudaGetSymbolAddress((void**)&hfp,    g_hfp);
    cudaGetSymbolAddress((void**)&ho,     g_ho);
    cudaGetSymbolAddress((void**)&wbf,    g_wbf);
    cudaGetSymbolAddress((void**)&hof,    g_hof);

    cudaFuncSetAttribute(k_fused_out, cudaFuncAttributeMaxDynamicSharedMemorySize,
                         K3_SMEM_FLOATS * (int)sizeof(float));
    cudaFuncSetAttribute(k_assign_hf, cudaFuncAttributeMaxDynamicSharedMemorySize,
                         K1_SMEM_FLOATS * (int)sizeof(float));

    k_prep_w<<<3, 256>>>(W1, W2, wbf);

    const float* cur = x;
    float* outs[3] = { bufA, bufB, (float*)d_out };

    for (int i = 0; i < 3; i++) {
        dim3 g1(BN, K1_BLOCKS_PER_B);
        k_assign_hf<<<g1, 256, K1_SMEM_FLOATS * sizeof(float)>>>(cur, eclf, assign, hfp);
        k_edge_mix<<<BN, 256>>>(hfp, emap, ho, hof);
        dim3 g3(BN, K3_BLOCKS_PER_B);
        k_fused_out<<<g3, 256, K3_SMEM_FLOATS * sizeof(float)>>>(
            cur, wbf + (size_t)i*8192, hof, b1 + i*DD, b2 + i*DD,
            ln1g + i*DD, ln1b + i*DD, ln2g, ln2b,
            assign, outs[i]);
        cur = outs[i];
    }
}

// round 16
// speedup vs baseline: 2.1530x; 1.0793x over previous
#include <cuda_runtime.h>
#include <cuda_bf16.h>
#include <cstdint>

#define BN 64
#define TT 12
#define NN 716
#define DD 64
#define EE 32
#define TN 8592            // TT*NN
#define XELEMS 35192832    // BN*TN*DD

typedef unsigned long long ull;

#define K1_STAGE 64
#define K1_STAGES 4
#define K1_CHUNK (K1_STAGE*K1_STAGES)                     // 256
#define K1_BLOCKS_PER_B ((TN + K1_CHUNK - 1)/K1_CHUNK)    // 34

__device__ float g_bufA[XELEMS];
__device__ float g_bufB[XELEMS];
__device__ float g_assign[(size_t)BN*TN*EE];
__device__ float g_hfp[(size_t)BN*K1_BLOCKS_PER_B*EE*DD];
__device__ float g_ho[BN*EE*DD];
// GEMV B fragments: [layer][split(2)][ktile(4)][ntile(16)][lane(32)][reg(2)] u32
__device__ uint32_t g_wbf[3*2*4*16*32*2];
// hyper B fragments: [b][split(2)][ktile(2)][ntile(8)][lane(32)][reg(2)] u32
__device__ uint32_t g_hof[(size_t)BN*2048];

__device__ __forceinline__ ull fma2(ull a, ull b, ull c) {
    ull d;
    asm("fma.rn.f32x2 %0, %1, %2, %3;" : "=l"(d) : "l"(a), "l"(b), "l"(c));
    return d;
}
__device__ __forceinline__ ull packdup(float m) {
    ull d;
    asm("mov.b64 %0, {%1, %1};" : "=l"(d) : "f"(m));
    return d;
}
__device__ __forceinline__ ull pack2(float lo, float hi) {
    ull d;
    asm("mov.b64 %0, {%1, %2};" : "=l"(d) : "f"(lo), "f"(hi));
    return d;
}
__device__ __forceinline__ void unpack2(ull v, float& lo, float& hi) {
    asm("mov.b64 {%0, %1}, %2;" : "=f"(lo), "=f"(hi) : "l"(v));
}
__device__ __forceinline__ void mma_bf16(float* d, uint32_t a0, uint32_t a1, uint32_t a2, uint32_t a3,
                                         uint32_t b0, uint32_t b1) {
    asm volatile("mma.sync.aligned.m16n8k16.row.col.f32.bf16.bf16.f32 "
        "{%0,%1,%2,%3}, {%4,%5,%6,%7}, {%8,%9}, {%0,%1,%2,%3};"
        : "+f"(d[0]), "+f"(d[1]), "+f"(d[2]), "+f"(d[3])
        : "r"(a0), "r"(a1), "r"(a2), "r"(a3), "r"(b0), "r"(b1));
}
__device__ __forceinline__ uint32_t pack_bf2(float a, float b) {
    __nv_bfloat162 t;
    t.x = __float2bfloat16_rn(a);
    t.y = __float2bfloat16_rn(b);
    return *(uint32_t*)&t;
}
__device__ __forceinline__ float bf16lo(float v) {
    return v - __bfloat162float(__float2bfloat16_rn(v));
}

// ============================ prep: W -> B fragments (hi/lo bf16) ============================
__global__ __launch_bounds__(256) void k_prep_w(const float* __restrict__ W1,
                                                const float* __restrict__ W2,
                                                uint32_t* __restrict__ wbf) {
    int layer = blockIdx.x;
    const float* w1 = W1 + layer*DD*DD;
    const float* w2 = W2 + layer*DD*DD;
    uint32_t* out = wbf + (size_t)layer*8192;
    for (int i = threadIdx.x; i < 4096; i += 256) {
        int lane  = i & 31;
        int ntile = (i >> 5) & 15;
        int ktile = (i >> 9) & 3;
        int split = i >> 11;
        int k0 = ktile*16 + (lane & 3)*2;
        int n  = ntile*8 + (lane >> 2);
        float v[4];
        #pragma unroll
        for (int q = 0; q < 4; q++) {
            int k = k0 + (q >> 1)*8 + (q & 1);
            v[q] = (n < 64) ? w1[k*64 + n] : w2[k*64 + (n - 64)];
        }
        uint32_t r0, r1;
        if (split == 0) {
            r0 = pack_bf2(v[0], v[1]);
            r1 = pack_bf2(v[2], v[3]);
        } else {
            r0 = pack_bf2(bf16lo(v[0]), bf16lo(v[1]));
            r1 = pack_bf2(bf16lo(v[2]), bf16lo(v[3]));
        }
        out[i*2 + 0] = r0;
        out[i*2 + 1] = r1;
    }
}

// ============================ K1: assign + hf partials (R15, verified) ============================
#define K1_SMEM_FLOATS 14336

__global__ __launch_bounds__(256, 4) void k_assign_hf(
    const float* __restrict__ x, const float* __restrict__ edge_clf,
    float* __restrict__ assign, float* __restrict__ hfp)
{
    extern __shared__ float sm1[];
    float* ecp4 = sm1;
    float* xs   = sm1 + 2048;
    float* as_  = sm1 + 6144;
    uint32_t* atf = (uint32_t*)(sm1 + 8192);
    uint32_t* bxf = (uint32_t*)(sm1 + 10240);

    int tid = threadIdx.x;
    int b = blockIdx.x;
    int r0base = blockIdx.y * K1_CHUNK;
    int lane = tid & 31, warp = tid >> 5;

    for (int i = tid; i < 64*32; i += 256) {
        int k = i >> 5, e = i & 31;
        ecp4[(k>>2)*128 + e*4 + (k&3)] = edge_clf[i];
    }

    float D0[4], D1[4];
    #pragma unroll
    for (int q = 0; q < 4; q++) { D0[q] = 0.f; D1[q] = 0.f; }
    int mtile = warp >> 2;
    int nt0 = (warp & 3) * 2;

    const float* xb = x + (size_t)b*TN*DD;

    for (int s = 0; s < K1_STAGES; s++) {
        int r0 = r0base + s*K1_STAGE;
        __syncthreads();
        #pragma unroll
        for (int p = 0; p < 4; p++) {
            int row = p*16 + (tid >> 4);
            int q = (tid & 15) * 4;
            int gr = r0 + row;
            float4 v = make_float4(0.f,0.f,0.f,0.f);
            if (gr < TN) v = *(const float4*)(xb + (size_t)gr*DD + q);
            *(float4*)(&xs[row*64 + q]) = v;
        }
        __syncthreads();
        {
            ull v2[8];
            #pragma unroll
            for (int j = 0; j < 8; j++) v2[j] = 0ull;
            #pragma unroll 4
            for (int k4 = 0; k4 < 16; k4++) {
                ulonglong2 ev = *(const ulonglong2*)&ecp4[k4*128 + lane*4];
                #pragma unroll
                for (int j = 0; j < 8; j++) {
                    ulonglong2 xv = *(const ulonglong2*)&xs[(warp*8 + j)*64 + 4*k4];
                    v2[j] = fma2(xv.x, ev.x, v2[j]);
                    v2[j] = fma2(xv.y, ev.y, v2[j]);
                }
            }
            #pragma unroll
            for (int jg = 0; jg < 2; jg++) {
                float vv[4], mm[4], ee[4], ss[4];
                #pragma unroll
                for (int j = 0; j < 4; j++) {
                    float vlo, vhi;
                    unpack2(v2[jg*4 + j], vlo, vhi);
                    vv[j] = vlo + vhi;
                    mm[j] = vv[j];
                }
                #pragma unroll
                for (int o = 16; o; o >>= 1) {
                    #pragma unroll
                    for (int j = 0; j < 4; j++)
                        mm[j] = fmaxf(mm[j], __shfl_xor_sync(0xffffffffu, mm[j], o));
                }
                #pragma unroll
                for (int j = 0; j < 4; j++) { ee[j] = __expf(vv[j] - mm[j]); ss[j] = ee[j]; }
                #pragma unroll
                for (int o = 16; o; o >>= 1) {
                    #pragma unroll
                    for (int j = 0; j < 4; j++)
                        ss[j] += __shfl_xor_sync(0xffffffffu, ss[j], o);
                }
                #pragma unroll
                for (int j = 0; j < 4; j++) {
                    int r = warp*8 + jg*4 + j;
                    int gr = r0 + r;
                    float p = ee[j] / ss[j];
                    bool valid = (gr < TN);
                    as_[r*32 + lane] = valid ? p : 0.f;
                    if (valid) assign[((size_t)b*TN + gr)*EE + lane] = p;
                }
            }
        }
        __syncthreads();
        {
            int fl = tid & 31, kt = (tid >> 5) & 3, mt = tid >> 7;
            int e0 = mt*16 + (fl >> 2);
            int e1 = e0 + 8;
            int rb = kt*16 + (fl & 3)*2;
            float a00 = as_[rb*32 + e0],     a01 = as_[(rb+1)*32 + e0];
            float a10 = as_[rb*32 + e1],     a11 = as_[(rb+1)*32 + e1];
            float a02 = as_[(rb+8)*32 + e0], a03 = as_[(rb+9)*32 + e0];
            float a12 = as_[(rb+8)*32 + e1], a13 = as_[(rb+9)*32 + e1];
            uint4 hi, lo;
            hi.x = pack_bf2(a00, a01); lo.x = pack_bf2(bf16lo(a00), bf16lo(a01));
            hi.y = pack_bf2(a10, a11); lo.y = pack_bf2(bf16lo(a10), bf16lo(a11));
            hi.z = pack_bf2(a02, a03); lo.z = pack_bf2(bf16lo(a02), bf16lo(a03));
            hi.w = pack_bf2(a12, a13); lo.w = pack_bf2(bf16lo(a12), bf16lo(a13));
            int off = ((mt*4 + kt)*32 + fl)*4;
            *(uint4*)&atf[off]        = hi;
            *(uint4*)&atf[1024 + off] = lo;
        }
        #pragma unroll
        for (int ii = 0; ii < 4; ii++) {
            int slot = tid + ii*256;
            int ln2 = slot & 31, ntl = (slot >> 5) & 7, kt = slot >> 8;
            int n = ntl*8 + (ln2 >> 2);
            int k0 = kt*16 + (ln2 & 3)*2;
            float v0 = xs[k0*64 + n],     v1 = xs[(k0+1)*64 + n];
            float v2 = xs[(k0+8)*64 + n], v3 = xs[(k0+9)*64 + n];
            int off = ((kt*8 + ntl)*32 + ln2)*2;
            bxf[off]     = pack_bf2(v0, v1);
            bxf[off + 1] = pack_bf2(v2, v3);
            bxf[2048 + off]     = pack_bf2(bf16lo(v0), bf16lo(v1));
            bxf[2048 + off + 1] = pack_bf2(bf16lo(v2), bf16lo(v3));
        }
        __syncthreads();
        // MMA with load-once reorder
        #pragma unroll
        for (int kt = 0; kt < 4; kt++) {
            uint4 ah = *(const uint4*)&atf[((mtile*4 + kt)*32 + lane)*4];
            uint4 al = *(const uint4*)&atf[1024 + ((mtile*4 + kt)*32 + lane)*4];
            uint2 bh0 = *(const uint2*)&bxf[((kt*8 + nt0)*32 + lane)*2];
            uint2 bl0 = *(const uint2*)&bxf[2048 + ((kt*8 + nt0)*32 + lane)*2];
            uint2 bh1 = *(const uint2*)&bxf[((kt*8 + nt0 + 1)*32 + lane)*2];
            uint2 bl1 = *(const uint2*)&bxf[2048 + ((kt*8 + nt0 + 1)*32 + lane)*2];
            mma_bf16(D0, ah.x, ah.y, ah.z, ah.w, bh0.x, bh0.y);
            mma_bf16(D0, ah.x, ah.y, ah.z, ah.w, bl0.x, bl0.y);
            mma_bf16(D0, al.x, al.y, al.z, al.w, bh0.x, bh0.y);
            mma_bf16(D1, ah.x, ah.y, ah.z, ah.w, bh1.x, bh1.y);
            mma_bf16(D1, ah.x, ah.y, ah.z, ah.w, bl1.x, bl1.y);
            mma_bf16(D1, al.x, al.y, al.z, al.w, bh1.x, bh1.y);
        }
    }

    float* hp = hfp + ((size_t)b*K1_BLOCKS_PER_B + blockIdx.y)*(EE*DD);
    int e0 = mtile*16 + (lane >> 2);
    int d0 = nt0*8 + (lane & 3)*2;
    *(float2*)(hp + e0*64 + d0)         = make_float2(D0[0], D0[1]);
    *(float2*)(hp + (e0+8)*64 + d0)     = make_float2(D0[2], D0[3]);
    *(float2*)(hp + e0*64 + d0 + 8)     = make_float2(D1[0], D1[1]);
    *(float2*)(hp + (e0+8)*64 + d0 + 8) = make_float2(D1[2], D1[3]);
}

// ============================ K2: reduce + edge mix + emit ho fragments ============================
__global__ __launch_bounds__(256) void k_edge_mix(
    const float* __restrict__ hfp, const float* __restrict__ edge_map,
    float* __restrict__ ho, uint32_t* __restrict__ hof)
{
    __shared__ float hfs[32][64];
    __shared__ float em[32][32];
    __shared__ float hos2[32][64];
    int tid = threadIdx.x;
    int b = blockIdx.x;
    float4 s0 = make_float4(0.f,0.f,0.f,0.f), s1 = make_float4(0.f,0.f,0.f,0.f);
    const float* pb = hfp + (size_t)b*K1_BLOCKS_PER_B*(EE*DD) + tid*8;
    #pragma unroll 2
    for (int c = 0; c < K1_BLOCKS_PER_B; c++) {
        float4 a0 = *(const float4*)(pb + (size_t)c*(EE*DD));
        float4 a1 = *(const float4*)(pb + (size_t)c*(EE*DD) + 4);
        s0.x += a0.x; s0.y += a0.y; s0.z += a0.z; s0.w += a0.w;
        s1.x += a1.x; s1.y += a1.y; s1.z += a1.z; s1.w += a1.w;
    }
    int e = tid >> 3, dbase = (tid & 7) * 8;
    *(float4*)&hfs[e][dbase]     = s0;
    *(float4*)&hfs[e][dbase + 4] = s1;
    for (int i = tid; i < 1024; i += 256) em[i>>5][i&31] = edge_map[i];
    __syncthreads();
    float o[8];
    #pragma unroll
    for (int j = 0; j < 8; j++) o[j] = 0.f;
    #pragma unroll
    for (int f = 0; f < 32; f++) {
        float w = em[e][f];
        #pragma unroll
        for (int j = 0; j < 8; j++) o[j] = fmaf(w, hfs[f][dbase + j], o[j]);
    }
    float* ob = ho + b*EE*DD + e*DD + dbase;
    #pragma unroll
    for (int j = 0; j < 8; j++) {
        float v = fmaxf(o[j], 0.f) + hfs[e][dbase + j];
        ob[j] = v;
        hos2[e][dbase + j] = v;
    }
    __syncthreads();
    uint32_t* hb = hof + (size_t)b*2048;
    for (int i = tid; i < 2048; i += 256) {
        int reg   = i & 1;
        int lane2 = (i >> 1) & 31;
        int ntile = (i >> 6) & 7;
        int ktile = (i >> 9) & 1;
        int split = i >> 10;
        int k = ktile*16 + (lane2 & 3)*2 + reg*8;
        int n = ntile*8 + (lane2 >> 2);
        float v0 = hos2[k][n], v1 = hos2[k+1][n];
        uint32_t val;
        if (split == 0) val = pack_bf2(v0, v1);
        else val = pack_bf2(bf16lo(v0), bf16lo(v1));
        hb[((split*2 + ktile)*8 + ntile)*64 + lane2*2 + reg] = val;
    }
}

// ============================ K3: dual HMMA, de-aliased smem, 4 blocks/SM ============================
#define K3_ROWS 64
#define K3_BLOCKS_PER_B ((TN + K3_ROWS - 1)/K3_ROWS)   // 135
// smem floats: Dsm[64*128]=8192 | Ysm[64*64]=4096 | prm 384  -> 12672 (50.7KB)
// staging aliases: afrag u32[0..4095], pfrag u32[4096..6143] (inside Dsm region)
#define K3_SMEM_FLOATS (8192 + 4096 + 384)

__global__ __launch_bounds__(256, 4) void k_fused_out(
    const float* __restrict__ x,
    const uint32_t* __restrict__ wbf,
    const uint32_t* __restrict__ hof,
    const float* __restrict__ b1, const float* __restrict__ b2,
    const float* __restrict__ ln1g, const float* __restrict__ ln1b,
    const float* __restrict__ ln2g, const float* __restrict__ ln2b,
    const float* __restrict__ assign,
    float* __restrict__ out)
{
    extern __shared__ float smem[];
    float* Dsm = smem;                         // [64][128]
    float* Ysm = smem + 8192;                  // [64][64]
    float* prm = smem + 12288;                 // [6][64]
    uint32_t* afrag = (uint32_t*)smem;         // hi [0..2047], lo [2048..4095]
    uint32_t* pfrag = (uint32_t*)smem + 4096;  // hi [0..1023], lo [1024..2047]

    int tid = threadIdx.x;
    int b = blockIdx.x;
    int base = blockIdx.y * K3_ROWS;
    int lane = tid & 31, warp = tid >> 5;
    const float* xb = x + (size_t)b*TN*DD;
    const float* ab = assign + (size_t)b*TN*EE;

    // ---- stage xm A-fragments (hi/lo) ----
    for (int i = tid; i < 64*32; i += 256) {
        int lr = i >> 5, kp = i & 31, k = kp*2;
        int row = base + lr;
        float2 xv = make_float2(0.f, 0.f), xp = make_float2(0.f, 0.f);
        if (row < TN) {
            xv = *(const float2*)(xb + (size_t)row*DD + k);
            if (row >= NN) xp = *(const float2*)(xb + (size_t)(row - NN)*DD + k);
        }
        float m0 = 0.5f*(xv.x + xp.x), m1 = 0.5f*(xv.y + xp.y);
        int mtile = lr >> 4, row_in = lr & 15;
        int ktile = k >> 4,  col_in = k & 15;
        int reg  = ((col_in >> 3) << 1) | (row_in >> 3);
        int fl   = (row_in & 7)*4 + ((col_in & 7) >> 1);
        int off  = ((mtile*4 + ktile)*32 + fl)*4 + reg;
        afrag[off]        = pack_bf2(m0, m1);
        afrag[2048 + off] = pack_bf2(bf16lo(m0), bf16lo(m1));
    }
    // ---- stage assign A-fragments (hi/lo), K=32 ----
    for (int i = tid; i < 64*16; i += 256) {
        int lr = i >> 4, kp = i & 15, k = kp*2;
        int row = base + lr;
        float a0 = 0.f, a1 = 0.f;
        if (row < TN) {
            float2 av = *(const float2*)(ab + (size_t)row*EE + k);
            a0 = av.x; a1 = av.y;
        }
        int mtile = lr >> 4, row_in = lr & 15;
        int ktile = k >> 4,  col_in = k & 15;
        int reg  = ((col_in >> 3) << 1) | (row_in >> 3);
        int fl   = (row_in & 7)*4 + ((col_in & 7) >> 1);
        int off  = ((mtile*2 + ktile)*32 + fl)*4 + reg;
        pfrag[off]        = pack_bf2(a0, a1);
        pfrag[1024 + off] = pack_bf2(bf16lo(a0), bf16lo(a1));
    }
    if (tid < 64) {
        prm[0*64 + tid] = b1[tid];   prm[1*64 + tid] = b2[tid];
        prm[2*64 + tid] = ln1g[tid]; prm[3*64 + tid] = ln1b[tid];
        prm[4*64 + tid] = ln2g[tid]; prm[5*64 + tid] = ln2b[tid];
    }
    __syncthreads();

    int mtile = warp & 3;
    int nh = warp >> 2;

    // ---- hyper MMA FIRST: Y = P@Ho (3-term split), store to Ysm immediately ----
    {
        const uint32_t* hofb = hof + (size_t)b*2048;
        float dY[4][4];
        #pragma unroll
        for (int j = 0; j < 4; j++)
            #pragma unroll
            for (int q = 0; q < 4; q++) dY[j][q] = 0.f;
        #pragma unroll
        for (int kt = 0; kt < 2; kt++) {
            uint4 ph = *(const uint4*)&pfrag[((mtile*2 + kt)*32 + lane)*4];
            uint4 pl = *(const uint4*)&pfrag[1024 + ((mtile*2 + kt)*32 + lane)*4];
            #pragma unroll
            for (int j = 0; j < 4; j++) {
                int ntile = nh*4 + j;
                uint2 bh = __ldg((const uint2*)(hofb + ((kt*8 + ntile)*32 + lane)*2));
                uint2 bl = __ldg((const uint2*)(hofb + ((( 2 + kt)*8 + ntile)*32 + lane)*2));
                mma_bf16(dY[j], ph.x, ph.y, ph.z, ph.w, bh.x, bh.y);
                mma_bf16(dY[j], ph.x, ph.y, ph.z, ph.w, bl.x, bl.y);
                mma_bf16(dY[j], pl.x, pl.y, pl.z, pl.w, bh.x, bh.y);
            }
        }
        // store Y (Ysm disjoint from afrag/pfrag -> no sync needed)
        int r0 = mtile*16 + (lane >> 2);
        int cb = (lane & 3)*2;
        #pragma unroll
        for (int j = 0; j < 4; j++) {
            int cn = (nh*4 + j)*8 + cb;
            *(float2*)&Ysm[r0*64 + cn]     = make_float2(dY[j][0], dY[j][1]);
            *(float2*)&Ysm[(r0+8)*64 + cn] = make_float2(dY[j][2], dY[j][3]);
        }
    }

    // ---- GEMV MMA: D = Xm@W (3-term split), load-once B ----
    float d[8][4];
    #pragma unroll
    for (int j = 0; j < 8; j++)
        #pragma unroll
        for (int q = 0; q < 4; q++) d[j][q] = 0.f;
    #pragma unroll
    for (int kt = 0; kt < 4; kt++) {
        uint4 ah = *(const uint4*)&afrag[((mtile*4 + kt)*32 + lane)*4];
        uint4 al = *(const uint4*)&afrag[2048 + ((mtile*4 + kt)*32 + lane)*4];
        #pragma unroll
        for (int j = 0; j < 8; j++) {
            int ntile = nh*8 + j;
            uint2 bh = __ldg((const uint2*)(wbf + ((kt*16 + ntile)*32 + lane)*2));
            uint2 bl = __ldg((const uint2*)(wbf + (((4 + kt)*16 + ntile)*32 + lane)*2));
            mma_bf16(d[j], ah.x, ah.y, ah.z, ah.w, bh.x, bh.y);
            mma_bf16(d[j], ah.x, ah.y, ah.z, ah.w, bl.x, bl.y);
            mma_bf16(d[j], al.x, al.y, al.z, al.w, bh.x, bh.y);
        }
    }
    __syncthreads();   // all frag reads done; Dsm region reusable

    {
        int r0 = mtile*16 + (lane >> 2);
        int cb = (lane & 3)*2;
        #pragma unroll
        for (int j = 0; j < 8; j++) {
            int cn = (nh*8 + j)*8 + cb;
            *(float2*)&Dsm[r0*128 + cn]     = make_float2(d[j][0], d[j][1]);
            *(float2*)&Dsm[(r0+8)*128 + cn] = make_float2(d[j][2], d[j][3]);
        }
    }
    __syncthreads();

    // ---- epilogue: warp -> rows warp*8..+7 ----
    float b1a = prm[0*64 + 2*lane], b1b = prm[0*64 + 2*lane + 1];
    float b2a = prm[1*64 + 2*lane], b2b = prm[1*64 + 2*lane + 1];
    float g1w = prm[2*64 + 2*lane], g1w2 = prm[2*64 + 2*lane + 1];
    float w1b = prm[3*64 + 2*lane], w1b2 = prm[3*64 + 2*lane + 1];
    float g2w = prm[4*64 + 2*lane], g2w2 = prm[4*64 + 2*lane + 1];
    float w2b = prm[5*64 + 2*lane], w2b2 = prm[5*64 + 2*lane + 1];
    float* ob = out + (size_t)b*TN*DD;
    int lrbase = warp*8;

    #pragma unroll
    for (int rg = 0; rg < 4; rg++) {
        float f0[2], f1[2], h0[2], h1[2], s[2], s2[2], t[2], t2[2];
        #pragma unroll
        for (int j = 0; j < 2; j++) {
            int lr = lrbase + rg*2 + j;
            int row = base + lr;
            float2 xv = make_float2(0.f, 0.f);
            if (row < TN) xv = *(const float2*)(xb + (size_t)row*DD + 2*lane);
            float2 gv1 = *(const float2*)&Dsm[lr*128 + 2*lane];
            float2 gv2 = *(const float2*)&Dsm[lr*128 + 64 + 2*lane];
            float2 yv  = *(const float2*)&Ysm[lr*64 + 2*lane];
            float g1a = gv1.x + b1a, g1b = gv1.y + b1b;
            float g2a = gv2.x + b2a, g2b = gv2.y + b2b;
            f0[j] = fmaxf(g1a*g2a, 0.f) + g1a + xv.x;
            f1[j] = fmaxf(g1b*g2b, 0.f) + g1b + xv.y;
            h0[j] = fmaxf(yv.x, 0.f) + xv.x;
            h1[j] = fmaxf(yv.y, 0.f) + xv.y;
            s[j]  = f0[j] + f1[j];   s2[j] = f0[j]*f0[j] + f1[j]*f1[j];
            t[j]  = h0[j] + h1[j];   t2[j] = h0[j]*h0[j] + h1[j]*h1[j];
        }
        #pragma unroll
        for (int o = 16; o; o >>= 1) {
            #pragma unroll
            for (int j = 0; j < 2; j++) {
                s[j]  += __shfl_xor_sync(0xffffffffu, s[j],  o);
                s2[j] += __shfl_xor_sync(0xffffffffu, s2[j], o);
                t[j]  += __shfl_xor_sync(0xffffffffu, t[j],  o);
                t2[j] += __shfl_xor_sync(0xffffffffu, t2[j], o);
            }
        }
        #pragma unroll
        for (int j = 0; j < 2; j++) {
            int row = base + lrbase + rg*2 + j;
            float mu = s[j] * (1.f/64.f);
            float var = s2[j] * (1.f/64.f) - mu*mu;
            float rs = rsqrtf(var + 1e-5f);
            float o1a = (f0[j] - mu)*rs*g1w + w1b;
            float o1b = (f1[j] - mu)*rs*g1w2 + w1b2;
            float mu2 = t[j] * (1.f/64.f);
            float var2 = t2[j] * (1.f/64.f) - mu2*mu2;
            float rs2 = rsqrtf(var2 + 1e-5f);
            float o2a = (h0[j] - mu2)*rs2*g2w + w2b;
            float o2b = (h1[j] - mu2)*rs2*g2w2 + w2b2;
            if (row < TN)
                *(float2*)(ob + (size_t)row*DD + 2*lane) =
                    make_float2(0.5f*(o1a + o2a), 0.5f*(o1b + o2b));
        }
    }
}

extern "C" void kernel_launch(void* const* d_in, const int* in_sizes, int n_in,
                              void* d_out, int out_size) {
    const float* x    = (const float*)d_in[0];
    const float* W1   = (const float*)d_in[1];
    const float* b1   = (const float*)d_in[2];
    const float* W2   = (const float*)d_in[3];
    const float* b2   = (const float*)d_in[4];
    const float* ln1g = (const float*)d_in[5];
    const float* ln1b = (const float*)d_in[6];
    const float* eclf = (const float*)d_in[7];
    const float* emap = (const float*)d_in[8];
    const float* ln2g = (const float*)d_in[9];
    const float* ln2b = (const float*)d_in[10];

    float *bufA, *bufB, *assign, *hfp, *ho;
    uint32_t *wbf, *hof;
    cudaGetSymbolAddress((void**)&bufA,   g_bufA);
    cudaGetSymbolAddress((void**)&bufB,   g_bufB);
    cudaGetSymbolAddress((void**)&assign, g_assign);
    cudaGetSymbolAddress((void**)&hfp,    g_hfp);
    cudaGetSymbolAddress((void**)&ho,     g_ho);
    cudaGetSymbolAddress((void**)&wbf,    g_wbf);
    cudaGetSymbolAddress((void**)&hof,    g_hof);

    cudaFuncSetAttribute(k_fused_out, cudaFuncAttributeMaxDynamicSharedMemorySize,
                         K3_SMEM_FLOATS * (int)sizeof(float));
    cudaFuncSetAttribute(k_assign_hf, cudaFuncAttributeMaxDynamicSharedMemorySize,
                         K1_SMEM_FLOATS * (int)sizeof(float));

    k_prep_w<<<3, 256>>>(W1, W2, wbf);

    const float* cur = x;
    float* outs[3] = { bufA, bufB, (float*)d_out };

    for (int i = 0; i < 3; i++) {
        dim3 g1(BN, K1_BLOCKS_PER_B);
        k_assign_hf<<<g1, 256, K1_SMEM_FLOATS * sizeof(float)>>>(cur, eclf, assign, hfp);
        k_edge_mix<<<BN, 256>>>(hfp, emap, ho, hof);
        dim3 g3(BN, K3_BLOCKS_PER_B);
        k_fused_out<<<g3, 256, K3_SMEM_FLOATS * sizeof(float)>>>(
            cur, wbf + (size_t)i*8192, hof, b1 + i*DD, b2 + i*DD,
            ln1g + i*DD, ln1b + i*DD, ln2g, ln2b,
            assign, outs[i]);
        cur = outs[i];
    }
}

// round 17
// speedup vs baseline: 2.3061x; 1.0711x over previous
#include <cuda_runtime.h>
#include <cuda_bf16.h>
#include <cstdint>

#define BN 64
#define TT 12
#define NN 716
#define DD 64
#define EE 32
#define TN 8592            // TT*NN
#define XELEMS 35192832    // BN*TN*DD

typedef unsigned long long ull;

#define K1_STAGE 64
#define K1_STAGES 4
#define K1_CHUNK (K1_STAGE*K1_STAGES)                     // 256
#define K1_BLOCKS_PER_B ((TN + K1_CHUNK - 1)/K1_CHUNK)    // 34

__device__ float g_bufA[XELEMS];
__device__ float g_bufB[XELEMS];
__device__ float g_assign[(size_t)BN*TN*EE];
__device__ float g_hfp[(size_t)BN*K1_BLOCKS_PER_B*EE*DD];
__device__ float g_ho[BN*EE*DD];
// GEMV B fragments: [layer][split(2)][ktile(4)][ntile(16)][lane(32)][reg(2)] u32
__device__ uint32_t g_wbf[3*2*4*16*32*2];
// hyper B fragments: [b][split(2)][ktile(2)][ntile(8)][lane(32)][reg(2)] u32
__device__ uint32_t g_hof[(size_t)BN*2048];
// edge_clf B fragments: [split(2)][ktile(4)][ntile(4)][lane(32)][reg(2)] u32
__device__ uint32_t g_ecf[2048];

__device__ __forceinline__ void mma_bf16(float* d, uint32_t a0, uint32_t a1, uint32_t a2, uint32_t a3,
                                         uint32_t b0, uint32_t b1) {
    asm volatile("mma.sync.aligned.m16n8k16.row.col.f32.bf16.bf16.f32 "
        "{%0,%1,%2,%3}, {%4,%5,%6,%7}, {%8,%9}, {%0,%1,%2,%3};"
        : "+f"(d[0]), "+f"(d[1]), "+f"(d[2]), "+f"(d[3])
        : "r"(a0), "r"(a1), "r"(a2), "r"(a3), "r"(b0), "r"(b1));
}
__device__ __forceinline__ uint32_t pack_bf2(float a, float b) {
    __nv_bfloat162 t;
    t.x = __float2bfloat16_rn(a);
    t.y = __float2bfloat16_rn(b);
    return *(uint32_t*)&t;
}
__device__ __forceinline__ float bf16lo(float v) {
    return v - __bfloat162float(__float2bfloat16_rn(v));
}

// ============================ prep: W -> B fragments (hi/lo bf16) ============================
__global__ __launch_bounds__(256) void k_prep_w(const float* __restrict__ W1,
                                                const float* __restrict__ W2,
                                                uint32_t* __restrict__ wbf) {
    int layer = blockIdx.x;
    const float* w1 = W1 + layer*DD*DD;
    const float* w2 = W2 + layer*DD*DD;
    uint32_t* out = wbf + (size_t)layer*8192;
    for (int i = threadIdx.x; i < 4096; i += 256) {
        int lane  = i & 31;
        int ntile = (i >> 5) & 15;
        int ktile = (i >> 9) & 3;
        int split = i >> 11;
        int k0 = ktile*16 + (lane & 3)*2;
        int n  = ntile*8 + (lane >> 2);
        float v[4];
        #pragma unroll
        for (int q = 0; q < 4; q++) {
            int k = k0 + (q >> 1)*8 + (q & 1);
            v[q] = (n < 64) ? w1[k*64 + n] : w2[k*64 + (n - 64)];
        }
        uint32_t r0, r1;
        if (split == 0) {
            r0 = pack_bf2(v[0], v[1]);
            r1 = pack_bf2(v[2], v[3]);
        } else {
            r0 = pack_bf2(bf16lo(v[0]), bf16lo(v[1]));
            r1 = pack_bf2(bf16lo(v[2]), bf16lo(v[3]));
        }
        out[i*2 + 0] = r0;
        out[i*2 + 1] = r1;
    }
}

// prep edge_clf B fragments: logits = xs[64x64] @ ec[64x32]
__global__ __launch_bounds__(256) void k_prep_ec(const float* __restrict__ ec,
                                                 uint32_t* __restrict__ ecf) {
    for (int i = threadIdx.x; i < 2048; i += 256) {
        int reg   = i & 1;
        int lane  = (i >> 1) & 31;
        int ntile = (i >> 6) & 3;
        int kt    = (i >> 8) & 3;
        int split = i >> 10;
        int k = kt*16 + (lane & 3)*2 + reg*8;
        int n = ntile*8 + (lane >> 2);
        float v0 = ec[k*EE + n], v1 = ec[(k+1)*EE + n];
        uint32_t val = (split == 0) ? pack_bf2(v0, v1)
                                    : pack_bf2(bf16lo(v0), bf16lo(v1));
        ecf[((split*4 + kt)*4 + ntile)*64 + lane*2 + reg] = val;
    }
}

// ============================ K1: logits + softmax + rank-1, all HMMA ============================
// dyn smem floats: xs[4096] | frag u32[4096] (axf, then bxf) | as_[2048] | atf u32[2048] = 49152 B
#define K1_SMEM_FLOATS 12288

__global__ __launch_bounds__(256, 4) void k_assign_hf(
    const float* __restrict__ x, const uint32_t* __restrict__ ecf,
    float* __restrict__ assign, float* __restrict__ hfp)
{
    extern __shared__ float sm1[];
    float* xs = sm1;                            // [64][64]
    uint32_t* frg = (uint32_t*)(sm1 + 4096);    // axf: hi[0..2047] lo[2048..4095]; later bxf
    float* as_ = sm1 + 8192;                    // [64][32]
    uint32_t* atf = (uint32_t*)(sm1 + 10240);   // hi[0..1023] lo[1024..2047]

    int tid = threadIdx.x;
    int b = blockIdx.x;
    int r0base = blockIdx.y * K1_CHUNK;
    int lane = tid & 31, warp = tid >> 5;

    float D0[4], D1[4];
    #pragma unroll
    for (int q = 0; q < 4; q++) { D0[q] = 0.f; D1[q] = 0.f; }
    int mtile = warp >> 2;        // rank-1 output e-tile
    int nt0 = (warp & 3) * 2;     // rank-1 output d-tiles

    const float* xb = x + (size_t)b*TN*DD;

    for (int s = 0; s < K1_STAGES; s++) {
        int r0 = r0base + s*K1_STAGE;
        __syncthreads();
        // ---- load xs (zero-padded) ----
        #pragma unroll
        for (int p = 0; p < 4; p++) {
            int row = p*16 + (tid >> 4);
            int q = (tid & 15) * 4;
            int gr = r0 + row;
            float4 v = make_float4(0.f,0.f,0.f,0.f);
            if (gr < TN) v = *(const float4*)(xb + (size_t)gr*DD + q);
            *(float4*)(&xs[row*64 + q]) = v;
        }
        __syncthreads();
        // ---- build xs A-fragments (axf) ----
        for (int i = tid; i < 2048; i += 256) {
            int lr = i >> 5, kp = i & 31, k = kp*2;
            float m0 = xs[lr*64 + k], m1 = xs[lr*64 + k + 1];
            int mt = lr >> 4, row_in = lr & 15;
            int kt = k >> 4,  col_in = k & 15;
            int reg = ((col_in >> 3) << 1) | (row_in >> 3);
            int fl  = (row_in & 7)*4 + ((col_in & 7) >> 1);
            int off = ((mt*4 + kt)*32 + fl)*4 + reg;
            frg[off]        = pack_bf2(m0, m1);
            frg[2048 + off] = pack_bf2(bf16lo(m0), bf16lo(m1));
        }
        __syncthreads();
        // ---- logits MMA: warp handles pairs w*2, w*2+1 of (mtile4 x ntile4) ----
        #pragma unroll
        for (int i = 0; i < 2; i++) {
            int pr = warp*2 + i;
            int mt = pr >> 2, nt = pr & 3;
            float DL[4] = {0.f, 0.f, 0.f, 0.f};
            #pragma unroll
            for (int kt = 0; kt < 4; kt++) {
                uint4 ah = *(const uint4*)&frg[((mt*4 + kt)*32 + lane)*4];
                uint4 al = *(const uint4*)&frg[2048 + ((mt*4 + kt)*32 + lane)*4];
                uint2 bh = __ldg((const uint2*)(ecf + ((kt*4 + nt)*64 + lane*2)));
                uint2 bl = __ldg((const uint2*)(ecf + (((4 + kt)*4 + nt)*64 + lane*2)));
                mma_bf16(DL, ah.x, ah.y, ah.z, ah.w, bh.x, bh.y);
                mma_bf16(DL, ah.x, ah.y, ah.z, ah.w, bl.x, bl.y);
                mma_bf16(DL, al.x, al.y, al.z, al.w, bh.x, bh.y);
            }
            int rr = mt*16 + (lane >> 2);
            int cn = nt*8 + (lane & 3)*2;
            *(float2*)&as_[rr*32 + cn]     = make_float2(DL[0], DL[1]);
            *(float2*)&as_[(rr+8)*32 + cn] = make_float2(DL[2], DL[3]);
        }
        __syncthreads();
        // ---- softmax in place: warp -> rows warp*8..+7, lane = e (interleaved chains) ----
        #pragma unroll
        for (int jg = 0; jg < 2; jg++) {
            float vv[4], mm[4], ee[4], ss[4];
            #pragma unroll
            for (int j = 0; j < 4; j++) {
                int r = warp*8 + jg*4 + j;
                vv[j] = as_[r*32 + lane];
                mm[j] = vv[j];
            }
            #pragma unroll
            for (int o = 16; o; o >>= 1) {
                #pragma unroll
                for (int j = 0; j < 4; j++)
                    mm[j] = fmaxf(mm[j], __shfl_xor_sync(0xffffffffu, mm[j], o));
            }
            #pragma unroll
            for (int j = 0; j < 4; j++) { ee[j] = __expf(vv[j] - mm[j]); ss[j] = ee[j]; }
            #pragma unroll
            for (int o = 16; o; o >>= 1) {
                #pragma unroll
                for (int j = 0; j < 4; j++)
                    ss[j] += __shfl_xor_sync(0xffffffffu, ss[j], o);
            }
            #pragma unroll
            for (int j = 0; j < 4; j++) {
                int r = warp*8 + jg*4 + j;
                int gr = r0 + r;
                float p = ee[j] / ss[j];
                bool valid = (gr < TN);
                as_[r*32 + lane] = valid ? p : 0.f;
                if (valid) assign[((size_t)b*TN + gr)*EE + lane] = p;
            }
        }
        __syncthreads();
        // ---- stage atf (as_ A^T frags for rank-1) ----
        {
            int fl = tid & 31, kt = (tid >> 5) & 3, mt = tid >> 7;
            int e0 = mt*16 + (fl >> 2);
            int e1 = e0 + 8;
            int rb = kt*16 + (fl & 3)*2;
            float a00 = as_[rb*32 + e0],     a01 = as_[(rb+1)*32 + e0];
            float a10 = as_[rb*32 + e1],     a11 = as_[(rb+1)*32 + e1];
            float a02 = as_[(rb+8)*32 + e0], a03 = as_[(rb+9)*32 + e0];
            float a12 = as_[(rb+8)*32 + e1], a13 = as_[(rb+9)*32 + e1];
            uint4 hi, lo;
            hi.x = pack_bf2(a00, a01); lo.x = pack_bf2(bf16lo(a00), bf16lo(a01));
            hi.y = pack_bf2(a10, a11); lo.y = pack_bf2(bf16lo(a10), bf16lo(a11));
            hi.z = pack_bf2(a02, a03); lo.z = pack_bf2(bf16lo(a02), bf16lo(a03));
            hi.w = pack_bf2(a12, a13); lo.w = pack_bf2(bf16lo(a12), bf16lo(a13));
            int off = ((mt*4 + kt)*32 + fl)*4;
            *(uint4*)&atf[off]        = hi;
            *(uint4*)&atf[1024 + off] = lo;
        }
        // ---- stage bxf (xs B frags) over the dead axf region ----
        #pragma unroll
        for (int ii = 0; ii < 4; ii++) {
            int slot = tid + ii*256;
            int ln2 = slot & 31, ntl = (slot >> 5) & 7, kt = slot >> 8;
            int n = ntl*8 + (ln2 >> 2);
            int k0 = kt*16 + (ln2 & 3)*2;
            float v0 = xs[k0*64 + n],     v1 = xs[(k0+1)*64 + n];
            float v2 = xs[(k0+8)*64 + n], v3 = xs[(k0+9)*64 + n];
            int off = ((kt*8 + ntl)*32 + ln2)*2;
            frg[off]     = pack_bf2(v0, v1);
            frg[off + 1] = pack_bf2(v2, v3);
            frg[2048 + off]     = pack_bf2(bf16lo(v0), bf16lo(v1));
            frg[2048 + off + 1] = pack_bf2(bf16lo(v2), bf16lo(v3));
        }
        __syncthreads();
        // ---- rank-1 MMA: hf += as^T @ xs ----
        #pragma unroll
        for (int kt = 0; kt < 4; kt++) {
            uint4 ah = *(const uint4*)&atf[((mtile*4 + kt)*32 + lane)*4];
            uint4 al = *(const uint4*)&atf[1024 + ((mtile*4 + kt)*32 + lane)*4];
            uint2 bh0 = *(const uint2*)&frg[((kt*8 + nt0)*32 + lane)*2];
            uint2 bl0 = *(const uint2*)&frg[2048 + ((kt*8 + nt0)*32 + lane)*2];
            uint2 bh1 = *(const uint2*)&frg[((kt*8 + nt0 + 1)*32 + lane)*2];
            uint2 bl1 = *(const uint2*)&frg[2048 + ((kt*8 + nt0 + 1)*32 + lane)*2];
            mma_bf16(D0, ah.x, ah.y, ah.z, ah.w, bh0.x, bh0.y);
            mma_bf16(D0, ah.x, ah.y, ah.z, ah.w, bl0.x, bl0.y);
            mma_bf16(D0, al.x, al.y, al.z, al.w, bh0.x, bh0.y);
            mma_bf16(D1, ah.x, ah.y, ah.z, ah.w, bh1.x, bh1.y);
            mma_bf16(D1, ah.x, ah.y, ah.z, ah.w, bl1.x, bl1.y);
            mma_bf16(D1, al.x, al.y, al.z, al.w, bh1.x, bh1.y);
        }
    }

    float* hp = hfp + ((size_t)b*K1_BLOCKS_PER_B + blockIdx.y)*(EE*DD);
    int e0 = mtile*16 + (lane >> 2);
    int d0 = nt0*8 + (lane & 3)*2;
    *(float2*)(hp + e0*64 + d0)         = make_float2(D0[0], D0[1]);
    *(float2*)(hp + (e0+8)*64 + d0)     = make_float2(D0[2], D0[3]);
    *(float2*)(hp + e0*64 + d0 + 8)     = make_float2(D1[0], D1[1]);
    *(float2*)(hp + (e0+8)*64 + d0 + 8) = make_float2(D1[2], D1[3]);
}

// ============================ K2: reduce + edge mix + emit ho fragments ============================
__global__ __launch_bounds__(256) void k_edge_mix(
    const float* __restrict__ hfp, const float* __restrict__ edge_map,
    float* __restrict__ ho, uint32_t* __restrict__ hof)
{
    __shared__ float hfs[32][64];
    __shared__ float em[32][32];
    __shared__ float hos2[32][64];
    int tid = threadIdx.x;
    int b = blockIdx.x;
    float4 s0 = make_float4(0.f,0.f,0.f,0.f), s1 = make_float4(0.f,0.f,0.f,0.f);
    const float* pb = hfp + (size_t)b*K1_BLOCKS_PER_B*(EE*DD) + tid*8;
    #pragma unroll 2
    for (int c = 0; c < K1_BLOCKS_PER_B; c++) {
        float4 a0 = *(const float4*)(pb + (size_t)c*(EE*DD));
        float4 a1 = *(const float4*)(pb + (size_t)c*(EE*DD) + 4);
        s0.x += a0.x; s0.y += a0.y; s0.z += a0.z; s0.w += a0.w;
        s1.x += a1.x; s1.y += a1.y; s1.z += a1.z; s1.w += a1.w;
    }
    int e = tid >> 3, dbase = (tid & 7) * 8;
    *(float4*)&hfs[e][dbase]     = s0;
    *(float4*)&hfs[e][dbase + 4] = s1;
    for (int i = tid; i < 1024; i += 256) em[i>>5][i&31] = edge_map[i];
    __syncthreads();
    float o[8];
    #pragma unroll
    for (int j = 0; j < 8; j++) o[j] = 0.f;
    #pragma unroll
    for (int f = 0; f < 32; f++) {
        float w = em[e][f];
        #pragma unroll
        for (int j = 0; j < 8; j++) o[j] = fmaf(w, hfs[f][dbase + j], o[j]);
    }
    float* ob = ho + b*EE*DD + e*DD + dbase;
    #pragma unroll
    for (int j = 0; j < 8; j++) {
        float v = fmaxf(o[j], 0.f) + hfs[e][dbase + j];
        ob[j] = v;
        hos2[e][dbase + j] = v;
    }
    __syncthreads();
    uint32_t* hb = hof + (size_t)b*2048;
    for (int i = tid; i < 2048; i += 256) {
        int reg   = i & 1;
        int lane2 = (i >> 1) & 31;
        int ntile = (i >> 6) & 7;
        int ktile = (i >> 9) & 1;
        int split = i >> 10;
        int k = ktile*16 + (lane2 & 3)*2 + reg*8;
        int n = ntile*8 + (lane2 >> 2);
        float v0 = hos2[k][n], v1 = hos2[k+1][n];
        uint32_t val;
        if (split == 0) val = pack_bf2(v0, v1);
        else val = pack_bf2(bf16lo(v0), bf16lo(v1));
        hb[((split*2 + ktile)*8 + ntile)*64 + lane2*2 + reg] = val;
    }
}

// ============================ K3: dual HMMA, de-aliased smem, 4 blocks/SM (R16) ============================
#define K3_ROWS 64
#define K3_BLOCKS_PER_B ((TN + K3_ROWS - 1)/K3_ROWS)   // 135
#define K3_SMEM_FLOATS (8192 + 4096 + 384)

__global__ __launch_bounds__(256, 4) void k_fused_out(
    const float* __restrict__ x,
    const uint32_t* __restrict__ wbf,
    const uint32_t* __restrict__ hof,
    const float* __restrict__ b1, const float* __restrict__ b2,
    const float* __restrict__ ln1g, const float* __restrict__ ln1b,
    const float* __restrict__ ln2g, const float* __restrict__ ln2b,
    const float* __restrict__ assign,
    float* __restrict__ out)
{
    extern __shared__ float smem[];
    float* Dsm = smem;
    float* Ysm = smem + 8192;
    float* prm = smem + 12288;
    uint32_t* afrag = (uint32_t*)smem;
    uint32_t* pfrag = (uint32_t*)smem + 4096;

    int tid = threadIdx.x;
    int b = blockIdx.x;
    int base = blockIdx.y * K3_ROWS;
    int lane = tid & 31, warp = tid >> 5;
    const float* xb = x + (size_t)b*TN*DD;
    const float* ab = assign + (size_t)b*TN*EE;

    for (int i = tid; i < 64*32; i += 256) {
        int lr = i >> 5, kp = i & 31, k = kp*2;
        int row = base + lr;
        float2 xv = make_float2(0.f, 0.f), xp = make_float2(0.f, 0.f);
        if (row < TN) {
            xv = *(const float2*)(xb + (size_t)row*DD + k);
            if (row >= NN) xp = *(const float2*)(xb + (size_t)(row - NN)*DD + k);
        }
        float m0 = 0.5f*(xv.x + xp.x), m1 = 0.5f*(xv.y + xp.y);
        int mtile = lr >> 4, row_in = lr & 15;
        int ktile = k >> 4,  col_in = k & 15;
        int reg  = ((col_in >> 3) << 1) | (row_in >> 3);
        int fl   = (row_in & 7)*4 + ((col_in & 7) >> 1);
        int off  = ((mtile*4 + ktile)*32 + fl)*4 + reg;
        afrag[off]        = pack_bf2(m0, m1);
        afrag[2048 + off] = pack_bf2(bf16lo(m0), bf16lo(m1));
    }
    for (int i = tid; i < 64*16; i += 256) {
        int lr = i >> 4, kp = i & 15, k = kp*2;
        int row = base + lr;
        float a0 = 0.f, a1 = 0.f;
        if (row < TN) {
            float2 av = *(const float2*)(ab + (size_t)row*EE + k);
            a0 = av.x; a1 = av.y;
        }
        int mtile = lr >> 4, row_in = lr & 15;
        int ktile = k >> 4,  col_in = k & 15;
        int reg  = ((col_in >> 3) << 1) | (row_in >> 3);
        int fl   = (row_in & 7)*4 + ((col_in & 7) >> 1);
        int off  = ((mtile*2 + ktile)*32 + fl)*4 + reg;
        pfrag[off]        = pack_bf2(a0, a1);
        pfrag[1024 + off] = pack_bf2(bf16lo(a0), bf16lo(a1));
    }
    if (tid < 64) {
        prm[0*64 + tid] = b1[tid];   prm[1*64 + tid] = b2[tid];
        prm[2*64 + tid] = ln1g[tid]; prm[3*64 + tid] = ln1b[tid];
        prm[4*64 + tid] = ln2g[tid]; prm[5*64 + tid] = ln2b[tid];
    }
    __syncthreads();

    int mtile = warp & 3;
    int nh = warp >> 2;

    {
        const uint32_t* hofb = hof + (size_t)b*2048;
        float dY[4][4];
        #pragma unroll
        for (int j = 0; j < 4; j++)
            #pragma unroll
            for (int q = 0; q < 4; q++) dY[j][q] = 0.f;
        #pragma unroll
        for (int kt = 0; kt < 2; kt++) {
            uint4 ph = *(const uint4*)&pfrag[((mtile*2 + kt)*32 + lane)*4];
            uint4 pl = *(const uint4*)&pfrag[1024 + ((mtile*2 + kt)*32 + lane)*4];
            #pragma unroll
            for (int j = 0; j < 4; j++) {
                int ntile = nh*4 + j;
                uint2 bh = __ldg((const uint2*)(hofb + ((kt*8 + ntile)*32 + lane)*2));
                uint2 bl = __ldg((const uint2*)(hofb + ((( 2 + kt)*8 + ntile)*32 + lane)*2));
                mma_bf16(dY[j], ph.x, ph.y, ph.z, ph.w, bh.x, bh.y);
                mma_bf16(dY[j], ph.x, ph.y, ph.z, ph.w, bl.x, bl.y);
                mma_bf16(dY[j], pl.x, pl.y, pl.z, pl.w, bh.x, bh.y);
            }
        }
        int r0 = mtile*16 + (lane >> 2);
        int cb = (lane & 3)*2;
        #pragma unroll
        for (int j = 0; j < 4; j++) {
            int cn = (nh*4 + j)*8 + cb;
            *(float2*)&Ysm[r0*64 + cn]     = make_float2(dY[j][0], dY[j][1]);
            *(float2*)&Ysm[(r0+8)*64 + cn] = make_float2(dY[j][2], dY[j][3]);
        }
    }

    float d[8][4];
    #pragma unroll
    for (int j = 0; j < 8; j++)
        #pragma unroll
        for (int q = 0; q < 4; q++) d[j][q] = 0.f;
    #pragma unroll
    for (int kt = 0; kt < 4; kt++) {
        uint4 ah = *(const uint4*)&afrag[((mtile*4 + kt)*32 + lane)*4];
        uint4 al = *(const uint4*)&afrag[2048 + ((mtile*4 + kt)*32 + lane)*4];
        #pragma unroll
        for (int j = 0; j < 8; j++) {
            int ntile = nh*8 + j;
            uint2 bh = __ldg((const uint2*)(wbf + ((kt*16 + ntile)*32 + lane)*2));
            uint2 bl = __ldg((const uint2*)(wbf + (((4 + kt)*16 + ntile)*32 + lane)*2));
            mma_bf16(d[j], ah.x, ah.y, ah.z, ah.w, bh.x, bh.y);
            mma_bf16(d[j], ah.x, ah.y, ah.z, ah.w, bl.x, bl.y);
            mma_bf16(d[j], al.x, al.y, al.z, al.w, bh.x, bh.y);
        }
    }
    __syncthreads();

    {
        int r0 = mtile*16 + (lane >> 2);
        int cb = (lane & 3)*2;
        #pragma unroll
        for (int j = 0; j < 8; j++) {
            int cn = (nh*8 + j)*8 + cb;
            *(float2*)&Dsm[r0*128 + cn]     = make_float2(d[j][0], d[j][1]);
            *(float2*)&Dsm[(r0+8)*128 + cn] = make_float2(d[j][2], d[j][3]);
        }
    }
    __syncthreads();

    float b1a = prm[0*64 + 2*lane], b1b = prm[0*64 + 2*lane + 1];
    float b2a = prm[1*64 + 2*lane], b2b = prm[1*64 + 2*lane + 1];
    float g1w = prm[2*64 + 2*lane], g1w2 = prm[2*64 + 2*lane + 1];
    float w1b = prm[3*64 + 2*lane], w1b2 = prm[3*64 + 2*lane + 1];
    float g2w = prm[4*64 + 2*lane], g2w2 = prm[4*64 + 2*lane + 1];
    float w2b = prm[5*64 + 2*lane], w2b2 = prm[5*64 + 2*lane + 1];
    float* ob = out + (size_t)b*TN*DD;
    int lrbase = warp*8;

    #pragma unroll
    for (int rg = 0; rg < 4; rg++) {
        float f0[2], f1[2], h0[2], h1[2], s[2], s2[2], t[2], t2[2];
        #pragma unroll
        for (int j = 0; j < 2; j++) {
            int lr = lrbase + rg*2 + j;
            int row = base + lr;
            float2 xv = make_float2(0.f, 0.f);
            if (row < TN) xv = *(const float2*)(xb + (size_t)row*DD + 2*lane);
            float2 gv1 = *(const float2*)&Dsm[lr*128 + 2*lane];
            float2 gv2 = *(const float2*)&Dsm[lr*128 + 64 + 2*lane];
            float2 yv  = *(const float2*)&Ysm[lr*64 + 2*lane];
            float g1a = gv1.x + b1a, g1b = gv1.y + b1b;
            float g2a = gv2.x + b2a, g2b = gv2.y + b2b;
            f0[j] = fmaxf(g1a*g2a, 0.f) + g1a + xv.x;
            f1[j] = fmaxf(g1b*g2b, 0.f) + g1b + xv.y;
            h0[j] = fmaxf(yv.x, 0.f) + xv.x;
            h1[j] = fmaxf(yv.y, 0.f) + xv.y;
            s[j]  = f0[j] + f1[j];   s2[j] = f0[j]*f0[j] + f1[j]*f1[j];
            t[j]  = h0[j] + h1[j];   t2[j] = h0[j]*h0[j] + h1[j]*h1[j];
        }
        #pragma unroll
        for (int o = 16; o; o >>= 1) {
            #pragma unroll
            for (int j = 0; j < 2; j++) {
                s[j]  += __shfl_xor_sync(0xffffffffu, s[j],  o);
                s2[j] += __shfl_xor_sync(0xffffffffu, s2[j], o);
                t[j]  += __shfl_xor_sync(0xffffffffu, t[j],  o);
                t2[j] += __shfl_xor_sync(0xffffffffu, t2[j], o);
            }
        }
        #pragma unroll
        for (int j = 0; j < 2; j++) {
            int row = base + lrbase + rg*2 + j;
            float mu = s[j] * (1.f/64.f);
            float var = s2[j] * (1.f/64.f) - mu*mu;
            float rs = rsqrtf(var + 1e-5f);
            float o1a = (f0[j] - mu)*rs*g1w + w1b;
            float o1b = (f1[j] - mu)*rs*g1w2 + w1b2;
            float mu2 = t[j] * (1.f/64.f);
            float var2 = t2[j] * (1.f/64.f) - mu2*mu2;
            float rs2 = rsqrtf(var2 + 1e-5f);
            float o2a = (h0[j] - mu2)*rs2*g2w + w2b;
            float o2b = (h1[j] - mu2)*rs2*g2w2 + w2b2;
            if (row < TN)
                *(float2*)(ob + (size_t)row*DD + 2*lane) =
                    make_float2(0.5f*(o1a + o2a), 0.5f*(o1b + o2b));
        }
    }
}

extern "C" void kernel_launch(void* const* d_in, const int* in_sizes, int n_in,
                              void* d_out, int out_size) {
    const float* x    = (const float*)d_in[0];
    const float* W1   = (const float*)d_in[1];
    const float* b1   = (const float*)d_in[2];
    const float* W2   = (const float*)d_in[3];
    const float* b2   = (const float*)d_in[4];
    const float* ln1g = (const float*)d_in[5];
    const float* ln1b = (const float*)d_in[6];
    const float* eclf = (const float*)d_in[7];
    const float* emap = (const float*)d_in[8];
    const float* ln2g = (const float*)d_in[9];
    const float* ln2b = (const float*)d_in[10];

    float *bufA, *bufB, *assign, *hfp, *ho;
    uint32_t *wbf, *hof, *ecf;
    cudaGetSymbolAddress((void**)&bufA,   g_bufA);
    cudaGetSymbolAddress((void**)&bufB,   g_bufB);
    cudaGetSymbolAddress((void**)&assign, g_assign);
    cudaGetSymbolAddress((void**)&hfp,    g_hfp);
    cudaGetSymbolAddress((void**)&ho,     g_ho);
    cudaGetSymbolAddress((void**)&wbf,    g_wbf);
    cudaGetSymbolAddress((void**)&hof,    g_hof);
    cudaGetSymbolAddress((void**)&ecf,    g_ecf);

    cudaFuncSetAttribute(k_fused_out, cudaFuncAttributeMaxDynamicSharedMemorySize,
                         K3_SMEM_FLOATS * (int)sizeof(float));
    cudaFuncSetAttribute(k_assign_hf, cudaFuncAttributeMaxDynamicSharedMemorySize,
                         K1_SMEM_FLOATS * (int)sizeof(float));

    k_prep_w<<<3, 256>>>(W1, W2, wbf);
    k_prep_ec<<<1, 256>>>(eclf, ecf);

    const float* cur = x;
    float* outs[3] = { bufA, bufB, (float*)d_out };

    for (int i = 0; i < 3; i++) {
        dim3 g1(BN, K1_BLOCKS_PER_B);
        k_assign_hf<<<g1, 256, K1_SMEM_FLOATS * sizeof(float)>>>(cur, ecf, assign, hfp);
        k_edge_mix<<<BN, 256>>>(hfp, emap, ho, hof);
        dim3 g3(BN, K3_BLOCKS_PER_B);
        k_fused_out<<<g3, 256, K3_SMEM_FLOATS * sizeof(float)>>>(
            cur, wbf + (size_t)i*8192, hof, b1 + i*DD, b2 + i*DD,
            ln1g + i*DD, ln1b + i*DD, ln2g, ln2b,
            assign, outs[i]);
        cur = outs[i];
    }
}